// round 3
// baseline (speedup 1.0000x reference)
#include <cuda_runtime.h>
#include <cuda_bf16.h>
#include <math.h>

#define C_    256
#define NLAT_ 256
#define NLON_ 512
#define L_    256
#define M_    257
#define NREF_ 64
#define S_    (NLAT_*NLON_)      // 131072
#define K2C_  512                // 2*C for complex concat
#define MP_   528                // 2*M=514 padded to mult of 16

// sizes
#define XS_SZ   ((size_t)C_*S_)                  // 33554432
#define LW_SZ   ((size_t)L_*M_*NLAT_)            // 16842752
#define LGT_SZ  ((size_t)M_*NLAT_*L_)            // 16842752
#define WC_SZ   ((size_t)L_*C_*K2C_)             // 33554432
#define F_SZ    ((size_t)2*M_*C_*NLAT_)          // 33685504
#define H_SZ    ((size_t)L_*M_*K2C_)             // 33685504
#define XSP_SZ  ((size_t)M_*C_*L_)               // 16842752
#define G2_SZ   ((size_t)NLAT_*C_*MP_)           // 34603008
#define DCS_SZ  ((size_t)2*M_*NLON_)             // 263168
#define D2_SZ   ((size_t)NLON_*MP_)              // 270336

// ---------------- device scratch (split bf16 pairs + fp32) ----------------
__device__ __align__(128) __nv_bfloat16 g_x_h[XS_SZ],  g_x_l[XS_SZ];    // (c,j,n)
__device__ __align__(128) __nv_bfloat16 g_xt_h[XS_SZ], g_xt_l[XS_SZ];   // (s,c)
__device__ __align__(128) __nv_bfloat16 g_lw_h[LW_SZ], g_lw_l[LW_SZ];   // (l,m,j)
__device__ __align__(128) __nv_bfloat16 g_lg_h[LGT_SZ],g_lg_l[LGT_SZ];  // (m,j,l)
__device__ __align__(128) __nv_bfloat16 g_wr_h[WC_SZ], g_wr_l[WC_SZ];   // [Wre|-Wim] (l,f,2C)
__device__ __align__(128) __nv_bfloat16 g_wi_h[WC_SZ], g_wi_l[WC_SZ];   // [Wim| Wre]
__device__ __align__(128) __nv_bfloat16 g_F_h[F_SZ],   g_F_l[F_SZ];     // (ri,m,c,j)
__device__ __align__(128) __nv_bfloat16 g_H_h[H_SZ],   g_H_l[H_SZ];     // (l,m,2C)
__device__ __align__(128) __nv_bfloat16 g_xr_h[XSP_SZ],g_xr_l[XSP_SZ];  // (m,f,l) re
__device__ __align__(128) __nv_bfloat16 g_xi_h[XSP_SZ],g_xi_l[XSP_SZ];  // (m,f,l) im
__device__ __align__(128) __nv_bfloat16 g_G_h[G2_SZ],  g_G_l[G2_SZ];    // (j,f,528)
__device__ __align__(128) __nv_bfloat16 g_mA_h[XS_SZ], g_mA_l[XS_SZ];   // mlp scratch (s,c)
__device__ __align__(128) __nv_bfloat16 g_mB_h[XS_SZ], g_mB_l[XS_SZ];
__device__ __align__(128) __nv_bfloat16 g_dc_h[DCS_SZ],g_dc_l[DCS_SZ];  // (ri,m,n)
__device__ __align__(128) __nv_bfloat16 g_d2_h[D2_SZ], g_d2_l[D2_SZ];   // (n,528)
__device__ __align__(128) __nv_bfloat16 g_wt_h[4*C_*C_], g_wt_l[4*C_*C_]; // wT (c',c)
__device__ __align__(128) float g_grids[XS_SZ];                          // (n,j,f) then y2 (s,c)
__device__ float g_lsc[L_];
__device__ float g_part[2][512][C_];
__device__ float g_mu[C_], g_rstd[C_];

// ---------------- helpers ----------------
__device__ __forceinline__ float gelu_f(float v){
    return 0.5f*v*(1.0f + erff(v*0.7071067811865476f));
}
__device__ __forceinline__ void split2(float v, __nv_bfloat16* H, __nv_bfloat16* Lo, size_t off){
    __nv_bfloat16 h = __float2bfloat16(v);
    H[off]  = h;
    Lo[off] = __float2bfloat16(v - __bfloat162float(h));
}

// ---------------- prep kernels ----------------
__global__ void p_split_x(const float* __restrict__ x){
    size_t i = (size_t)blockIdx.x*256 + threadIdx.x;
    if (i >= XS_SZ) return;
    split2(x[i], g_x_h, g_x_l, i);
}

// x (c,j,n) -> xT (s=n*256+j, c), tiled transpose
__global__ void p_xT(const float* __restrict__ x){
    __shared__ float sm[32][33];
    int j  = blockIdx.y;
    int tc = blockIdx.x & 7;          // c tile (8)
    int tn = blockIdx.x >> 3;         // n tile (16)
    int tx = threadIdx.x, ty = threadIdx.y;
    #pragma unroll
    for (int k=0;k<4;k++){
        int c = tc*32 + ty + k*8;
        sm[ty+k*8][tx] = x[(size_t)c*S_ + (size_t)j*NLON_ + tn*32 + tx];
    }
    __syncthreads();
    #pragma unroll
    for (int k=0;k<4;k++){
        int n = tn*32 + ty + k*8;
        int c = tc*32 + tx;
        size_t off = ((size_t)n*NLAT_ + j)*C_ + c;
        split2(sm[tx][ty+k*8], g_xt_h, g_xt_l, off);
    }
}

__global__ void p_lw(const float* __restrict__ leg, const float* __restrict__ wq){
    size_t i = (size_t)blockIdx.x*256 + threadIdx.x;
    if (i >= LW_SZ) return;
    split2(leg[i]*wq[i & (NLAT_-1)], g_lw_h, g_lw_l, i);
}

// leg (l,m,j) -> lgt (m,j,l), tiled transpose over (l,j) at fixed m
__global__ void p_legT(const float* __restrict__ leg){
    __shared__ float sm[32][33];
    int m  = blockIdx.y;
    int tl = blockIdx.x & 7;
    int tj = blockIdx.x >> 3;
    int tx = threadIdx.x, ty = threadIdx.y;
    #pragma unroll
    for (int k=0;k<4;k++){
        int l = tl*32 + ty + k*8;
        sm[ty+k*8][tx] = leg[(size_t)l*M_*NLAT_ + (size_t)m*NLAT_ + tj*32 + tx];
    }
    __syncthreads();
    #pragma unroll
    for (int k=0;k<4;k++){
        int j = tj*32 + ty + k*8;
        int l = tl*32 + tx;
        size_t off = ((size_t)m*NLAT_ + j)*L_ + l;
        split2(sm[tx][ty+k*8], g_lg_h, g_lg_l, off);
    }
}

__global__ void p_W(const float* __restrict__ wr, const float* __restrict__ wi){
    size_t i = (size_t)blockIdx.x*256 + threadIdx.x;
    if (i >= (size_t)L_*C_*C_) return;
    int c = (int)(i & 255);
    int f = (int)((i>>8) & 255);
    int l = (int)(i>>16);
    float pos = (float)(l*(NREF_-1)) / (float)(L_-1);
    int i0 = (int)floorf(pos);
    if (i0 > NREF_-2) i0 = NREF_-2;
    float fr = pos - (float)i0;
    size_t base = ((size_t)f*C_ + c)*NREF_ + i0;
    float vre = wr[base]*(1.0f-fr) + wr[base+1]*fr;
    float vim = wi[base]*(1.0f-fr) + wi[base+1]*fr;
    size_t ob = ((size_t)l*C_ + f)*K2C_;
    split2( vre, g_wr_h, g_wr_l, ob + c);
    split2(-vim, g_wr_h, g_wr_l, ob + C_ + c);
    split2( vim, g_wi_h, g_wi_l, ob + c);
    split2( vre, g_wi_h, g_wi_l, ob + C_ + c);
}

__global__ void p_dft(){
    int i = blockIdx.x*256 + threadIdx.x;
    if (i < L_) g_lsc[i] = sqrtf(1.0f + (float)i) * (1.0f/(float)C_);
    if (i < (int)DCS_SZ){
        int n = i & 511;
        int m = (i >> 9) % M_;
        int ri = i / (M_*NLON_);
        int a = (m*n) & 511;
        float ang = (float)a * (1.0f/256.0f);
        float v = ri ? -sinpif(ang) : cospif(ang);
        split2(v, g_dc_h, g_dc_l, (size_t)i);
    }
    if (i < (int)D2_SZ){
        int mp = i % MP_;
        int n  = i / MP_;
        float v = 0.f;
        if (mp < M_){
            float wm = (mp==0 || mp==M_-1) ? 1.0f : 2.0f;
            int a = (mp*n) & 511;
            v = wm * cospif((float)a*(1.0f/256.0f)) * (1.0f/NLON_);
        } else if (mp < 2*M_-1+1){ // 257..513
            int m2 = mp - M_;
            if (m2 < M_){
                float wm = (m2==0 || m2==M_-1) ? 1.0f : 2.0f;
                int a = (m2*n) & 511;
                v = -wm * sinpif((float)a*(1.0f/256.0f)) * (1.0f/NLON_);
            }
        }
        split2(v, g_d2_h, g_d2_l, (size_t)i);
    }
}

__global__ void p_wT(const float* w1, const float* w2, const float* w3, const float* w4){
    int i = blockIdx.x*256 + threadIdx.x;
    if (i >= C_*C_) return;
    int c = i / C_, cp = i % C_;   // read w[c][cp], write wT[cp][c]
    const float* ws[4] = {w1, w2, w3, w4};
    #pragma unroll
    for (int k=0;k<4;k++){
        split2(ws[k][i], g_wt_h, g_wt_l, (size_t)k*C_*C_ + (size_t)cp*C_ + c);
    }
}

__global__ void p_zeroG2(){
    int i = blockIdx.x*256 + threadIdx.x;
    int tot = NLAT_*C_*(MP_ - 514);
    if (i >= tot) return;
    int k  = i % (MP_-514);
    int jf = i / (MP_-514);
    size_t off = (size_t)jf*MP_ + 514 + k;
    g_G_h[off] = __float2bfloat16(0.f);
    g_G_l[off] = __float2bfloat16(0.f);
}

// ---------------- split-bf16 tensor-core GEMM ----------------
// D[b,i,j] = scale(b) * sum_k (Ah+Al)[b,i,k]*(Bh+Bl)[b,j,k]  (3-term emulation)
//            (+biasJ[j]) -> ACT -> (+addsrc[off]); writes fp32 Dout and/or split (Oh,Ol)
#define MMA_OP(cc, aa, bb) asm volatile( \
    "mma.sync.aligned.m16n8k16.row.col.f32.bf16.bf16.f32 " \
    "{%0,%1,%2,%3},{%4,%5,%6,%7},{%8,%9},{%0,%1,%2,%3};" \
    : "+f"(cc[0]),"+f"(cc[1]),"+f"(cc[2]),"+f"(cc[3]) \
    : "r"(aa[0]),"r"(aa[1]),"r"(aa[2]),"r"(aa[3]),"r"(bb[0]),"r"(bb[1]))

template<int ACT>
__global__ __launch_bounds__(256) void mmagemm(
    const __nv_bfloat16* __restrict__ Ah, const __nv_bfloat16* __restrict__ Al,
    const __nv_bfloat16* __restrict__ Bh, const __nv_bfloat16* __restrict__ Bl,
    float* __restrict__ Dout,
    __nv_bfloat16* __restrict__ Oh, __nv_bfloat16* __restrict__ Ol,
    const float* __restrict__ biasJ, const float* __restrict__ bscale,
    const float* __restrict__ addsrc,
    int Mrows, int Ncols, int K,
    long sAi, long sAb, long sBi, long sBb,
    long sCi, long sCj, long sCb)
{
    __shared__ uint4 sAh[256], sAl[256], sBh[256], sBl[256];

    const int t    = threadIdx.x;
    const int lane = t & 31;
    const int warp = t >> 5;
    const int g    = lane >> 2;
    const int tig  = lane & 3;
    const int sw   = (lane >> 4) & 1;
    const int wm   = warp >> 2;     // 0..1
    const int wn   = warp & 3;      // 0..3
    const int bz   = blockIdx.z;
    const long i0  = (long)blockIdx.y * 128;
    const long j0  = (long)blockIdx.x * 128;

    const __nv_bfloat16* Ahb = Ah + (long)bz*sAb;
    const __nv_bfloat16* Alb = Al + (long)bz*sAb;
    const __nv_bfloat16* Bhb = Bh + (long)bz*sBb;
    const __nv_bfloat16* Blb = Bl + (long)bz*sBb;

    const int lr = t >> 1;            // 0..127 tile row
    const int kc = (t & 1) * 8;       // k sub-chunk
    const long arow = i0 + lr;
    const long brow = j0 + lr;
    const bool aok = arow < (long)Mrows;
    const bool bok = brow < (long)Ncols;
    const int pc = lr*2 + ((t&1) ^ ((lr>>2)&1));   // swizzled 16B-chunk index

    float acc[64];
    #pragma unroll
    for (int i=0;i<64;i++) acc[i] = 0.f;

    const uint4 z4 = make_uint4(0u,0u,0u,0u);
    uint4 rAh, rAl, rBh, rBl;
    {
        long ao = arow*sAi + kc, bo = brow*sBi + kc;
        rAh = aok ? *(const uint4*)(Ahb + ao) : z4;
        rAl = aok ? *(const uint4*)(Alb + ao) : z4;
        rBh = bok ? *(const uint4*)(Bhb + bo) : z4;
        rBl = bok ? *(const uint4*)(Blb + bo) : z4;
    }

    const int nk = K >> 4;
    const unsigned* A32h = (const unsigned*)sAh;
    const unsigned* A32l = (const unsigned*)sAl;
    const unsigned* B32h = (const unsigned*)sBh;
    const unsigned* B32l = (const unsigned*)sBl;

    for (int ks = 0; ks < nk; ks++){
        __syncthreads();
        sAh[pc] = rAh; sAl[pc] = rAl; sBh[pc] = rBh; sBl[pc] = rBl;
        __syncthreads();
        if (ks + 1 < nk){
            long kq = (long)(ks+1)*16 + kc;
            long ao = arow*sAi + kq, bo = brow*sBi + kq;
            rAh = aok ? *(const uint4*)(Ahb + ao) : z4;
            rAl = aok ? *(const uint4*)(Alb + ao) : z4;
            rBh = bok ? *(const uint4*)(Bhb + bo) : z4;
            rBl = bok ? *(const uint4*)(Blb + bo) : z4;
        }
        // fragments
        unsigned bh[4][2], bl[4][2], ah[4][4], al[4][4];
        #pragma unroll
        for (int nt=0; nt<4; nt++){
            int base = (wn*32 + nt*8 + g)*8 + tig;
            bh[nt][0] = B32h[base + sw*4];
            bh[nt][1] = B32h[base + (sw^1)*4];
            bl[nt][0] = B32l[base + sw*4];
            bl[nt][1] = B32l[base + (sw^1)*4];
        }
        #pragma unroll
        for (int mt=0; mt<4; mt++){
            int r0 = wm*64 + mt*16 + g;
            int b0 = r0*8 + tig;
            int b1 = (r0+8)*8 + tig;
            ah[mt][0] = A32h[b0 + sw*4];
            ah[mt][1] = A32h[b1 + sw*4];
            ah[mt][2] = A32h[b0 + (sw^1)*4];
            ah[mt][3] = A32h[b1 + (sw^1)*4];
            al[mt][0] = A32l[b0 + sw*4];
            al[mt][1] = A32l[b1 + sw*4];
            al[mt][2] = A32l[b0 + (sw^1)*4];
            al[mt][3] = A32l[b1 + (sw^1)*4];
        }
        #pragma unroll
        for (int mt=0; mt<4; mt++)
            #pragma unroll
            for (int nt=0; nt<4; nt++) MMA_OP((&acc[(mt*4+nt)*4]), ah[mt], bh[nt]);
        #pragma unroll
        for (int mt=0; mt<4; mt++)
            #pragma unroll
            for (int nt=0; nt<4; nt++) MMA_OP((&acc[(mt*4+nt)*4]), ah[mt], bl[nt]);
        #pragma unroll
        for (int mt=0; mt<4; mt++)
            #pragma unroll
            for (int nt=0; nt<4; nt++) MMA_OP((&acc[(mt*4+nt)*4]), al[mt], bh[nt]);
    }

    float scl = bscale ? bscale[bz] : 1.0f;
    #pragma unroll
    for (int mt=0; mt<4; mt++){
        long rA = i0 + wm*64 + mt*16 + g;
        #pragma unroll
        for (int nt=0; nt<4; nt++){
            long cB = j0 + wn*32 + nt*8 + 2*tig;
            float* a = &acc[(mt*4+nt)*4];
            #pragma unroll
            for (int h=0; h<2; h++){
                long row = rA + h*8;
                if (row >= (long)Mrows) continue;
                #pragma unroll
                for (int q=0; q<2; q++){
                    long col = cB + q;
                    if (col >= (long)Ncols) continue;
                    float v = a[h*2+q] * scl;
                    if (biasJ) v += biasJ[col];
                    if (ACT == 1) v = gelu_f(v);
                    long off = (long)bz*sCb + row*sCi + col*sCj;
                    if (addsrc) v += addsrc[off];
                    if (Dout) Dout[off] = v;
                    if (Oh) split2(v, Oh, Ol, (size_t)off);
                }
            }
        }
    }
}

// ---------------- norm + finalize ----------------
__global__ void norm1_k(){
    int b = blockIdx.x, c = threadIdx.x;
    const float* base = g_grids + (size_t)b*256*C_;
    float s=0.f, q=0.f;
    for (int r=0;r<256;r++){
        float v = base[(size_t)r*C_ + c];
        s += v; q = fmaf(v,v,q);
    }
    g_part[0][b][c] = s;
    g_part[1][b][c] = q;
}
__global__ void norm2_k(){
    int c = threadIdx.x;
    float s=0.f, q=0.f;
    for (int b=0;b<512;b++){ s += g_part[0][b][c]; q += g_part[1][b][c]; }
    float mu = s * (1.0f/(float)S_);
    float var = q * (1.0f/(float)S_) - mu*mu;
    g_mu[c] = mu;
    g_rstd[c] = rsqrtf(var + 1e-3f);
}
// y2 (s,c) -> out (c,j,n) with norm + residual
__global__ void fin_k(const float* __restrict__ x,
                      const float* __restrict__ gamma,
                      const float* __restrict__ beta,
                      float* __restrict__ out){
    __shared__ float sm[32][33];
    int j  = blockIdx.y;
    int tc = blockIdx.x & 7;
    int tn = blockIdx.x >> 3;
    int tx = threadIdx.x, ty = threadIdx.y;
    #pragma unroll
    for (int k=0;k<4;k++){
        int n = tn*32 + ty + k*8;
        sm[ty+k*8][tx] = g_grids[((size_t)n*NLAT_ + j)*C_ + tc*32 + tx];
    }
    __syncthreads();
    #pragma unroll
    for (int k=0;k<4;k++){
        int c = tc*32 + ty + k*8;
        int n = tn*32 + tx;
        size_t off = (size_t)c*S_ + (size_t)j*NLON_ + n;
        float v = sm[tx][ty+k*8];
        out[off] = (v - g_mu[c])*g_rstd[c]*gamma[c] + beta[c] + x[off];
    }
}

// ---------------- host side ----------------
#define DEVPTR(T, var, sym) T* var; cudaGetSymbolAddress((void**)&var, sym)

static void launch_gemm(int act, dim3 grid,
    const __nv_bfloat16* Ah, const __nv_bfloat16* Al,
    const __nv_bfloat16* Bh, const __nv_bfloat16* Bl,
    float* Dout, __nv_bfloat16* Oh, __nv_bfloat16* Ol,
    const float* biasJ, const float* bscale, const float* addsrc,
    int M, int N, int K,
    long sAi, long sAb, long sBi, long sBb, long sCi, long sCj, long sCb)
{
    if (act)
        mmagemm<1><<<grid,256>>>(Ah,Al,Bh,Bl,Dout,Oh,Ol,biasJ,bscale,addsrc,
                                 M,N,K,sAi,sAb,sBi,sBb,sCi,sCj,sCb);
    else
        mmagemm<0><<<grid,256>>>(Ah,Al,Bh,Bl,Dout,Oh,Ol,biasJ,bscale,addsrc,
                                 M,N,K,sAi,sAb,sBi,sBb,sCi,sCj,sCb);
}

extern "C" void kernel_launch(void* const* d_in, const int* in_sizes, int n_in,
                              void* d_out, int out_size){
    const float* x      = (const float*)d_in[0];
    const float* leg    = (const float*)d_in[1];
    const float* wquad  = (const float*)d_in[2];
    const float* w_real = (const float*)d_in[3];
    const float* w_imag = (const float*)d_in[4];
    const float* m1w1   = (const float*)d_in[5];
    const float* m1b1   = (const float*)d_in[6];
    const float* m1w2   = (const float*)d_in[7];
    const float* m1b2   = (const float*)d_in[8];
    const float* m2w1   = (const float*)d_in[9];
    const float* m2b1   = (const float*)d_in[10];
    const float* m2w2   = (const float*)d_in[11];
    const float* m2b2   = (const float*)d_in[12];
    const float* gamma  = (const float*)d_in[13];
    const float* beta   = (const float*)d_in[14];
    float* out = (float*)d_out;

    DEVPTR(__nv_bfloat16, xh, g_x_h);  DEVPTR(__nv_bfloat16, xl, g_x_l);
    DEVPTR(__nv_bfloat16, xth,g_xt_h); DEVPTR(__nv_bfloat16, xtl,g_xt_l);
    DEVPTR(__nv_bfloat16, lwh,g_lw_h); DEVPTR(__nv_bfloat16, lwl,g_lw_l);
    DEVPTR(__nv_bfloat16, lgh,g_lg_h); DEVPTR(__nv_bfloat16, lgl,g_lg_l);
    DEVPTR(__nv_bfloat16, wrh,g_wr_h); DEVPTR(__nv_bfloat16, wrl,g_wr_l);
    DEVPTR(__nv_bfloat16, wih,g_wi_h); DEVPTR(__nv_bfloat16, wil,g_wi_l);
    DEVPTR(__nv_bfloat16, Fh, g_F_h);  DEVPTR(__nv_bfloat16, Fl, g_F_l);
    DEVPTR(__nv_bfloat16, Hh, g_H_h);  DEVPTR(__nv_bfloat16, Hl, g_H_l);
    DEVPTR(__nv_bfloat16, xrh,g_xr_h); DEVPTR(__nv_bfloat16, xrl,g_xr_l);
    DEVPTR(__nv_bfloat16, xih,g_xi_h); DEVPTR(__nv_bfloat16, xil,g_xi_l);
    DEVPTR(__nv_bfloat16, Gh, g_G_h);  DEVPTR(__nv_bfloat16, Gl, g_G_l);
    DEVPTR(__nv_bfloat16, mAh,g_mA_h); DEVPTR(__nv_bfloat16, mAl,g_mA_l);
    DEVPTR(__nv_bfloat16, mBh,g_mB_h); DEVPTR(__nv_bfloat16, mBl,g_mB_l);
    DEVPTR(__nv_bfloat16, dch,g_dc_h); DEVPTR(__nv_bfloat16, dcl,g_dc_l);
    DEVPTR(__nv_bfloat16, d2h,g_d2_h); DEVPTR(__nv_bfloat16, d2l,g_d2_l);
    DEVPTR(__nv_bfloat16, wth,g_wt_h); DEVPTR(__nv_bfloat16, wtl,g_wt_l);
    DEVPTR(float, grids, g_grids);
    DEVPTR(float, lsc,   g_lsc);

    // ---- prep ----
    p_split_x<<<(unsigned)((XS_SZ+255)/256), 256>>>(x);
    p_xT     <<<dim3(128, NLAT_), dim3(32,8)>>>(x);
    p_lw     <<<(unsigned)((LW_SZ+255)/256), 256>>>(leg, wquad);
    p_legT   <<<dim3(64, M_), dim3(32,8)>>>(leg);
    p_W      <<<(unsigned)(((size_t)L_*C_*C_+255)/256), 256>>>(w_real, w_imag);
    p_dft    <<<(D2_SZ+255)/256, 256>>>();
    p_wT     <<<(C_*C_+255)/256, 256>>>(m1w1, m1w2, m2w1, m2w2);
    p_zeroG2 <<<(NLAT_*C_*14+255)/256, 256>>>();

    // ---- S1: rfft. D[cj, m] batched over ri; out F (ri,m,c,j) split ----
    launch_gemm(0, dim3(3, 512, 2),
        xh, xl, dch, dcl, nullptr, Fh, Fl, nullptr, nullptr, nullptr,
        C_*NLAT_, M_, NLON_,
        NLON_, 0, NLON_, (long)M_*NLON_,
        1, (long)C_*NLAT_, (long)M_*C_*NLAT_);

    // ---- S2: Legendre fwd (batch m): D[l, c] -> H (l,m,2C) ----
    launch_gemm(0, dim3(2, 2, M_),
        lwh, lwl, Fh, Fl, nullptr, Hh, Hl, nullptr, nullptr, nullptr,
        L_, C_, NLAT_,
        (long)M_*NLAT_, NLAT_, NLAT_, (long)C_*NLAT_,
        (long)M_*K2C_, 1, K2C_);
    launch_gemm(0, dim3(2, 2, M_),
        lwh, lwl, Fh + M_*(size_t)C_*NLAT_, Fl + M_*(size_t)C_*NLAT_,
        nullptr, Hh + C_, Hl + C_, nullptr, nullptr, nullptr,
        L_, C_, NLAT_,
        (long)M_*NLAT_, NLAT_, NLAT_, (long)C_*NLAT_,
        (long)M_*K2C_, 1, K2C_);

    // ---- S3: spectral conv (batch l): D[f, m] -> xs (m,f,l) split, scale lsc ----
    launch_gemm(0, dim3(3, 2, L_),
        wrh, wrl, Hh, Hl, nullptr, xrh, xrl, nullptr, lsc, nullptr,
        C_, M_, K2C_,
        K2C_, (long)C_*K2C_, K2C_, (long)M_*K2C_,
        L_, (long)C_*L_, 1);
    launch_gemm(0, dim3(3, 2, L_),
        wih, wil, Hh, Hl, nullptr, xih, xil, nullptr, lsc, nullptr,
        C_, M_, K2C_,
        K2C_, (long)C_*K2C_, K2C_, (long)M_*K2C_,
        L_, (long)C_*L_, 1);

    // ---- S4: Legendre inv (batch m): D[j, f] -> G2 (j,f,528) split ----
    launch_gemm(0, dim3(2, 2, M_),
        lgh, lgl, xrh, xrl, nullptr, Gh, Gl, nullptr, nullptr, nullptr,
        NLAT_, C_, L_,
        L_, (long)NLAT_*L_, L_, (long)C_*L_,
        (long)C_*MP_, MP_, 1);
    launch_gemm(0, dim3(2, 2, M_),
        lgh, lgl, xih, xil, nullptr, Gh + M_, Gl + M_, nullptr, nullptr, nullptr,
        NLAT_, C_, L_,
        L_, (long)NLAT_*L_, L_, (long)C_*L_,
        (long)C_*MP_, MP_, 1);

    // ---- S5: irfft + GELU. D[n, jf] -> grids (n,j,f) fp32 ----
    launch_gemm(1, dim3(512, 4, 1),
        d2h, d2l, Gh, Gl, grids, nullptr, nullptr, nullptr, nullptr, nullptr,
        NLON_, NLAT_*C_, MP_,
        MP_, 0, MP_, 0,
        (long)NLAT_*C_, 1, 0);

    // ---- MLP1: h1 = gelu(xT @ w1 + b1) -> mA split (s,c) ----
    launch_gemm(1, dim3(2, 1024, 1),
        xth, xtl, wth + 0, wtl + 0, nullptr, mAh, mAl, m1b1, nullptr, nullptr,
        S_, C_, C_, C_, 0, C_, 0, C_, 1, 0);
    // ---- MLP2: y1 = gelu(h1 @ w2 + b2) + grids -> mB split ----
    launch_gemm(1, dim3(2, 1024, 1),
        mAh, mAl, wth + C_*C_, wtl + C_*C_, nullptr, mBh, mBl, m1b2, nullptr, grids,
        S_, C_, C_, C_, 0, C_, 0, C_, 1, 0);
    // ---- MLP3 ----
    launch_gemm(1, dim3(2, 1024, 1),
        mBh, mBl, wth + 2*C_*C_, wtl + 2*C_*C_, nullptr, mAh, mAl, m2b1, nullptr, nullptr,
        S_, C_, C_, C_, 0, C_, 0, C_, 1, 0);
    // ---- MLP4: y2 -> grids (fp32) ----
    launch_gemm(1, dim3(2, 1024, 1),
        mAh, mAl, wth + 3*C_*C_, wtl + 3*C_*C_, grids, nullptr, nullptr, m2b2, nullptr, nullptr,
        S_, C_, C_, C_, 0, C_, 0, C_, 1, 0);

    // ---- instance norm + residual + transpose out ----
    norm1_k<<<512, 256>>>();
    norm2_k<<<1, 256>>>();
    fin_k<<<dim3(128, NLAT_), dim3(32,8)>>>(x, gamma, beta, out);
}

// round 6
// speedup vs baseline: 1.0876x; 1.0876x over previous
#include <cuda_runtime.h>
#include <cuda_bf16.h>
#include <math.h>

#define C_    256
#define NLAT_ 256
#define NLON_ 512
#define L_    256
#define M_    257
#define NREF_ 64
#define S_    (NLAT_*NLON_)
#define K2C_  512
#define MP_   544               // 2*M=514 padded to mult of 32

#define XS_SZ   ((size_t)C_*S_)
#define LW_SZ   ((size_t)L_*M_*NLAT_)
#define LGT_SZ  ((size_t)M_*NLAT_*L_)
#define WC_SZ   ((size_t)L_*C_*K2C_)
#define F_SZ    ((size_t)2*M_*C_*NLAT_)
#define H_SZ    ((size_t)L_*M_*K2C_)
#define XSP_SZ  ((size_t)M_*C_*L_)
#define G2_SZ   ((size_t)NLAT_*C_*MP_)
#define DCS_SZ  ((size_t)2*M_*NLON_)
#define D2_SZ   ((size_t)NLON_*MP_)

__device__ __align__(128) __nv_bfloat16 g_x_h[XS_SZ],  g_x_l[XS_SZ];
__device__ __align__(128) __nv_bfloat16 g_xt_h[XS_SZ], g_xt_l[XS_SZ];
__device__ __align__(128) __nv_bfloat16 g_lw_h[LW_SZ], g_lw_l[LW_SZ];
__device__ __align__(128) __nv_bfloat16 g_lg_h[LGT_SZ],g_lg_l[LGT_SZ];
__device__ __align__(128) __nv_bfloat16 g_wr_h[WC_SZ], g_wr_l[WC_SZ];
__device__ __align__(128) __nv_bfloat16 g_wi_h[WC_SZ], g_wi_l[WC_SZ];
__device__ __align__(128) __nv_bfloat16 g_F_h[F_SZ],   g_F_l[F_SZ];
__device__ __align__(128) __nv_bfloat16 g_H_h[H_SZ],   g_H_l[H_SZ];
__device__ __align__(128) __nv_bfloat16 g_xr_h[XSP_SZ],g_xr_l[XSP_SZ];
__device__ __align__(128) __nv_bfloat16 g_xi_h[XSP_SZ],g_xi_l[XSP_SZ];
__device__ __align__(128) __nv_bfloat16 g_G_h[G2_SZ],  g_G_l[G2_SZ];
__device__ __align__(128) __nv_bfloat16 g_mA_h[XS_SZ], g_mA_l[XS_SZ];
__device__ __align__(128) __nv_bfloat16 g_mB_h[XS_SZ], g_mB_l[XS_SZ];
__device__ __align__(128) __nv_bfloat16 g_dc_h[DCS_SZ],g_dc_l[DCS_SZ];
__device__ __align__(128) __nv_bfloat16 g_d2_h[D2_SZ], g_d2_l[D2_SZ];
__device__ __align__(128) __nv_bfloat16 g_wt_h[4*C_*C_], g_wt_l[4*C_*C_];
__device__ __align__(128) float g_grids[XS_SZ];
__device__ float g_lsc[L_];
__device__ float g_part[2][512][C_];
__device__ float g_mu[C_], g_rstd[C_];

__device__ __forceinline__ float gelu_f(float v){
    return 0.5f*v*(1.0f + erff(v*0.7071067811865476f));
}
__device__ __forceinline__ void split2(float v, __nv_bfloat16* H, __nv_bfloat16* Lo, size_t off){
    __nv_bfloat16 h = __float2bfloat16(v);
    H[off]  = h;
    Lo[off] = __float2bfloat16(v - __bfloat162float(h));
}
__device__ __forceinline__ unsigned smem_u32(const void* p){
    unsigned a;
    asm("{ .reg .u64 t; cvta.to.shared.u64 t, %1; cvt.u32.u64 %0, t; }" : "=r"(a) : "l"(p));
    return a;
}
// byte offset of 32-bit word w (0..15) in row r; 16B chunks swizzled by (r>>1)&3
__device__ __forceinline__ int swadr(int r, int w){
    return r*64 + ((((w>>2) ^ ((r>>1)&3))) << 4) + ((w & 3) << 2);
}
__device__ __forceinline__ void cpa16(unsigned saddr, const void* g, bool v){
    asm volatile("cp.async.cg.shared.global [%0], [%1], 16, %2;"
                 :: "r"(saddr), "l"(g), "r"(v ? 16 : 0));
}
#define CP_COMMIT() asm volatile("cp.async.commit_group;")
#define LDMX4(r0,r1,r2,r3,addr) \
    asm volatile("ldmatrix.sync.aligned.m8n8.x4.shared.b16 {%0,%1,%2,%3}, [%4];" \
        : "=r"(r0),"=r"(r1),"=r"(r2),"=r"(r3) : "r"(addr))
#define MMA_OP(cc, aa, bb) asm volatile( \
    "mma.sync.aligned.m16n8k16.row.col.f32.bf16.bf16.f32 " \
    "{%0,%1,%2,%3},{%4,%5,%6,%7},{%8,%9},{%0,%1,%2,%3};" \
    : "+f"(cc[0]),"+f"(cc[1]),"+f"(cc[2]),"+f"(cc[3]) \
    : "r"(aa[0]),"r"(aa[1]),"r"(aa[2]),"r"(aa[3]),"r"(bb[0]),"r"(bb[1]))

// ---------------- prep kernels (identical to passing R2) ----------------
__global__ void p_split_x(const float* __restrict__ x){
    size_t i = (size_t)blockIdx.x*256 + threadIdx.x;
    if (i >= XS_SZ) return;
    split2(x[i], g_x_h, g_x_l, i);
}
__global__ void p_xT(const float* __restrict__ x){
    __shared__ float sm[32][33];
    int j  = blockIdx.y;
    int tc = blockIdx.x & 7;
    int tn = blockIdx.x >> 3;
    int tx = threadIdx.x, ty = threadIdx.y;
    #pragma unroll
    for (int k=0;k<4;k++){
        int c = tc*32 + ty + k*8;
        sm[ty+k*8][tx] = x[(size_t)c*S_ + (size_t)j*NLON_ + tn*32 + tx];
    }
    __syncthreads();
    #pragma unroll
    for (int k=0;k<4;k++){
        int n = tn*32 + ty + k*8;
        int c = tc*32 + tx;
        size_t off = ((size_t)n*NLAT_ + j)*C_ + c;
        split2(sm[tx][ty+k*8], g_xt_h, g_xt_l, off);
    }
}
__global__ void p_lw(const float* __restrict__ leg, const float* __restrict__ wq){
    size_t i = (size_t)blockIdx.x*256 + threadIdx.x;
    if (i >= LW_SZ) return;
    split2(leg[i]*wq[i & (NLAT_-1)], g_lw_h, g_lw_l, i);
}
__global__ void p_legT(const float* __restrict__ leg){
    __shared__ float sm[32][33];
    int m  = blockIdx.y;
    int tl = blockIdx.x & 7;
    int tj = blockIdx.x >> 3;
    int tx = threadIdx.x, ty = threadIdx.y;
    #pragma unroll
    for (int k=0;k<4;k++){
        int l = tl*32 + ty + k*8;
        sm[ty+k*8][tx] = leg[(size_t)l*M_*NLAT_ + (size_t)m*NLAT_ + tj*32 + tx];
    }
    __syncthreads();
    #pragma unroll
    for (int k=0;k<4;k++){
        int j = tj*32 + ty + k*8;
        int l = tl*32 + tx;
        size_t off = ((size_t)m*NLAT_ + j)*L_ + l;
        split2(sm[tx][ty+k*8], g_lg_h, g_lg_l, off);
    }
}
__global__ void p_W(const float* __restrict__ wr, const float* __restrict__ wi){
    size_t i = (size_t)blockIdx.x*256 + threadIdx.x;
    if (i >= (size_t)L_*C_*C_) return;
    int c = (int)(i & 255);
    int f = (int)((i>>8) & 255);
    int l = (int)(i>>16);
    float pos = (float)(l*(NREF_-1)) / (float)(L_-1);
    int i0 = (int)floorf(pos);
    if (i0 > NREF_-2) i0 = NREF_-2;
    float fr = pos - (float)i0;
    size_t base = ((size_t)f*C_ + c)*NREF_ + i0;
    float vre = wr[base]*(1.0f-fr) + wr[base+1]*fr;
    float vim = wi[base]*(1.0f-fr) + wi[base+1]*fr;
    size_t ob = ((size_t)l*C_ + f)*K2C_;
    split2( vre, g_wr_h, g_wr_l, ob + c);
    split2(-vim, g_wr_h, g_wr_l, ob + C_ + c);
    split2( vim, g_wi_h, g_wi_l, ob + c);
    split2( vre, g_wi_h, g_wi_l, ob + C_ + c);
}
__global__ void p_dft(){
    int i = blockIdx.x*256 + threadIdx.x;
    if (i < L_) g_lsc[i] = sqrtf(1.0f + (float)i) * (1.0f/(float)C_);
    if (i < (int)DCS_SZ){
        int n = i & 511;
        int m = (i >> 9) % M_;
        int ri = i / (M_*NLON_);
        int a = (m*n) & 511;
        float ang = (float)a * (1.0f/256.0f);
        float v = ri ? -sinpif(ang) : cospif(ang);
        split2(v, g_dc_h, g_dc_l, (size_t)i);
    }
    if (i < (int)D2_SZ){
        int mp = i % MP_;
        int n  = i / MP_;
        float v = 0.f;
        if (mp < M_){
            float wm = (mp==0 || mp==M_-1) ? 1.0f : 2.0f;
            int a = (mp*n) & 511;
            v = wm * cospif((float)a*(1.0f/256.0f)) * (1.0f/NLON_);
        } else if (mp < 2*M_){
            int m2 = mp - M_;
            float wm = (m2==0 || m2==M_-1) ? 1.0f : 2.0f;
            int a = (m2*n) & 511;
            v = -wm * sinpif((float)a*(1.0f/256.0f)) * (1.0f/NLON_);
        }
        split2(v, g_d2_h, g_d2_l, (size_t)i);
    }
}
__global__ void p_wT(const float* w1, const float* w2, const float* w3, const float* w4){
    int i = blockIdx.x*256 + threadIdx.x;
    if (i >= C_*C_) return;
    int c = i / C_, cp = i % C_;
    const float* ws[4] = {w1, w2, w3, w4};
    #pragma unroll
    for (int k=0;k<4;k++)
        split2(ws[k][i], g_wt_h, g_wt_l, (size_t)k*C_*C_ + (size_t)cp*C_ + c);
}
__global__ void p_zeroG2(){
    int i = blockIdx.x*256 + threadIdx.x;
    int nz = MP_ - 514;
    int tot = NLAT_*C_*nz;
    if (i >= tot) return;
    int k  = i % nz;
    int jf = i / nz;
    size_t off = (size_t)jf*MP_ + 514 + k;
    g_G_h[off] = __float2bfloat16(0.f);
    g_G_l[off] = __float2bfloat16(0.f);
}

// ---------------- pipelined mma.sync split-bf16 GEMM ----------------
// 128x128 tile, K-chunk 32, 2-stage cp.async double buffer, ldmatrix frags.
// Stage layout (32KB): Ah[0,8K) Al[8K,16K) Bh[16K,24K) Bl[24K,32K),
// each 128 rows x 64B (16 words), 16B chunks swizzled by (row>>1)&3.
#define STGB 32768
#define SMEM_DYN (2*STGB)

template<int ACT>
__global__ __launch_bounds__(256) void mmagemm(
    const __nv_bfloat16* __restrict__ Ah, const __nv_bfloat16* __restrict__ Al,
    const __nv_bfloat16* __restrict__ Bh, const __nv_bfloat16* __restrict__ Bl,
    float* __restrict__ Dout,
    __nv_bfloat16* __restrict__ Oh, __nv_bfloat16* __restrict__ Ol,
    const float* __restrict__ biasJ, const float* __restrict__ bscale,
    const float* __restrict__ addsrc,
    int Mrows, int Ncols, int K,
    long sAi, long sAb, long sBi, long sBb,
    long sCi, long sCj, long sCb)
{
    extern __shared__ char dsm[];
    const unsigned sb = smem_u32(dsm);

    const int t    = threadIdx.x;
    const int lane = t & 31;
    const int warp = t >> 5;
    const int g    = lane >> 2;
    const int tig  = lane & 3;
    const int mm   = lane >> 3;      // ldmatrix matrix id
    const int rrl  = lane & 7;       // ldmatrix row-in-matrix
    const int wm   = warp >> 2;      // 0..1
    const int wn   = warp & 3;       // 0..3
    const int bz   = blockIdx.z;
    const long i0  = (long)blockIdx.y * 128;
    const long j0  = (long)blockIdx.x * 128;

    const __nv_bfloat16* Ahb = Ah + (long)bz*sAb;
    const __nv_bfloat16* Alb = Al + (long)bz*sAb;
    const __nv_bfloat16* Bhb = Bh + (long)bz*sBb;
    const __nv_bfloat16* Blb = Bl + (long)bz*sBb;

    const int row   = t >> 1;
    const int half  = t & 1;
    const long arow = i0 + row;               // always valid (Mrows mult of 128)
    const long brow = j0 + row;
    const bool bok  = brow < (long)Ncols;
    const long aoff = arow * sAi;
    const long boff = brow * sBi;

    float acc[64];
    #pragma unroll
    for (int i=0;i<64;i++) acc[i] = 0.f;

    auto load_stage = [&](int ks, int s){
        unsigned st = sb + s*STGB;
        long kg = (long)ks*32;
        #pragma unroll
        for (int q=0;q<2;q++){
            int c = half*2 + q;               // 16B chunk 0..3
            long ke = kg + c*8;
            unsigned so = (unsigned)(row*64 + ((c ^ ((row>>1)&3)) << 4));
            cpa16(st + so,          Ahb + aoff + ke, true);
            cpa16(st + 8192 + so,   Alb + aoff + ke, true);
            cpa16(st + 16384 + so,  Bhb + boff + ke, bok);
            cpa16(st + 24576 + so,  Blb + boff + ke, bok);
        }
    };

    const int nk = K >> 5;
    load_stage(0, 0);
    CP_COMMIT();

    for (int ks = 0; ks < nk; ks++){
        const int s = ks & 1;
        if (ks + 1 < nk){
            load_stage(ks+1, s^1);
            CP_COMMIT();
            asm volatile("cp.async.wait_group 1;");
        } else {
            asm volatile("cp.async.wait_group 0;");
        }
        __syncthreads();

        const unsigned sA = sb + s*STGB;
        const unsigned sB = sA + 16384;
        #pragma unroll
        for (int kk=0; kk<2; kk++){
            unsigned ah[4][4], al[4][4], bh[4][2], bl[4][2];
            #pragma unroll
            for (int p=0;p<2;p++){
                int rowB = wn*32 + (p*2 + (mm>>1))*8 + rrl;
                int wB   = kk*8 + (mm&1)*4;
                unsigned ad = sB + (unsigned)swadr(rowB, wB);
                LDMX4(bh[p*2][0], bh[p*2][1], bh[p*2+1][0], bh[p*2+1][1], ad);
                LDMX4(bl[p*2][0], bl[p*2][1], bl[p*2+1][0], bl[p*2+1][1], ad + 8192);
            }
            #pragma unroll
            for (int mt=0; mt<4; mt++){
                int rowA = wm*64 + mt*16 + (mm&1)*8 + rrl;
                int wA   = kk*8 + (mm>>1)*4;
                unsigned ad = sA + (unsigned)swadr(rowA, wA);
                LDMX4(ah[mt][0], ah[mt][1], ah[mt][2], ah[mt][3], ad);
                LDMX4(al[mt][0], al[mt][1], al[mt][2], al[mt][3], ad + 8192);
            }
            #pragma unroll
            for (int mt=0; mt<4; mt++)
                #pragma unroll
                for (int nt=0; nt<4; nt++) MMA_OP((&acc[(mt*4+nt)*4]), ah[mt], bh[nt]);
            #pragma unroll
            for (int mt=0; mt<4; mt++)
                #pragma unroll
                for (int nt=0; nt<4; nt++) MMA_OP((&acc[(mt*4+nt)*4]), ah[mt], bl[nt]);
            #pragma unroll
            for (int mt=0; mt<4; mt++)
                #pragma unroll
                for (int nt=0; nt<4; nt++) MMA_OP((&acc[(mt*4+nt)*4]), al[mt], bh[nt]);
        }
        __syncthreads();
    }

    // ---------------- epilogue (identical math to R2) ----------------
    float scl = bscale ? bscale[bz] : 1.0f;
    #pragma unroll
    for (int mt=0; mt<4; mt++){
        long rA = i0 + wm*64 + mt*16 + g;
        #pragma unroll
        for (int nt=0; nt<4; nt++){
            long cB = j0 + wn*32 + nt*8 + 2*tig;
            float* a = &acc[(mt*4+nt)*4];
            #pragma unroll
            for (int h=0; h<2; h++){
                long rowg = rA + h*8;
                if (rowg >= (long)Mrows) continue;
                #pragma unroll
                for (int q=0; q<2; q++){
                    long col = cB + q;
                    if (col >= (long)Ncols) continue;
                    float v = a[h*2+q] * scl;
                    if (biasJ) v += biasJ[col];
                    if (ACT == 1) v = gelu_f(v);
                    long off = (long)bz*sCb + rowg*sCi + col*sCj;
                    if (addsrc) v += addsrc[off];
                    if (Dout) Dout[off] = v;
                    if (Oh) split2(v, Oh, Ol, (size_t)off);
                }
            }
        }
    }
}

// ---------------- norm + finalize ----------------
__global__ void norm1_k(){
    int b = blockIdx.x, c = threadIdx.x;
    const float* base = g_grids + (size_t)b*256*C_;
    float s=0.f, q=0.f;
    for (int r=0;r<256;r++){
        float v = base[(size_t)r*C_ + c];
        s += v; q = fmaf(v,v,q);
    }
    g_part[0][b][c] = s;
    g_part[1][b][c] = q;
}
__global__ void norm2_k(){
    int c = threadIdx.x;
    float s=0.f, q=0.f;
    for (int b=0;b<512;b++){ s += g_part[0][b][c]; q += g_part[1][b][c]; }
    float mu = s * (1.0f/(float)S_);
    float var = q * (1.0f/(float)S_) - mu*mu;
    g_mu[c] = mu;
    g_rstd[c] = rsqrtf(var + 1e-3f);
}
__global__ void fin_k(const float* __restrict__ x,
                      const float* __restrict__ gamma,
                      const float* __restrict__ beta,
                      float* __restrict__ out){
    __shared__ float sm[32][33];
    int j  = blockIdx.y;
    int tc = blockIdx.x & 7;
    int tn = blockIdx.x >> 3;
    int tx = threadIdx.x, ty = threadIdx.y;
    #pragma unroll
    for (int k=0;k<4;k++){
        int n = tn*32 + ty + k*8;
        sm[ty+k*8][tx] = g_grids[((size_t)n*NLAT_ + j)*C_ + tc*32 + tx];
    }
    __syncthreads();
    #pragma unroll
    for (int k=0;k<4;k++){
        int c = tc*32 + ty + k*8;
        int n = tn*32 + tx;
        size_t off = (size_t)c*S_ + (size_t)j*NLON_ + n;
        float v = sm[tx][ty+k*8];
        out[off] = (v - g_mu[c])*g_rstd[c]*gamma[c] + beta[c] + x[off];
    }
}

// ---------------- host side ----------------
#define DEVPTR(T, var, sym) T* var; cudaGetSymbolAddress((void**)&var, sym)

static void launch_gemm(int act, dim3 grid,
    const __nv_bfloat16* Ah, const __nv_bfloat16* Al,
    const __nv_bfloat16* Bh, const __nv_bfloat16* Bl,
    float* Dout, __nv_bfloat16* Oh, __nv_bfloat16* Ol,
    const float* biasJ, const float* bscale, const float* addsrc,
    int M, int N, int K,
    long sAi, long sAb, long sBi, long sBb, long sCi, long sCj, long sCb)
{
    if (act)
        mmagemm<1><<<grid,256,SMEM_DYN>>>(Ah,Al,Bh,Bl,Dout,Oh,Ol,biasJ,bscale,addsrc,
                                          M,N,K,sAi,sAb,sBi,sBb,sCi,sCj,sCb);
    else
        mmagemm<0><<<grid,256,SMEM_DYN>>>(Ah,Al,Bh,Bl,Dout,Oh,Ol,biasJ,bscale,addsrc,
                                          M,N,K,sAi,sAb,sBi,sBb,sCi,sCj,sCb);
}

extern "C" void kernel_launch(void* const* d_in, const int* in_sizes, int n_in,
                              void* d_out, int out_size){
    const float* x      = (const float*)d_in[0];
    const float* leg    = (const float*)d_in[1];
    const float* wquad  = (const float*)d_in[2];
    const float* w_real = (const float*)d_in[3];
    const float* w_imag = (const float*)d_in[4];
    const float* m1w1   = (const float*)d_in[5];
    const float* m1b1   = (const float*)d_in[6];
    const float* m1w2   = (const float*)d_in[7];
    const float* m1b2   = (const float*)d_in[8];
    const float* m2w1   = (const float*)d_in[9];
    const float* m2b1   = (const float*)d_in[10];
    const float* m2w2   = (const float*)d_in[11];
    const float* m2b2   = (const float*)d_in[12];
    const float* gamma  = (const float*)d_in[13];
    const float* beta   = (const float*)d_in[14];
    float* out = (float*)d_out;

    cudaFuncSetAttribute(mmagemm<0>, cudaFuncAttributeMaxDynamicSharedMemorySize, SMEM_DYN);
    cudaFuncSetAttribute(mmagemm<1>, cudaFuncAttributeMaxDynamicSharedMemorySize, SMEM_DYN);

    DEVPTR(__nv_bfloat16, xh, g_x_h);  DEVPTR(__nv_bfloat16, xl, g_x_l);
    DEVPTR(__nv_bfloat16, xth,g_xt_h); DEVPTR(__nv_bfloat16, xtl,g_xt_l);
    DEVPTR(__nv_bfloat16, lwh,g_lw_h); DEVPTR(__nv_bfloat16, lwl,g_lw_l);
    DEVPTR(__nv_bfloat16, lgh,g_lg_h); DEVPTR(__nv_bfloat16, lgl,g_lg_l);
    DEVPTR(__nv_bfloat16, wrh,g_wr_h); DEVPTR(__nv_bfloat16, wrl,g_wr_l);
    DEVPTR(__nv_bfloat16, wih,g_wi_h); DEVPTR(__nv_bfloat16, wil,g_wi_l);
    DEVPTR(__nv_bfloat16, Fh, g_F_h);  DEVPTR(__nv_bfloat16, Fl, g_F_l);
    DEVPTR(__nv_bfloat16, Hh, g_H_h);  DEVPTR(__nv_bfloat16, Hl, g_H_l);
    DEVPTR(__nv_bfloat16, xrh,g_xr_h); DEVPTR(__nv_bfloat16, xrl,g_xr_l);
    DEVPTR(__nv_bfloat16, xih,g_xi_h); DEVPTR(__nv_bfloat16, xil,g_xi_l);
    DEVPTR(__nv_bfloat16, Gh, g_G_h);  DEVPTR(__nv_bfloat16, Gl, g_G_l);
    DEVPTR(__nv_bfloat16, mAh,g_mA_h); DEVPTR(__nv_bfloat16, mAl,g_mA_l);
    DEVPTR(__nv_bfloat16, mBh,g_mB_h); DEVPTR(__nv_bfloat16, mBl,g_mB_l);
    DEVPTR(__nv_bfloat16, dch,g_dc_h); DEVPTR(__nv_bfloat16, dcl,g_dc_l);
    DEVPTR(__nv_bfloat16, d2h,g_d2_h); DEVPTR(__nv_bfloat16, d2l,g_d2_l);
    DEVPTR(__nv_bfloat16, wth,g_wt_h); DEVPTR(__nv_bfloat16, wtl,g_wt_l);
    DEVPTR(float, grids, g_grids);
    DEVPTR(float, lsc,   g_lsc);

    // ---- prep ----
    p_split_x<<<(unsigned)((XS_SZ+255)/256), 256>>>(x);
    p_xT     <<<dim3(128, NLAT_), dim3(32,8)>>>(x);
    p_lw     <<<(unsigned)((LW_SZ+255)/256), 256>>>(leg, wquad);
    p_legT   <<<dim3(64, M_), dim3(32,8)>>>(leg);
    p_W      <<<(unsigned)(((size_t)L_*C_*C_+255)/256), 256>>>(w_real, w_imag);
    p_dft    <<<(unsigned)((D2_SZ+255)/256), 256>>>();
    p_wT     <<<(C_*C_+255)/256, 256>>>(m1w1, m1w2, m2w1, m2w2);
    p_zeroG2 <<<(unsigned)((NLAT_*C_*(MP_-514)+255)/256), 256>>>();

    // ---- S1: rfft DFT-GEMM ----
    launch_gemm(0, dim3(3, 512, 2),
        xh, xl, dch, dcl, nullptr, Fh, Fl, nullptr, nullptr, nullptr,
        C_*NLAT_, M_, NLON_,
        NLON_, 0, NLON_, (long)M_*NLON_,
        1, (long)C_*NLAT_, (long)M_*C_*NLAT_);

    // ---- S2: Legendre fwd (batch m) ----
    launch_gemm(0, dim3(2, 2, M_),
        lwh, lwl, Fh, Fl, nullptr, Hh, Hl, nullptr, nullptr, nullptr,
        L_, C_, NLAT_,
        (long)M_*NLAT_, NLAT_, NLAT_, (long)C_*NLAT_,
        (long)M_*K2C_, 1, K2C_);
    launch_gemm(0, dim3(2, 2, M_),
        lwh, lwl, Fh + M_*(size_t)C_*NLAT_, Fl + M_*(size_t)C_*NLAT_,
        nullptr, Hh + C_, Hl + C_, nullptr, nullptr, nullptr,
        L_, C_, NLAT_,
        (long)M_*NLAT_, NLAT_, NLAT_, (long)C_*NLAT_,
        (long)M_*K2C_, 1, K2C_);

    // ---- S3: spectral conv (batch l) ----
    launch_gemm(0, dim3(3, 2, L_),
        wrh, wrl, Hh, Hl, nullptr, xrh, xrl, nullptr, lsc, nullptr,
        C_, M_, K2C_,
        K2C_, (long)C_*K2C_, K2C_, (long)M_*K2C_,
        L_, (long)C_*L_, 1);
    launch_gemm(0, dim3(3, 2, L_),
        wih, wil, Hh, Hl, nullptr, xih, xil, nullptr, lsc, nullptr,
        C_, M_, K2C_,
        K2C_, (long)C_*K2C_, K2C_, (long)M_*K2C_,
        L_, (long)C_*L_, 1);

    // ---- S4: Legendre inv (batch m) ----
    launch_gemm(0, dim3(2, 2, M_),
        lgh, lgl, xrh, xrl, nullptr, Gh, Gl, nullptr, nullptr, nullptr,
        NLAT_, C_, L_,
        L_, (long)NLAT_*L_, L_, (long)C_*L_,
        (long)C_*MP_, MP_, 1);
    launch_gemm(0, dim3(2, 2, M_),
        lgh, lgl, xih, xil, nullptr, Gh + M_, Gl + M_, nullptr, nullptr, nullptr,
        NLAT_, C_, L_,
        L_, (long)NLAT_*L_, L_, (long)C_*L_,
        (long)C_*MP_, MP_, 1);

    // ---- S5: irfft + GELU ----
    launch_gemm(1, dim3(512, 4, 1),
        d2h, d2l, Gh, Gl, grids, nullptr, nullptr, nullptr, nullptr, nullptr,
        NLON_, NLAT_*C_, MP_,
        MP_, 0, MP_, 0,
        (long)NLAT_*C_, 1, 0);

    // ---- MLPs ----
    launch_gemm(1, dim3(2, 1024, 1),
        xth, xtl, wth + 0, wtl + 0, nullptr, mAh, mAl, m1b1, nullptr, nullptr,
        S_, C_, C_, C_, 0, C_, 0, C_, 1, 0);
    launch_gemm(1, dim3(2, 1024, 1),
        mAh, mAl, wth + C_*C_, wtl + C_*C_, nullptr, mBh, mBl, m1b2, nullptr, grids,
        S_, C_, C_, C_, 0, C_, 0, C_, 1, 0);
    launch_gemm(1, dim3(2, 1024, 1),
        mBh, mBl, wth + 2*C_*C_, wtl + 2*C_*C_, nullptr, mAh, mAl, m2b1, nullptr, nullptr,
        S_, C_, C_, C_, 0, C_, 0, C_, 1, 0);
    launch_gemm(1, dim3(2, 1024, 1),
        mAh, mAl, wth + 3*C_*C_, wtl + 3*C_*C_, grids, nullptr, nullptr, m2b2, nullptr, nullptr,
        S_, C_, C_, C_, 0, C_, 0, C_, 1, 0);

    // ---- instance norm + residual + transpose out ----
    norm1_k<<<512, 256>>>();
    norm2_k<<<1, 256>>>();
    fin_k<<<dim3(128, NLAT_), dim3(32,8)>>>(x, gamma, beta, out);
}

// round 7
// speedup vs baseline: 1.4663x; 1.3481x over previous
#include <cuda_runtime.h>
#include <cuda_fp16.h>
#include <math.h>

#define C_    256
#define NLAT_ 256
#define NLON_ 512
#define L_    256
#define M_    257
#define NREF_ 64
#define S_    (NLAT_*NLON_)
#define K2C_  512
#define MP_   544               // 2*M=514 padded to mult of 32

#define XS_SZ   ((size_t)C_*S_)
#define LW_SZ   ((size_t)L_*M_*NLAT_)
#define LGT_SZ  ((size_t)M_*NLAT_*L_)
#define WC_SZ   ((size_t)L_*C_*K2C_)
#define F_SZ    ((size_t)2*M_*C_*NLAT_)
#define H_SZ    ((size_t)L_*M_*K2C_)
#define XSP_SZ  ((size_t)M_*C_*L_)
#define G2_SZ   ((size_t)NLAT_*C_*MP_)
#define DCS_SZ  ((size_t)2*M_*NLON_)
#define D2_SZ   ((size_t)NLON_*MP_)

// A-side operands keep hi+lo; B-side / intermediates are hi-only.
__device__ __align__(128) __half g_x_h[XS_SZ],  g_x_l[XS_SZ];     // (c,j,n)   A of S1
__device__ __align__(128) __half g_xt_h[XS_SZ], g_xt_l[XS_SZ];    // (s,c)     A of MLP1
__device__ __align__(128) __half g_lw_h[LW_SZ], g_lw_l[LW_SZ];    // 16*(l,m,j) A of S2
__device__ __align__(128) __half g_lg_h[LGT_SZ],g_lg_l[LGT_SZ];   // 16*(m,j,l) A of S4
__device__ __align__(128) __half g_wr_h[WC_SZ], g_wr_l[WC_SZ];    // [Wre|-Wim] A of S3
__device__ __align__(128) __half g_wi_h[WC_SZ], g_wi_l[WC_SZ];    // [Wim| Wre]
__device__ __align__(128) __half g_F_h[F_SZ];                     // (ri,m,c,j) B of S2
__device__ __align__(128) __half g_H_h[H_SZ];                     // (l,m,2C)   B of S3 (16x)
__device__ __align__(128) __half g_xr_h[XSP_SZ];                  // (m,f,l)    B of S4
__device__ __align__(128) __half g_xi_h[XSP_SZ];
__device__ __align__(128) __half g_G_h[G2_SZ];                    // (j,f,544)  B of S5 (16x)
__device__ __align__(128) __half g_mA_h[XS_SZ], g_mA_l[XS_SZ];    // mlp scratch (s,c)
__device__ __align__(128) __half g_mB_h[XS_SZ], g_mB_l[XS_SZ];
__device__ __align__(128) __half g_dc_h[DCS_SZ];                  // (ri,m,n)   B of S1
__device__ __align__(128) __half g_d2_h[D2_SZ], g_d2_l[D2_SZ];    // 256*(n,544) A of S5
__device__ __align__(128) __half g_wt_h[4*C_*C_], g_wt_l[4*C_*C_];// 16*wT      B of MLPs? (A-side corr on acts; wt is B) -> lo unused but harmless
__device__ __align__(128) float g_grids[XS_SZ];
__device__ float g_lsc16[L_];        // sqrt(1+l)/C/16
__device__ float g_cscale[2];        // {1/16, 1/4096}
__device__ float g_part[2][512][C_];
__device__ float g_mu[C_], g_rstd[C_];

__device__ __forceinline__ float gelu_f(float v){
    return 0.5f*v*(1.0f + erff(v*0.7071067811865476f));
}
__device__ __forceinline__ void split2(float v, __half* H, __half* Lo, size_t off){
    __half h = __float2half_rn(v);
    H[off]  = h;
    if (Lo) Lo[off] = __float2half_rn(v - __half2float(h));
}
__device__ __forceinline__ unsigned smem_u32(const void* p){
    unsigned a;
    asm("{ .reg .u64 t; cvta.to.shared.u64 t, %1; cvt.u32.u64 %0, t; }" : "=r"(a) : "l"(p));
    return a;
}
__device__ __forceinline__ int swadr(int r, int w){
    return r*64 + ((((w>>2) ^ ((r>>1)&3))) << 4) + ((w & 3) << 2);
}
__device__ __forceinline__ void cpa16(unsigned saddr, const void* g, bool v){
    asm volatile("cp.async.cg.shared.global [%0], [%1], 16, %2;"
                 :: "r"(saddr), "l"(g), "r"(v ? 16 : 0));
}
#define CP_COMMIT() asm volatile("cp.async.commit_group;")
#define LDMX4(r0,r1,r2,r3,addr) \
    asm volatile("ldmatrix.sync.aligned.m8n8.x4.shared.b16 {%0,%1,%2,%3}, [%4];" \
        : "=r"(r0),"=r"(r1),"=r"(r2),"=r"(r3) : "r"(addr))
#define MMA_OP(cc, aa, bb) asm volatile( \
    "mma.sync.aligned.m16n8k16.row.col.f32.f16.f16.f32 " \
    "{%0,%1,%2,%3},{%4,%5,%6,%7},{%8,%9},{%0,%1,%2,%3};" \
    : "+f"(cc[0]),"+f"(cc[1]),"+f"(cc[2]),"+f"(cc[3]) \
    : "r"(aa[0]),"r"(aa[1]),"r"(aa[2]),"r"(aa[3]),"r"(bb[0]),"r"(bb[1]))

// ---------------- prep kernels ----------------
__global__ void p_split_x(const float* __restrict__ x){
    size_t i = (size_t)blockIdx.x*256 + threadIdx.x;
    if (i >= XS_SZ) return;
    split2(x[i], g_x_h, g_x_l, i);
}
__global__ void p_xT(const float* __restrict__ x){
    __shared__ float sm[32][33];
    int j  = blockIdx.y;
    int tc = blockIdx.x & 7;
    int tn = blockIdx.x >> 3;
    int tx = threadIdx.x, ty = threadIdx.y;
    #pragma unroll
    for (int k=0;k<4;k++){
        int c = tc*32 + ty + k*8;
        sm[ty+k*8][tx] = x[(size_t)c*S_ + (size_t)j*NLON_ + tn*32 + tx];
    }
    __syncthreads();
    #pragma unroll
    for (int k=0;k<4;k++){
        int n = tn*32 + ty + k*8;
        int c = tc*32 + tx;
        size_t off = ((size_t)n*NLAT_ + j)*C_ + c;
        split2(sm[tx][ty+k*8], g_xt_h, g_xt_l, off);
    }
}
__global__ void p_lw(const float* __restrict__ leg, const float* __restrict__ wq){
    size_t i = (size_t)blockIdx.x*256 + threadIdx.x;
    if (i >= LW_SZ) return;
    split2(16.0f*leg[i]*wq[i & (NLAT_-1)], g_lw_h, g_lw_l, i);
}
__global__ void p_legT(const float* __restrict__ leg){
    __shared__ float sm[32][33];
    int m  = blockIdx.y;
    int tl = blockIdx.x & 7;
    int tj = blockIdx.x >> 3;
    int tx = threadIdx.x, ty = threadIdx.y;
    #pragma unroll
    for (int k=0;k<4;k++){
        int l = tl*32 + ty + k*8;
        sm[ty+k*8][tx] = leg[(size_t)l*M_*NLAT_ + (size_t)m*NLAT_ + tj*32 + tx];
    }
    __syncthreads();
    #pragma unroll
    for (int k=0;k<4;k++){
        int j = tj*32 + ty + k*8;
        int l = tl*32 + tx;
        size_t off = ((size_t)m*NLAT_ + j)*L_ + l;
        split2(16.0f*sm[tx][ty+k*8], g_lg_h, g_lg_l, off);
    }
}
__global__ void p_W(const float* __restrict__ wr, const float* __restrict__ wi){
    size_t i = (size_t)blockIdx.x*256 + threadIdx.x;
    if (i >= (size_t)L_*C_*C_) return;
    int c = (int)(i & 255);
    int f = (int)((i>>8) & 255);
    int l = (int)(i>>16);
    float pos = (float)(l*(NREF_-1)) / (float)(L_-1);
    int i0 = (int)floorf(pos);
    if (i0 > NREF_-2) i0 = NREF_-2;
    float fr = pos - (float)i0;
    size_t base = ((size_t)f*C_ + c)*NREF_ + i0;
    float vre = wr[base]*(1.0f-fr) + wr[base+1]*fr;
    float vim = wi[base]*(1.0f-fr) + wi[base+1]*fr;
    size_t ob = ((size_t)l*C_ + f)*K2C_;
    split2( vre, g_wr_h, g_wr_l, ob + c);
    split2(-vim, g_wr_h, g_wr_l, ob + C_ + c);
    split2( vim, g_wi_h, g_wi_l, ob + c);
    split2( vre, g_wi_h, g_wi_l, ob + C_ + c);
}
__global__ void p_dft(){
    int i = blockIdx.x*256 + threadIdx.x;
    if (i < L_) g_lsc16[i] = sqrtf(1.0f + (float)i) * (1.0f/(float)C_) * (1.0f/16.0f);
    if (i < 2)  g_cscale[i] = (i==0) ? 0.0625f : (1.0f/4096.0f);
    if (i < (int)DCS_SZ){
        int n = i & 511;
        int m = (i >> 9) % M_;
        int ri = i / (M_*NLON_);
        int a = (m*n) & 511;
        float ang = (float)a * (1.0f/256.0f);
        float v = ri ? -sinpif(ang) : cospif(ang);
        g_dc_h[i] = __float2half_rn(v);
    }
    if (i < (int)D2_SZ){
        int mp = i % MP_;
        int n  = i / MP_;
        float v = 0.f;
        if (mp < M_){
            float wm = (mp==0 || mp==M_-1) ? 1.0f : 2.0f;
            int a = (mp*n) & 511;
            v = wm * cospif((float)a*(1.0f/256.0f)) * 0.5f;       // x256 of /512
        } else if (mp < 2*M_){
            int m2 = mp - M_;
            float wm = (m2==0 || m2==M_-1) ? 1.0f : 2.0f;
            int a = (m2*n) & 511;
            v = -wm * sinpif((float)a*(1.0f/256.0f)) * 0.5f;
        }
        split2(v, g_d2_h, g_d2_l, (size_t)i);
    }
}
__global__ void p_wT(const float* w1, const float* w2, const float* w3, const float* w4){
    int i = blockIdx.x*256 + threadIdx.x;
    if (i >= C_*C_) return;
    int c = i / C_, cp = i % C_;
    const float* ws[4] = {w1, w2, w3, w4};
    #pragma unroll
    for (int k=0;k<4;k++)
        split2(16.0f*ws[k][i], g_wt_h, g_wt_l, (size_t)k*C_*C_ + (size_t)cp*C_ + c);
}
__global__ void p_zeroG2(){
    int i = blockIdx.x*256 + threadIdx.x;
    int nz = MP_ - 514;
    int tot = NLAT_*C_*nz;
    if (i >= tot) return;
    int k  = i % nz;
    int jf = i / nz;
    g_G_h[(size_t)jf*MP_ + 514 + k] = __float2half_rn(0.f);
}

// ---------------- pipelined mma.sync 2-pass split-fp16 GEMM ----------------
// D = (Ah+Al)·Bh^T (A hi/lo fp16, B hi fp16), 128x128 tile, K-chunk 32,
// 2-stage cp.async, ldmatrix frags. Stage 24KB: Ah[0,8K) Al[8K,16K) Bh[16K,24K).
#define STGB 24576
#define SMEM_DYN (2*STGB)

template<int ACT>
__global__ __launch_bounds__(256) void mmagemm(
    const __half* __restrict__ Ah, const __half* __restrict__ Al,
    const __half* __restrict__ Bh,
    float* __restrict__ Dout,
    __half* __restrict__ Oh, __half* __restrict__ Ol,
    const float* __restrict__ biasJ, const float* __restrict__ bscale,
    const float* __restrict__ addsrc,
    int Mrows, int Ncols, int K,
    long sAi, long sAb, long sBi, long sBb,
    long sCi, long sCj, long sCb)
{
    extern __shared__ char dsm[];
    const unsigned sb = smem_u32(dsm);

    const int t    = threadIdx.x;
    const int lane = t & 31;
    const int warp = t >> 5;
    const int g    = lane >> 2;
    const int tig  = lane & 3;
    const int mm   = lane >> 3;
    const int rrl  = lane & 7;
    const int wm   = warp >> 2;
    const int wn   = warp & 3;
    const int bz   = blockIdx.z;
    const long i0  = (long)blockIdx.y * 128;
    const long j0  = (long)blockIdx.x * 128;

    const __half* Ahb = Ah + (long)bz*sAb;
    const __half* Alb = Al + (long)bz*sAb;
    const __half* Bhb = Bh + (long)bz*sBb;

    const int row   = t >> 1;
    const int half  = t & 1;
    const long arow = i0 + row;
    const long brow = j0 + row;
    const bool bok  = brow < (long)Ncols;
    const long aoff = arow * sAi;
    const long boff = brow * sBi;

    float acc[64];
    #pragma unroll
    for (int i=0;i<64;i++) acc[i] = 0.f;

    auto load_stage = [&](int ks, int s){
        unsigned st = sb + s*STGB;
        long kg = (long)ks*32;
        #pragma unroll
        for (int q=0;q<2;q++){
            int c = half*2 + q;
            long ke = kg + c*8;
            unsigned so = (unsigned)(row*64 + ((c ^ ((row>>1)&3)) << 4));
            cpa16(st + so,          Ahb + aoff + ke, true);
            cpa16(st + 8192 + so,   Alb + aoff + ke, true);
            cpa16(st + 16384 + so,  Bhb + boff + ke, bok);
        }
    };

    const int nk = K >> 5;
    load_stage(0, 0);
    CP_COMMIT();

    for (int ks = 0; ks < nk; ks++){
        const int s = ks & 1;
        if (ks + 1 < nk){
            load_stage(ks+1, s^1);
            CP_COMMIT();
            asm volatile("cp.async.wait_group 1;");
        } else {
            asm volatile("cp.async.wait_group 0;");
        }
        __syncthreads();

        const unsigned sA = sb + s*STGB;
        const unsigned sB = sA + 16384;
        #pragma unroll
        for (int kk=0; kk<2; kk++){
            unsigned ah[4][4], al[4][4], bh[4][2];
            #pragma unroll
            for (int p=0;p<2;p++){
                int rowB = wn*32 + (p*2 + (mm>>1))*8 + rrl;
                int wB   = kk*8 + (mm&1)*4;
                unsigned ad = sB + (unsigned)swadr(rowB, wB);
                LDMX4(bh[p*2][0], bh[p*2][1], bh[p*2+1][0], bh[p*2+1][1], ad);
            }
            #pragma unroll
            for (int mt=0; mt<4; mt++){
                int rowA = wm*64 + mt*16 + (mm&1)*8 + rrl;
                int wA   = kk*8 + (mm>>1)*4;
                unsigned ad = sA + (unsigned)swadr(rowA, wA);
                LDMX4(ah[mt][0], ah[mt][1], ah[mt][2], ah[mt][3], ad);
                LDMX4(al[mt][0], al[mt][1], al[mt][2], al[mt][3], ad + 8192);
            }
            #pragma unroll
            for (int mt=0; mt<4; mt++)
                #pragma unroll
                for (int nt=0; nt<4; nt++) MMA_OP((&acc[(mt*4+nt)*4]), ah[mt], bh[nt]);
            #pragma unroll
            for (int mt=0; mt<4; mt++)
                #pragma unroll
                for (int nt=0; nt<4; nt++) MMA_OP((&acc[(mt*4+nt)*4]), al[mt], bh[nt]);
        }
        __syncthreads();
    }

    // ---------------- epilogue ----------------
    float scl = bscale ? bscale[bz] : 1.0f;
    #pragma unroll
    for (int mt=0; mt<4; mt++){
        long rA = i0 + wm*64 + mt*16 + g;
        #pragma unroll
        for (int nt=0; nt<4; nt++){
            long cB = j0 + wn*32 + nt*8 + 2*tig;
            float* a = &acc[(mt*4+nt)*4];
            #pragma unroll
            for (int h2=0; h2<2; h2++){
                long rowg = rA + h2*8;
                if (rowg >= (long)Mrows) continue;
                #pragma unroll
                for (int q=0; q<2; q++){
                    long col = cB + q;
                    if (col >= (long)Ncols) continue;
                    float v = a[h2*2+q] * scl;
                    if (biasJ) v += biasJ[col];
                    if (ACT == 1) v = gelu_f(v);
                    long off = (long)bz*sCb + rowg*sCi + col*sCj;
                    if (addsrc) v += addsrc[off];
                    if (Dout) Dout[off] = v;
                    if (Oh) split2(v, Oh, Ol, (size_t)off);
                }
            }
        }
    }
}

// ---------------- norm + finalize ----------------
__global__ void norm1_k(){
    int b = blockIdx.x, c = threadIdx.x;
    const float* base = g_grids + (size_t)b*256*C_;
    float s=0.f, q=0.f;
    for (int r=0;r<256;r++){
        float v = base[(size_t)r*C_ + c];
        s += v; q = fmaf(v,v,q);
    }
    g_part[0][b][c] = s;
    g_part[1][b][c] = q;
}
__global__ void norm2_k(){
    int c = threadIdx.x;
    float s=0.f, q=0.f;
    for (int b=0;b<512;b++){ s += g_part[0][b][c]; q += g_part[1][b][c]; }
    float mu = s * (1.0f/(float)S_);
    float var = q * (1.0f/(float)S_) - mu*mu;
    g_mu[c] = mu;
    g_rstd[c] = rsqrtf(var + 1e-3f);
}
__global__ void fin_k(const float* __restrict__ x,
                      const float* __restrict__ gamma,
                      const float* __restrict__ beta,
                      float* __restrict__ out){
    __shared__ float sm[32][33];
    int j  = blockIdx.y;
    int tc = blockIdx.x & 7;
    int tn = blockIdx.x >> 3;
    int tx = threadIdx.x, ty = threadIdx.y;
    #pragma unroll
    for (int k=0;k<4;k++){
        int n = tn*32 + ty + k*8;
        sm[ty+k*8][tx] = g_grids[((size_t)n*NLAT_ + j)*C_ + tc*32 + tx];
    }
    __syncthreads();
    #pragma unroll
    for (int k=0;k<4;k++){
        int c = tc*32 + ty + k*8;
        int n = tn*32 + tx;
        size_t off = (size_t)c*S_ + (size_t)j*NLON_ + n;
        float v = sm[tx][ty+k*8];
        out[off] = (v - g_mu[c])*g_rstd[c]*gamma[c] + beta[c] + x[off];
    }
}

// ---------------- host side ----------------
#define DEVPTR(T, var, sym) T* var; cudaGetSymbolAddress((void**)&var, sym)

static void launch_gemm(int act, dim3 grid,
    const __half* Ah, const __half* Al, const __half* Bh,
    float* Dout, __half* Oh, __half* Ol,
    const float* biasJ, const float* bscale, const float* addsrc,
    int M, int N, int K,
    long sAi, long sAb, long sBi, long sBb, long sCi, long sCj, long sCb)
{
    if (act)
        mmagemm<1><<<grid,256,SMEM_DYN>>>(Ah,Al,Bh,Dout,Oh,Ol,biasJ,bscale,addsrc,
                                          M,N,K,sAi,sAb,sBi,sBb,sCi,sCj,sCb);
    else
        mmagemm<0><<<grid,256,SMEM_DYN>>>(Ah,Al,Bh,Dout,Oh,Ol,biasJ,bscale,addsrc,
                                          M,N,K,sAi,sAb,sBi,sBb,sCi,sCj,sCb);
}

extern "C" void kernel_launch(void* const* d_in, const int* in_sizes, int n_in,
                              void* d_out, int out_size){
    const float* x      = (const float*)d_in[0];
    const float* leg    = (const float*)d_in[1];
    const float* wquad  = (const float*)d_in[2];
    const float* w_real = (const float*)d_in[3];
    const float* w_imag = (const float*)d_in[4];
    const float* m1w1   = (const float*)d_in[5];
    const float* m1b1   = (const float*)d_in[6];
    const float* m1w2   = (const float*)d_in[7];
    const float* m1b2   = (const float*)d_in[8];
    const float* m2w1   = (const float*)d_in[9];
    const float* m2b1   = (const float*)d_in[10];
    const float* m2w2   = (const float*)d_in[11];
    const float* m2b2   = (const float*)d_in[12];
    const float* gamma  = (const float*)d_in[13];
    const float* beta   = (const float*)d_in[14];
    float* out = (float*)d_out;

    cudaFuncSetAttribute(mmagemm<0>, cudaFuncAttributeMaxDynamicSharedMemorySize, SMEM_DYN);
    cudaFuncSetAttribute(mmagemm<1>, cudaFuncAttributeMaxDynamicSharedMemorySize, SMEM_DYN);

    DEVPTR(__half, xh, g_x_h);  DEVPTR(__half, xl, g_x_l);
    DEVPTR(__half, xth,g_xt_h); DEVPTR(__half, xtl,g_xt_l);
    DEVPTR(__half, lwh,g_lw_h); DEVPTR(__half, lwl,g_lw_l);
    DEVPTR(__half, lgh,g_lg_h); DEVPTR(__half, lgl,g_lg_l);
    DEVPTR(__half, wrh,g_wr_h); DEVPTR(__half, wrl,g_wr_l);
    DEVPTR(__half, wih,g_wi_h); DEVPTR(__half, wil,g_wi_l);
    DEVPTR(__half, Fh, g_F_h);
    DEVPTR(__half, Hh, g_H_h);
    DEVPTR(__half, xrh,g_xr_h);
    DEVPTR(__half, xih,g_xi_h);
    DEVPTR(__half, Gh, g_G_h);
    DEVPTR(__half, mAh,g_mA_h); DEVPTR(__half, mAl,g_mA_l);
    DEVPTR(__half, mBh,g_mB_h); DEVPTR(__half, mBl,g_mB_l);
    DEVPTR(__half, dch,g_dc_h);
    DEVPTR(__half, d2h,g_d2_h); DEVPTR(__half, d2l,g_d2_l);
    DEVPTR(__half, wth,g_wt_h);
    DEVPTR(float, grids, g_grids);
    DEVPTR(float, lsc16, g_lsc16);
    DEVPTR(float, cscale, g_cscale);

    // ---- prep (ordered so launch #3 = the big S1 GEMM for ncu) ----
    p_dft    <<<(unsigned)((D2_SZ+255)/256), 256>>>();
    p_split_x<<<(unsigned)((XS_SZ+255)/256), 256>>>(x);
    p_xT     <<<dim3(128, NLAT_), dim3(32,8)>>>(x);

    // ---- S1: rfft DFT-GEMM. rows=cj, cols=m, batch ri -> F (ri,m,c,j) hi ----
    launch_gemm(0, dim3(3, 512, 2),
        xh, xl, dch, nullptr, Fh, nullptr, nullptr, nullptr, nullptr,
        C_*NLAT_, M_, NLON_,
        NLON_, 0, NLON_, (long)M_*NLON_,
        1, (long)C_*NLAT_, (long)M_*C_*NLAT_);

    p_lw     <<<(unsigned)((LW_SZ+255)/256), 256>>>(leg, wquad);
    p_legT   <<<dim3(64, M_), dim3(32,8)>>>(leg);
    p_W      <<<(unsigned)(((size_t)L_*C_*C_+255)/256), 256>>>(w_real, w_imag);
    p_wT     <<<(C_*C_+255)/256, 256>>>(m1w1, m1w2, m2w1, m2w2);
    p_zeroG2 <<<(unsigned)((NLAT_*C_*(MP_-514)+255)/256), 256>>>();

    // ---- S2: Legendre fwd (batch m). A=16*lw -> H = 16x true (l,m,2C) hi ----
    launch_gemm(0, dim3(2, 2, M_),
        lwh, lwl, Fh, nullptr, Hh, nullptr, nullptr, nullptr, nullptr,
        L_, C_, NLAT_,
        (long)M_*NLAT_, NLAT_, NLAT_, (long)C_*NLAT_,
        (long)M_*K2C_, 1, K2C_);
    launch_gemm(0, dim3(2, 2, M_),
        lwh, lwl, Fh + M_*(size_t)C_*NLAT_, nullptr, Hh + C_, nullptr,
        nullptr, nullptr, nullptr,
        L_, C_, NLAT_,
        (long)M_*NLAT_, NLAT_, NLAT_, (long)C_*NLAT_,
        (long)M_*K2C_, 1, K2C_);

    // ---- S3: spectral conv (batch l). bscale = lsc/16 -> xs true (m,f,l) hi ----
    launch_gemm(0, dim3(3, 2, L_),
        wrh, wrl, Hh, nullptr, xrh, nullptr, nullptr, lsc16, nullptr,
        C_, M_, K2C_,
        K2C_, (long)C_*K2C_, K2C_, (long)M_*K2C_,
        L_, (long)C_*L_, 1);
    launch_gemm(0, dim3(3, 2, L_),
        wih, wil, Hh, nullptr, xih, nullptr, nullptr, lsc16, nullptr,
        C_, M_, K2C_,
        K2C_, (long)C_*K2C_, K2C_, (long)M_*K2C_,
        L_, (long)C_*L_, 1);

    // ---- S4: Legendre inv (batch m). A=16*lgT -> G = 16x true (j,f,544) hi ----
    launch_gemm(0, dim3(2, 2, M_),
        lgh, lgl, xrh, nullptr, Gh, nullptr, nullptr, nullptr, nullptr,
        NLAT_, C_, L_,
        L_, (long)NLAT_*L_, L_, (long)C_*L_,
        (long)C_*MP_, MP_, 1);
    launch_gemm(0, dim3(2, 2, M_),
        lgh, lgl, xih, nullptr, Gh + M_, nullptr, nullptr, nullptr, nullptr,
        NLAT_, C_, L_,
        L_, (long)NLAT_*L_, L_, (long)C_*L_,
        (long)C_*MP_, MP_, 1);

    // ---- S5: irfft + GELU. A=256*d2, B=16*G -> *1/4096, fp32 grids (n,j,f) ----
    launch_gemm(1, dim3(512, 4, 1),
        d2h, d2l, Gh, grids, nullptr, nullptr, nullptr, cscale+1, nullptr,
        NLON_, NLAT_*C_, MP_,
        MP_, 0, MP_, 0,
        (long)NLAT_*C_, 1, 0);

    // ---- MLPs: B = 16*wT, bscale = 1/16 ----
    launch_gemm(1, dim3(2, 1024, 1),
        xth, xtl, wth + 0, nullptr, mAh, mAl, m1b1, cscale, nullptr,
        S_, C_, C_, C_, 0, C_, 0, C_, 1, 0);
    launch_gemm(1, dim3(2, 1024, 1),
        mAh, mAl, wth + C_*C_, nullptr, mBh, mBl, m1b2, cscale, grids,
        S_, C_, C_, C_, 0, C_, 0, C_, 1, 0);
    launch_gemm(1, dim3(2, 1024, 1),
        mBh, mBl, wth + 2*C_*C_, nullptr, mAh, mAl, m2b1, cscale, nullptr,
        S_, C_, C_, C_, 0, C_, 0, C_, 1, 0);
    launch_gemm(1, dim3(2, 1024, 1),
        mAh, mAl, wth + 3*C_*C_, grids, nullptr, nullptr, m2b2, cscale, nullptr,
        S_, C_, C_, C_, 0, C_, 0, C_, 1, 0);

    // ---- instance norm + residual + transpose out ----
    norm1_k<<<512, 256>>>();
    norm2_k<<<1, 256>>>();
    fin_k<<<dim3(128, NLAT_), dim3(32,8)>>>(x, gamma, beta, out);
}

// round 8
// speedup vs baseline: 1.6045x; 1.0943x over previous
#include <cuda_runtime.h>
#include <cuda_fp16.h>
#include <math.h>

#define C_    256
#define NLAT_ 256
#define NLON_ 512
#define L_    256
#define M_    257
#define NREF_ 64
#define S_    (NLAT_*NLON_)
#define K2C_  512
#define MP_   576               // 2*M=514 padded to mult of 64

#define XS_SZ   ((size_t)C_*S_)
#define LW_SZ   ((size_t)L_*M_*NLAT_)
#define LGT_SZ  ((size_t)M_*NLAT_*L_)
#define WC_SZ   ((size_t)L_*C_*K2C_)
#define F_SZ    ((size_t)2*M_*C_*NLAT_)
#define H_SZ    ((size_t)L_*M_*K2C_)
#define XSP_SZ  ((size_t)M_*C_*L_)
#define G2_SZ   ((size_t)NLAT_*C_*MP_)
#define DCS_SZ  ((size_t)2*M_*NLON_)
#define D2_SZ   ((size_t)NLON_*MP_)

// A-side operands keep hi+lo; B-side / intermediates are hi-only.
__device__ __align__(128) __half g_x_h[XS_SZ],  g_x_l[XS_SZ];
__device__ __align__(128) __half g_xt_h[XS_SZ], g_xt_l[XS_SZ];
__device__ __align__(128) __half g_lw_h[LW_SZ], g_lw_l[LW_SZ];
__device__ __align__(128) __half g_lg_h[LGT_SZ],g_lg_l[LGT_SZ];
__device__ __align__(128) __half g_wr_h[WC_SZ], g_wr_l[WC_SZ];
__device__ __align__(128) __half g_wi_h[WC_SZ], g_wi_l[WC_SZ];
__device__ __align__(128) __half g_F_h[F_SZ];
__device__ __align__(128) __half g_H_h[H_SZ];
__device__ __align__(128) __half g_xr_h[XSP_SZ];
__device__ __align__(128) __half g_xi_h[XSP_SZ];
__device__ __align__(128) __half g_G_h[G2_SZ];
__device__ __align__(128) __half g_mA_h[XS_SZ], g_mA_l[XS_SZ];
__device__ __align__(128) __half g_mB_h[XS_SZ], g_mB_l[XS_SZ];
__device__ __align__(128) __half g_dc_h[DCS_SZ];
__device__ __align__(128) __half g_d2_h[D2_SZ], g_d2_l[D2_SZ];
__device__ __align__(128) __half g_wt_h[4*C_*C_], g_wt_l[4*C_*C_];
__device__ __align__(128) float g_grids[XS_SZ];
__device__ float g_lsc16[L_];
__device__ float g_cscale[2];        // {1/16, 1/4096}
__device__ float g_part[2][512][C_];
__device__ float g_mu[C_], g_rstd[C_];

__device__ __forceinline__ float gelu_f(float v){
    return 0.5f*v*(1.0f + erff(v*0.7071067811865476f));
}
__device__ __forceinline__ void split2(float v, __half* H, __half* Lo, size_t off){
    __half h = __float2half_rn(v);
    H[off]  = h;
    if (Lo) Lo[off] = __float2half_rn(v - __half2float(h));
}
__device__ __forceinline__ unsigned smem_u32(const void* p){
    unsigned a;
    asm("{ .reg .u64 t; cvta.to.shared.u64 t, %1; cvt.u32.u64 %0, t; }" : "=r"(a) : "l"(p));
    return a;
}
// 128B rows: byte offset of 32-bit word w (0..31) in row r, 16B chunks xor r&7
__device__ __forceinline__ int swadr(int r, int w){
    return r*128 + ((((w>>2) ^ (r&7))) << 4) + ((w & 3) << 2);
}
__device__ __forceinline__ void cpa16(unsigned saddr, const void* g, bool v){
    asm volatile("cp.async.cg.shared.global [%0], [%1], 16, %2;"
                 :: "r"(saddr), "l"(g), "r"(v ? 16 : 0));
}
#define CP_COMMIT() asm volatile("cp.async.commit_group;")
#define LDMX4(r0,r1,r2,r3,addr) \
    asm volatile("ldmatrix.sync.aligned.m8n8.x4.shared.b16 {%0,%1,%2,%3}, [%4];" \
        : "=r"(r0),"=r"(r1),"=r"(r2),"=r"(r3) : "r"(addr))
#define MMA_OP(cc, aa, bb) asm volatile( \
    "mma.sync.aligned.m16n8k16.row.col.f32.f16.f16.f32 " \
    "{%0,%1,%2,%3},{%4,%5,%6,%7},{%8,%9},{%0,%1,%2,%3};" \
    : "+f"(cc[0]),"+f"(cc[1]),"+f"(cc[2]),"+f"(cc[3]) \
    : "r"(aa[0]),"r"(aa[1]),"r"(aa[2]),"r"(aa[3]),"r"(bb[0]),"r"(bb[1]))

// ---------------- prep kernels ----------------
__global__ void p_split_x(const float* __restrict__ x){
    size_t i = (size_t)blockIdx.x*256 + threadIdx.x;
    if (i >= XS_SZ) return;
    split2(x[i], g_x_h, g_x_l, i);
}
__global__ void p_xT(const float* __restrict__ x){
    __shared__ float sm[32][33];
    int j  = blockIdx.y;
    int tc = blockIdx.x & 7;
    int tn = blockIdx.x >> 3;
    int tx = threadIdx.x, ty = threadIdx.y;
    #pragma unroll
    for (int k=0;k<4;k++){
        int c = tc*32 + ty + k*8;
        sm[ty+k*8][tx] = x[(size_t)c*S_ + (size_t)j*NLON_ + tn*32 + tx];
    }
    __syncthreads();
    #pragma unroll
    for (int k=0;k<4;k++){
        int n = tn*32 + ty + k*8;
        int c = tc*32 + tx;
        size_t off = ((size_t)n*NLAT_ + j)*C_ + c;
        split2(sm[tx][ty+k*8], g_xt_h, g_xt_l, off);
    }
}
__global__ void p_lw(const float* __restrict__ leg, const float* __restrict__ wq){
    size_t i = (size_t)blockIdx.x*256 + threadIdx.x;
    if (i >= LW_SZ) return;
    split2(16.0f*leg[i]*wq[i & (NLAT_-1)], g_lw_h, g_lw_l, i);
}
__global__ void p_legT(const float* __restrict__ leg){
    __shared__ float sm[32][33];
    int m  = blockIdx.y;
    int tl = blockIdx.x & 7;
    int tj = blockIdx.x >> 3;
    int tx = threadIdx.x, ty = threadIdx.y;
    #pragma unroll
    for (int k=0;k<4;k++){
        int l = tl*32 + ty + k*8;
        sm[ty+k*8][tx] = leg[(size_t)l*M_*NLAT_ + (size_t)m*NLAT_ + tj*32 + tx];
    }
    __syncthreads();
    #pragma unroll
    for (int k=0;k<4;k++){
        int j = tj*32 + ty + k*8;
        int l = tl*32 + tx;
        size_t off = ((size_t)m*NLAT_ + j)*L_ + l;
        split2(16.0f*sm[tx][ty+k*8], g_lg_h, g_lg_l, off);
    }
}
// tiled filter interpolation: block = (l-tile of 16, f), smem-staged refs
__global__ void p_W2(const float* __restrict__ wr, const float* __restrict__ wi){
    __shared__ float sr[256][8], si[256][8];
    int f  = blockIdx.y;
    int l0 = blockIdx.x * 16;
    int c  = threadIdx.x;
    int i0min = (l0*(NREF_-1)) / (L_-1);
    if (i0min > NREF_-8) i0min = NREF_-8;
    size_t rb = ((size_t)f*C_ + c)*NREF_ + i0min;
    #pragma unroll
    for (int k=0;k<8;k++){ sr[c][k] = wr[rb+k]; si[c][k] = wi[rb+k]; }
    __syncthreads();
    #pragma unroll 4
    for (int li=0; li<16; li++){
        int l = l0 + li;
        float pos = (float)(l*(NREF_-1)) / (float)(L_-1);
        int i0 = (int)floorf(pos);
        if (i0 > NREF_-2) i0 = NREF_-2;
        float fr = pos - (float)i0;
        int k = i0 - i0min;
        float vre = sr[c][k]*(1.0f-fr) + sr[c][k+1]*fr;
        float vim = si[c][k]*(1.0f-fr) + si[c][k+1]*fr;
        size_t ob = ((size_t)l*C_ + f)*K2C_;
        split2( vre, g_wr_h, g_wr_l, ob + c);
        split2(-vim, g_wr_h, g_wr_l, ob + C_ + c);
        split2( vim, g_wi_h, g_wi_l, ob + c);
        split2( vre, g_wi_h, g_wi_l, ob + C_ + c);
    }
}
__global__ void p_dft(){
    int i = blockIdx.x*256 + threadIdx.x;
    if (i < L_) g_lsc16[i] = sqrtf(1.0f + (float)i) * (1.0f/(float)C_) * (1.0f/16.0f);
    if (i < 2)  g_cscale[i] = (i==0) ? 0.0625f : (1.0f/4096.0f);
    if (i < (int)DCS_SZ){
        int n = i & 511;
        int m = (i >> 9) % M_;
        int ri = i / (M_*NLON_);
        int a = (m*n) & 511;
        float ang = (float)a * (1.0f/256.0f);
        float v = ri ? -sinpif(ang) : cospif(ang);
        g_dc_h[i] = __float2half_rn(v);
    }
    if (i < (int)D2_SZ){
        int mp = i % MP_;
        int n  = i / MP_;
        float v = 0.f;
        if (mp < M_){
            float wm = (mp==0 || mp==M_-1) ? 1.0f : 2.0f;
            int a = (mp*n) & 511;
            v = wm * cospif((float)a*(1.0f/256.0f)) * 0.5f;    // 256x of /512
        } else if (mp < 2*M_){
            int m2 = mp - M_;
            float wm = (m2==0 || m2==M_-1) ? 1.0f : 2.0f;
            int a = (m2*n) & 511;
            v = -wm * sinpif((float)a*(1.0f/256.0f)) * 0.5f;
        }
        split2(v, g_d2_h, g_d2_l, (size_t)i);
    }
}
__global__ void p_wT(const float* w1, const float* w2, const float* w3, const float* w4){
    int i = blockIdx.x*256 + threadIdx.x;
    if (i >= C_*C_) return;
    int c = i / C_, cp = i % C_;
    const float* ws[4] = {w1, w2, w3, w4};
    #pragma unroll
    for (int k=0;k<4;k++)
        split2(16.0f*ws[k][i], g_wt_h, g_wt_l, (size_t)k*C_*C_ + (size_t)cp*C_ + c);
}
__global__ void p_zeroG2(){
    int i = blockIdx.x*256 + threadIdx.x;
    int nz = MP_ - 514;
    int tot = NLAT_*C_*nz;
    if (i >= tot) return;
    int k  = i % nz;
    int jf = i / nz;
    g_G_h[(size_t)jf*MP_ + 514 + k] = __float2half_rn(0.f);
}

// ---------------- pipelined mma.sync 2-pass split-fp16 GEMM ----------------
// D = (Ah+Al)·Bh^T, 128x128 tile, K-chunk 64, 2-stage cp.async.
// Stage 48KB: Ah[0,16K) Al[16K,32K) Bh[32K,48K); rows 128B wide, xor-8 swizzle.
#define STGB 49152
#define SMEM_DYN (2*STGB)

template<int ACT>
__global__ __launch_bounds__(256) void mmagemm(
    const __half* __restrict__ Ah, const __half* __restrict__ Al,
    const __half* __restrict__ Bh,
    float* __restrict__ Dout,
    __half* __restrict__ Oh, __half* __restrict__ Ol,
    const float* __restrict__ biasJ, const float* __restrict__ bscale,
    const float* __restrict__ addsrc,
    int Mrows, int Ncols, int K,
    long sAi, long sAb, long sBi, long sBb,
    long sCi, long sCj, long sCb)
{
    extern __shared__ char dsm[];
    const unsigned sb = smem_u32(dsm);

    const int t    = threadIdx.x;
    const int lane = t & 31;
    const int warp = t >> 5;
    const int g    = lane >> 2;
    const int tig  = lane & 3;
    const int mm   = lane >> 3;
    const int rrl  = lane & 7;
    const int wm   = warp >> 2;
    const int wn   = warp & 3;
    const int bz   = blockIdx.z;
    const long i0  = (long)blockIdx.y * 128;
    const long j0  = (long)blockIdx.x * 128;

    const __half* Ahb = Ah + (long)bz*sAb;
    const __half* Alb = Al + (long)bz*sAb;
    const __half* Bhb = Bh + (long)bz*sBb;

    const int row   = t >> 1;
    const int half  = t & 1;
    const long arow = i0 + row;
    const long brow = j0 + row;
    const bool bok  = brow < (long)Ncols;
    const long aoff = arow * sAi;
    const long boff = brow * sBi;

    float acc[64];
    #pragma unroll
    for (int i=0;i<64;i++) acc[i] = 0.f;

    auto load_stage = [&](int ks, int s){
        unsigned st = sb + s*STGB;
        long kg = (long)ks*64;
        #pragma unroll
        for (int q=0;q<4;q++){
            int c = half*4 + q;               // 16B chunk 0..7
            long ke = kg + c*8;
            unsigned so = (unsigned)(row*128 + ((c ^ (row & 7)) << 4));
            cpa16(st + so,          Ahb + aoff + ke, true);
            cpa16(st + 16384 + so,  Alb + aoff + ke, true);
            cpa16(st + 32768 + so,  Bhb + boff + ke, bok);
        }
    };

    const int nk = K >> 6;
    load_stage(0, 0);
    CP_COMMIT();

    for (int ks = 0; ks < nk; ks++){
        const int s = ks & 1;
        if (ks + 1 < nk){
            load_stage(ks+1, s^1);
            CP_COMMIT();
            asm volatile("cp.async.wait_group 1;");
        } else {
            asm volatile("cp.async.wait_group 0;");
        }
        __syncthreads();

        const unsigned sA = sb + s*STGB;
        const unsigned sB = sA + 32768;
        #pragma unroll
        for (int kk=0; kk<4; kk++){
            unsigned ah[4][4], al[4][4], bh[4][2];
            #pragma unroll
            for (int p=0;p<2;p++){
                int rowB = wn*32 + (p*2 + (mm>>1))*8 + rrl;
                int wB   = kk*8 + (mm&1)*4;
                unsigned ad = sB + (unsigned)swadr(rowB, wB);
                LDMX4(bh[p*2][0], bh[p*2][1], bh[p*2+1][0], bh[p*2+1][1], ad);
            }
            #pragma unroll
            for (int mt=0; mt<4; mt++){
                int rowA = wm*64 + mt*16 + (mm&1)*8 + rrl;
                int wA   = kk*8 + (mm>>1)*4;
                unsigned ad = sA + (unsigned)swadr(rowA, wA);
                LDMX4(ah[mt][0], ah[mt][1], ah[mt][2], ah[mt][3], ad);
                LDMX4(al[mt][0], al[mt][1], al[mt][2], al[mt][3], ad + 16384);
            }
            #pragma unroll
            for (int mt=0; mt<4; mt++)
                #pragma unroll
                for (int nt=0; nt<4; nt++) MMA_OP((&acc[(mt*4+nt)*4]), ah[mt], bh[nt]);
            #pragma unroll
            for (int mt=0; mt<4; mt++)
                #pragma unroll
                for (int nt=0; nt<4; nt++) MMA_OP((&acc[(mt*4+nt)*4]), al[mt], bh[nt]);
        }
        __syncthreads();
    }

    // ---------------- epilogue ----------------
    float scl = bscale ? bscale[bz] : 1.0f;
    #pragma unroll
    for (int mt=0; mt<4; mt++){
        long rA = i0 + wm*64 + mt*16 + g;
        #pragma unroll
        for (int nt=0; nt<4; nt++){
            long cB = j0 + wn*32 + nt*8 + 2*tig;
            float* a = &acc[(mt*4+nt)*4];
            #pragma unroll
            for (int h2=0; h2<2; h2++){
                long rowg = rA + h2*8;
                if (rowg >= (long)Mrows) continue;
                long offr = (long)bz*sCb + rowg*sCi;
                if (sCj == 1 && cB + 1 < (long)Ncols){
                    float v0 = a[h2*2+0] * scl;
                    float v1 = a[h2*2+1] * scl;
                    if (biasJ){ v0 += biasJ[cB]; v1 += biasJ[cB+1]; }
                    if (ACT == 1){ v0 = gelu_f(v0); v1 = gelu_f(v1); }
                    long off = offr + cB;
                    if (addsrc){ v0 += addsrc[off]; v1 += addsrc[off+1]; }
                    if (Dout) *(float2*)(Dout + off) = make_float2(v0, v1);
                    if (Oh){
                        __half h0 = __float2half_rn(v0), h1 = __float2half_rn(v1);
                        *(__half2*)(Oh + off) = __halves2half2(h0, h1);
                        if (Ol) *(__half2*)(Ol + off) = __halves2half2(
                            __float2half_rn(v0 - __half2float(h0)),
                            __float2half_rn(v1 - __half2float(h1)));
                    }
                } else {
                    #pragma unroll
                    for (int q=0; q<2; q++){
                        long col = cB + q;
                        if (col >= (long)Ncols) continue;
                        float v = a[h2*2+q] * scl;
                        if (biasJ) v += biasJ[col];
                        if (ACT == 1) v = gelu_f(v);
                        long off = offr + col*sCj;
                        if (addsrc) v += addsrc[off];
                        if (Dout) Dout[off] = v;
                        if (Oh) split2(v, Oh, Ol, (size_t)off);
                    }
                }
            }
        }
    }
}

// ---------------- norm + finalize ----------------
__global__ void norm1_k(){
    int b = blockIdx.x, c = threadIdx.x;
    const float* base = g_grids + (size_t)b*256*C_;
    float s=0.f, q=0.f;
    for (int r=0;r<256;r++){
        float v = base[(size_t)r*C_ + c];
        s += v; q = fmaf(v,v,q);
    }
    g_part[0][b][c] = s;
    g_part[1][b][c] = q;
}
__global__ void norm2_k(){
    int c = threadIdx.x;
    float s=0.f, q=0.f;
    for (int b=0;b<512;b++){ s += g_part[0][b][c]; q += g_part[1][b][c]; }
    float mu = s * (1.0f/(float)S_);
    float var = q * (1.0f/(float)S_) - mu*mu;
    g_mu[c] = mu;
    g_rstd[c] = rsqrtf(var + 1e-3f);
}
__global__ void fin_k(const float* __restrict__ x,
                      const float* __restrict__ gamma,
                      const float* __restrict__ beta,
                      float* __restrict__ out){
    __shared__ float sm[32][33];
    int j  = blockIdx.y;
    int tc = blockIdx.x & 7;
    int tn = blockIdx.x >> 3;
    int tx = threadIdx.x, ty = threadIdx.y;
    #pragma unroll
    for (int k=0;k<4;k++){
        int n = tn*32 + ty + k*8;
        sm[ty+k*8][tx] = g_grids[((size_t)n*NLAT_ + j)*C_ + tc*32 + tx];
    }
    __syncthreads();
    #pragma unroll
    for (int k=0;k<4;k++){
        int c = tc*32 + ty + k*8;
        int n = tn*32 + tx;
        size_t off = (size_t)c*S_ + (size_t)j*NLON_ + n;
        float v = sm[tx][ty+k*8];
        out[off] = (v - g_mu[c])*g_rstd[c]*gamma[c] + beta[c] + x[off];
    }
}

// ---------------- host side ----------------
#define DEVPTR(T, var, sym) T* var; cudaGetSymbolAddress((void**)&var, sym)

static void launch_gemm(int act, dim3 grid,
    const __half* Ah, const __half* Al, const __half* Bh,
    float* Dout, __half* Oh, __half* Ol,
    const float* biasJ, const float* bscale, const float* addsrc,
    int M, int N, int K,
    long sAi, long sAb, long sBi, long sBb, long sCi, long sCj, long sCb)
{
    if (act)
        mmagemm<1><<<grid,256,SMEM_DYN>>>(Ah,Al,Bh,Dout,Oh,Ol,biasJ,bscale,addsrc,
                                          M,N,K,sAi,sAb,sBi,sBb,sCi,sCj,sCb);
    else
        mmagemm<0><<<grid,256,SMEM_DYN>>>(Ah,Al,Bh,Dout,Oh,Ol,biasJ,bscale,addsrc,
                                          M,N,K,sAi,sAb,sBi,sBb,sCi,sCj,sCb);
}

extern "C" void kernel_launch(void* const* d_in, const int* in_sizes, int n_in,
                              void* d_out, int out_size){
    const float* x      = (const float*)d_in[0];
    const float* leg    = (const float*)d_in[1];
    const float* wquad  = (const float*)d_in[2];
    const float* w_real = (const float*)d_in[3];
    const float* w_imag = (const float*)d_in[4];
    const float* m1w1   = (const float*)d_in[5];
    const float* m1b1   = (const float*)d_in[6];
    const float* m1w2   = (const float*)d_in[7];
    const float* m1b2   = (const float*)d_in[8];
    const float* m2w1   = (const float*)d_in[9];
    const float* m2b1   = (const float*)d_in[10];
    const float* m2w2   = (const float*)d_in[11];
    const float* m2b2   = (const float*)d_in[12];
    const float* gamma  = (const float*)d_in[13];
    const float* beta   = (const float*)d_in[14];
    float* out = (float*)d_out;

    cudaFuncSetAttribute(mmagemm<0>, cudaFuncAttributeMaxDynamicSharedMemorySize, SMEM_DYN);
    cudaFuncSetAttribute(mmagemm<1>, cudaFuncAttributeMaxDynamicSharedMemorySize, SMEM_DYN);

    DEVPTR(__half, xh, g_x_h);  DEVPTR(__half, xl, g_x_l);
    DEVPTR(__half, xth,g_xt_h); DEVPTR(__half, xtl,g_xt_l);
    DEVPTR(__half, lwh,g_lw_h); DEVPTR(__half, lwl,g_lw_l);
    DEVPTR(__half, lgh,g_lg_h); DEVPTR(__half, lgl,g_lg_l);
    DEVPTR(__half, wrh,g_wr_h); DEVPTR(__half, wrl,g_wr_l);
    DEVPTR(__half, wih,g_wi_h); DEVPTR(__half, wil,g_wi_l);
    DEVPTR(__half, Fh, g_F_h);
    DEVPTR(__half, Hh, g_H_h);
    DEVPTR(__half, xrh,g_xr_h);
    DEVPTR(__half, xih,g_xi_h);
    DEVPTR(__half, Gh, g_G_h);
    DEVPTR(__half, mAh,g_mA_h); DEVPTR(__half, mAl,g_mA_l);
    DEVPTR(__half, mBh,g_mB_h); DEVPTR(__half, mBl,g_mB_l);
    DEVPTR(__half, dch,g_dc_h);
    DEVPTR(__half, d2h,g_d2_h); DEVPTR(__half, d2l,g_d2_l);
    DEVPTR(__half, wth,g_wt_h);
    DEVPTR(float, grids, g_grids);
    DEVPTR(float, lsc16, g_lsc16);
    DEVPTR(float, cscale, g_cscale);

    // ---- prep (launch #3 = the big S1 GEMM for ncu) ----
    p_dft    <<<(unsigned)((D2_SZ+255)/256), 256>>>();
    p_split_x<<<(unsigned)((XS_SZ+255)/256), 256>>>(x);
    p_xT     <<<dim3(128, NLAT_), dim3(32,8)>>>(x);

    // ---- S1: rfft DFT-GEMM -> F (ri,m,c,j) hi ----
    launch_gemm(0, dim3(3, 512, 2),
        xh, xl, dch, nullptr, Fh, nullptr, nullptr, nullptr, nullptr,
        C_*NLAT_, M_, NLON_,
        NLON_, 0, NLON_, (long)M_*NLON_,
        1, (long)C_*NLAT_, (long)M_*C_*NLAT_);

    p_lw     <<<(unsigned)((LW_SZ+255)/256), 256>>>(leg, wquad);
    p_legT   <<<dim3(64, M_), dim3(32,8)>>>(leg);
    p_W2     <<<dim3(16, 256), 256>>>(w_real, w_imag);
    p_wT     <<<(C_*C_+255)/256, 256>>>(m1w1, m1w2, m2w1, m2w2);
    p_zeroG2 <<<(unsigned)((NLAT_*C_*(MP_-514)+255)/256), 256>>>();

    // ---- S2: Legendre fwd (batch m). A=16*lw -> H = 16x (l,m,2C) hi ----
    launch_gemm(0, dim3(2, 2, M_),
        lwh, lwl, Fh, nullptr, Hh, nullptr, nullptr, nullptr, nullptr,
        L_, C_, NLAT_,
        (long)M_*NLAT_, NLAT_, NLAT_, (long)C_*NLAT_,
        (long)M_*K2C_, 1, K2C_);
    launch_gemm(0, dim3(2, 2, M_),
        lwh, lwl, Fh + M_*(size_t)C_*NLAT_, nullptr, Hh + C_, nullptr,
        nullptr, nullptr, nullptr,
        L_, C_, NLAT_,
        (long)M_*NLAT_, NLAT_, NLAT_, (long)C_*NLAT_,
        (long)M_*K2C_, 1, K2C_);

    // ---- S3: spectral conv (batch l). bscale=lsc/16 -> xs (m,f,l) hi ----
    launch_gemm(0, dim3(3, 2, L_),
        wrh, wrl, Hh, nullptr, xrh, nullptr, nullptr, lsc16, nullptr,
        C_, M_, K2C_,
        K2C_, (long)C_*K2C_, K2C_, (long)M_*K2C_,
        L_, (long)C_*L_, 1);
    launch_gemm(0, dim3(3, 2, L_),
        wih, wil, Hh, nullptr, xih, nullptr, nullptr, lsc16, nullptr,
        C_, M_, K2C_,
        K2C_, (long)C_*K2C_, K2C_, (long)M_*K2C_,
        L_, (long)C_*L_, 1);

    // ---- S4: Legendre inv (batch m). A=16*lgT -> G = 16x (j,f,576) hi ----
    launch_gemm(0, dim3(2, 2, M_),
        lgh, lgl, xrh, nullptr, Gh, nullptr, nullptr, nullptr, nullptr,
        NLAT_, C_, L_,
        L_, (long)NLAT_*L_, L_, (long)C_*L_,
        (long)C_*MP_, MP_, 1);
    launch_gemm(0, dim3(2, 2, M_),
        lgh, lgl, xih, nullptr, Gh + M_, nullptr, nullptr, nullptr, nullptr,
        NLAT_, C_, L_,
        L_, (long)NLAT_*L_, L_, (long)C_*L_,
        (long)C_*MP_, MP_, 1);

    // ---- S5: irfft + GELU. A=256*d2, B=16*G -> *1/4096 fp32 grids ----
    launch_gemm(1, dim3(512, 4, 1),
        d2h, d2l, Gh, grids, nullptr, nullptr, nullptr, cscale+1, nullptr,
        NLON_, NLAT_*C_, MP_,
        MP_, 0, MP_, 0,
        (long)NLAT_*C_, 1, 0);

    // ---- MLPs: B = 16*wT, bscale = 1/16 ----
    launch_gemm(1, dim3(2, 1024, 1),
        xth, xtl, wth + 0, nullptr, mAh, mAl, m1b1, cscale, nullptr,
        S_, C_, C_, C_, 0, C_, 0, C_, 1, 0);
    launch_gemm(1, dim3(2, 1024, 1),
        mAh, mAl, wth + C_*C_, nullptr, mBh, mBl, m1b2, cscale, grids,
        S_, C_, C_, C_, 0, C_, 0, C_, 1, 0);
    launch_gemm(1, dim3(2, 1024, 1),
        mBh, mBl, wth + 2*C_*C_, nullptr, mAh, mAl, m2b1, cscale, nullptr,
        S_, C_, C_, C_, 0, C_, 0, C_, 1, 0);
    launch_gemm(1, dim3(2, 1024, 1),
        mAh, mAl, wth + 3*C_*C_, grids, nullptr, nullptr, m2b2, cscale, nullptr,
        S_, C_, C_, C_, 0, C_, 0, C_, 1, 0);

    // ---- instance norm + residual + transpose out ----
    norm1_k<<<512, 256>>>();
    norm2_k<<<1, 256>>>();
    fin_k<<<dim3(128, NLAT_), dim3(32,8)>>>(x, gamma, beta, out);
}

// round 9
// speedup vs baseline: 1.6415x; 1.0231x over previous
#include <cuda_runtime.h>
#include <cuda_fp16.h>
#include <math.h>

#define C_    256
#define NLAT_ 256
#define NLON_ 512
#define L_    256
#define M_    257
#define NREF_ 64
#define S_    (NLAT_*NLON_)
#define K2C_  512
#define MP_   544               // 2*M=514 padded to mult of 32

#define XS_SZ   ((size_t)C_*S_)
#define LW_SZ   ((size_t)L_*M_*NLAT_)
#define LGT_SZ  ((size_t)M_*NLAT_*L_)
#define WC_SZ   ((size_t)L_*C_*K2C_)
#define F_SZ    ((size_t)2*M_*C_*NLAT_)
#define H_SZ    ((size_t)L_*M_*K2C_)
#define XSP_SZ  ((size_t)M_*C_*L_)
#define G2_SZ   ((size_t)NLAT_*C_*MP_)
#define DCS_SZ  ((size_t)2*M_*NLON_)
#define D2_SZ   ((size_t)NLON_*MP_)

// A-side operands keep hi+lo; B-side / intermediates are hi-only.
__device__ __align__(128) __half g_x_h[XS_SZ],  g_x_l[XS_SZ];
__device__ __align__(128) __half g_xt_h[XS_SZ], g_xt_l[XS_SZ];
__device__ __align__(128) __half g_lw_h[LW_SZ], g_lw_l[LW_SZ];
__device__ __align__(128) __half g_lg_h[LGT_SZ],g_lg_l[LGT_SZ];
__device__ __align__(128) __half g_wr_h[WC_SZ], g_wr_l[WC_SZ];
__device__ __align__(128) __half g_wi_h[WC_SZ], g_wi_l[WC_SZ];
__device__ __align__(128) __half g_F_h[F_SZ];
__device__ __align__(128) __half g_H_h[H_SZ];
__device__ __align__(128) __half g_xr_h[XSP_SZ];
__device__ __align__(128) __half g_xi_h[XSP_SZ];
__device__ __align__(128) __half g_G_h[G2_SZ];
__device__ __align__(128) __half g_mA_h[XS_SZ], g_mA_l[XS_SZ];
__device__ __align__(128) __half g_mB_h[XS_SZ], g_mB_l[XS_SZ];
__device__ __align__(128) __half g_dc_h[DCS_SZ];
__device__ __align__(128) __half g_d2_h[D2_SZ], g_d2_l[D2_SZ];
__device__ __align__(128) __half g_wt_h[4*C_*C_], g_wt_l[4*C_*C_];
__device__ __align__(128) float g_grids[XS_SZ];
__device__ float g_lsc16[L_];
__device__ float g_cscale[2];        // {1/16, 1/4096}
__device__ float g_part[2][512][C_];
__device__ float g_mu[C_], g_rstd[C_];

__device__ __forceinline__ float gelu_f(float v){
    return 0.5f*v*(1.0f + erff(v*0.7071067811865476f));
}
__device__ __forceinline__ void split2(float v, __half* H, __half* Lo, size_t off){
    __half h = __float2half_rn(v);
    H[off]  = h;
    if (Lo) Lo[off] = __float2half_rn(v - __half2float(h));
}
__device__ __forceinline__ unsigned smem_u32(const void* p){
    unsigned a;
    asm("{ .reg .u64 t; cvta.to.shared.u64 t, %1; cvt.u32.u64 %0, t; }" : "=r"(a) : "l"(p));
    return a;
}
// 64B rows: byte offset of 32-bit word w (0..15) in row r, 16B chunks xor (r>>1)&3
__device__ __forceinline__ int swadr(int r, int w){
    return r*64 + ((((w>>2) ^ ((r>>1)&3))) << 4) + ((w & 3) << 2);
}
__device__ __forceinline__ void cpa16(unsigned saddr, const void* g, bool v){
    asm volatile("cp.async.cg.shared.global [%0], [%1], 16, %2;"
                 :: "r"(saddr), "l"(g), "r"(v ? 16 : 0));
}
#define CP_COMMIT() asm volatile("cp.async.commit_group;")
#define LDMX4(r0,r1,r2,r3,addr) \
    asm volatile("ldmatrix.sync.aligned.m8n8.x4.shared.b16 {%0,%1,%2,%3}, [%4];" \
        : "=r"(r0),"=r"(r1),"=r"(r2),"=r"(r3) : "r"(addr))
#define MMA_OP(cc, aa, bb) asm volatile( \
    "mma.sync.aligned.m16n8k16.row.col.f32.f16.f16.f32 " \
    "{%0,%1,%2,%3},{%4,%5,%6,%7},{%8,%9},{%0,%1,%2,%3};" \
    : "+f"(cc[0]),"+f"(cc[1]),"+f"(cc[2]),"+f"(cc[3]) \
    : "r"(aa[0]),"r"(aa[1]),"r"(aa[2]),"r"(aa[3]),"r"(bb[0]),"r"(bb[1]))

// ---------------- prep kernels ----------------
__global__ void p_split_x(const float* __restrict__ x){
    size_t i = (size_t)blockIdx.x*256 + threadIdx.x;
    if (i >= XS_SZ) return;
    split2(x[i], g_x_h, g_x_l, i);
}
__global__ void p_xT(const float* __restrict__ x){
    __shared__ float sm[32][33];
    int j  = blockIdx.y;
    int tc = blockIdx.x & 7;
    int tn = blockIdx.x >> 3;
    int tx = threadIdx.x, ty = threadIdx.y;
    #pragma unroll
    for (int k=0;k<4;k++){
        int c = tc*32 + ty + k*8;
        sm[ty+k*8][tx] = x[(size_t)c*S_ + (size_t)j*NLON_ + tn*32 + tx];
    }
    __syncthreads();
    #pragma unroll
    for (int k=0;k<4;k++){
        int n = tn*32 + ty + k*8;
        int c = tc*32 + tx;
        size_t off = ((size_t)n*NLAT_ + j)*C_ + c;
        split2(sm[tx][ty+k*8], g_xt_h, g_xt_l, off);
    }
}
__global__ void p_lw(const float* __restrict__ leg, const float* __restrict__ wq){
    size_t i = (size_t)blockIdx.x*256 + threadIdx.x;
    if (i >= LW_SZ) return;
    split2(16.0f*leg[i]*wq[i & (NLAT_-1)], g_lw_h, g_lw_l, i);
}
__global__ void p_legT(const float* __restrict__ leg){
    __shared__ float sm[32][33];
    int m  = blockIdx.y;
    int tl = blockIdx.x & 7;
    int tj = blockIdx.x >> 3;
    int tx = threadIdx.x, ty = threadIdx.y;
    #pragma unroll
    for (int k=0;k<4;k++){
        int l = tl*32 + ty + k*8;
        sm[ty+k*8][tx] = leg[(size_t)l*M_*NLAT_ + (size_t)m*NLAT_ + tj*32 + tx];
    }
    __syncthreads();
    #pragma unroll
    for (int k=0;k<4;k++){
        int j = tj*32 + ty + k*8;
        int l = tl*32 + tx;
        size_t off = ((size_t)m*NLAT_ + j)*L_ + l;
        split2(16.0f*sm[tx][ty+k*8], g_lg_h, g_lg_l, off);
    }
}
// tiled filter interpolation: block = (l-tile of 16, f), smem-staged refs
__global__ void p_W2(const float* __restrict__ wr, const float* __restrict__ wi){
    __shared__ float sr[256][8], si[256][8];
    int f  = blockIdx.y;
    int l0 = blockIdx.x * 16;
    int c  = threadIdx.x;
    int i0min = (l0*(NREF_-1)) / (L_-1);
    if (i0min > NREF_-8) i0min = NREF_-8;
    size_t rb = ((size_t)f*C_ + c)*NREF_ + i0min;
    #pragma unroll
    for (int k=0;k<8;k++){ sr[c][k] = wr[rb+k]; si[c][k] = wi[rb+k]; }
    __syncthreads();
    #pragma unroll 4
    for (int li=0; li<16; li++){
        int l = l0 + li;
        float pos = (float)(l*(NREF_-1)) / (float)(L_-1);
        int i0 = (int)floorf(pos);
        if (i0 > NREF_-2) i0 = NREF_-2;
        float fr = pos - (float)i0;
        int k = i0 - i0min;
        float vre = sr[c][k]*(1.0f-fr) + sr[c][k+1]*fr;
        float vim = si[c][k]*(1.0f-fr) + si[c][k+1]*fr;
        size_t ob = ((size_t)l*C_ + f)*K2C_;
        split2( vre, g_wr_h, g_wr_l, ob + c);
        split2(-vim, g_wr_h, g_wr_l, ob + C_ + c);
        split2( vim, g_wi_h, g_wi_l, ob + c);
        split2( vre, g_wi_h, g_wi_l, ob + C_ + c);
    }
}
__global__ void p_dft(){
    int i = blockIdx.x*256 + threadIdx.x;
    if (i < L_) g_lsc16[i] = sqrtf(1.0f + (float)i) * (1.0f/(float)C_) * (1.0f/16.0f);
    if (i < 2)  g_cscale[i] = (i==0) ? 0.0625f : (1.0f/4096.0f);
    if (i < (int)DCS_SZ){
        int n = i & 511;
        int m = (i >> 9) % M_;
        int ri = i / (M_*NLON_);
        int a = (m*n) & 511;
        float ang = (float)a * (1.0f/256.0f);
        float v = ri ? -sinpif(ang) : cospif(ang);
        g_dc_h[i] = __float2half_rn(v);
    }
    if (i < (int)D2_SZ){
        int mp = i % MP_;
        int n  = i / MP_;
        float v = 0.f;
        if (mp < M_){
            float wm = (mp==0 || mp==M_-1) ? 1.0f : 2.0f;
            int a = (mp*n) & 511;
            v = wm * cospif((float)a*(1.0f/256.0f)) * 0.5f;    // 256x of /512
        } else if (mp < 2*M_){
            int m2 = mp - M_;
            float wm = (m2==0 || m2==M_-1) ? 1.0f : 2.0f;
            int a = (m2*n) & 511;
            v = -wm * sinpif((float)a*(1.0f/256.0f)) * 0.5f;
        }
        split2(v, g_d2_h, g_d2_l, (size_t)i);
    }
}
__global__ void p_wT(const float* w1, const float* w2, const float* w3, const float* w4){
    int i = blockIdx.x*256 + threadIdx.x;
    if (i >= C_*C_) return;
    int c = i / C_, cp = i % C_;
    const float* ws[4] = {w1, w2, w3, w4};
    #pragma unroll
    for (int k=0;k<4;k++)
        split2(16.0f*ws[k][i], g_wt_h, g_wt_l, (size_t)k*C_*C_ + (size_t)cp*C_ + c);
}
__global__ void p_zeroG2(){
    int i = blockIdx.x*256 + threadIdx.x;
    int nz = MP_ - 514;
    int tot = NLAT_*C_*nz;
    if (i >= tot) return;
    int k  = i % nz;
    int jf = i / nz;
    g_G_h[(size_t)jf*MP_ + 514 + k] = __float2half_rn(0.f);
}

// ---------------- pipelined mma.sync 2-pass split-fp16 GEMM ----------------
// D = (Ah+Al)·Bh^T, 128x128 tile, K-chunk 32, 3-stage cp.async.
// Stage 24KB: Ah[0,8K) Al[8K,16K) Bh[16K,24K); rows 64B wide.
#define STGB 24576
#define NSTG 3
#define SMEM_DYN (NSTG*STGB)

template<int ACT>
__global__ __launch_bounds__(256) void mmagemm(
    const __half* __restrict__ Ah, const __half* __restrict__ Al,
    const __half* __restrict__ Bh,
    float* __restrict__ Dout,
    __half* __restrict__ Oh, __half* __restrict__ Ol,
    const float* __restrict__ biasJ, const float* __restrict__ bscale,
    const float* __restrict__ addsrc,
    int Mrows, int Ncols, int K,
    long sAi, long sAb, long sBi, long sBb,
    long sCi, long sCj, long sCb)
{
    extern __shared__ char dsm[];
    const unsigned sb = smem_u32(dsm);

    const int t    = threadIdx.x;
    const int lane = t & 31;
    const int warp = t >> 5;
    const int g    = lane >> 2;
    const int tig  = lane & 3;
    const int mm   = lane >> 3;
    const int rrl  = lane & 7;
    const int wm   = warp >> 2;
    const int wn   = warp & 3;
    const int bz   = blockIdx.z;
    const long i0  = (long)blockIdx.y * 128;
    const long j0  = (long)blockIdx.x * 128;

    const __half* Ahb = Ah + (long)bz*sAb;
    const __half* Alb = Al + (long)bz*sAb;
    const __half* Bhb = Bh + (long)bz*sBb;

    const int row   = t >> 1;
    const int half  = t & 1;
    const long arow = i0 + row;
    const long brow = j0 + row;
    const bool bok  = brow < (long)Ncols;
    const long aoff = arow * sAi;
    const long boff = brow * sBi;

    float acc[64];
    #pragma unroll
    for (int i=0;i<64;i++) acc[i] = 0.f;

    auto load_stage = [&](int ks, int s){
        unsigned st = sb + s*STGB;
        long kg = (long)ks*32;
        #pragma unroll
        for (int q=0;q<2;q++){
            int c = half*2 + q;
            long ke = kg + c*8;
            unsigned so = (unsigned)(row*64 + ((c ^ ((row>>1)&3)) << 4));
            cpa16(st + so,          Ahb + aoff + ke, true);
            cpa16(st + 8192 + so,   Alb + aoff + ke, true);
            cpa16(st + 16384 + so,  Bhb + boff + ke, bok);
        }
    };

    const int nk = K >> 5;
    load_stage(0, 0);
    CP_COMMIT();
    if (nk > 1){ load_stage(1, 1); }
    CP_COMMIT();

    for (int ks = 0; ks < nk; ks++){
        // groups outstanding: ks, ks+1 (if present). Wait until chunk ks ready.
        if (ks + 1 < nk) asm volatile("cp.async.wait_group 1;");
        else             asm volatile("cp.async.wait_group 0;");
        __syncthreads();

        const unsigned sA = sb + (ks % NSTG)*STGB;
        const unsigned sB = sA + 16384;
        #pragma unroll
        for (int kk=0; kk<2; kk++){
            unsigned ah[4][4], al[4][4], bh[4][2];
            #pragma unroll
            for (int p=0;p<2;p++){
                int rowB = wn*32 + (p*2 + (mm>>1))*8 + rrl;
                int wB   = kk*8 + (mm&1)*4;
                unsigned ad = sB + (unsigned)swadr(rowB, wB);
                LDMX4(bh[p*2][0], bh[p*2][1], bh[p*2+1][0], bh[p*2+1][1], ad);
            }
            #pragma unroll
            for (int mt=0; mt<4; mt++){
                int rowA = wm*64 + mt*16 + (mm&1)*8 + rrl;
                int wA   = kk*8 + (mm>>1)*4;
                unsigned ad = sA + (unsigned)swadr(rowA, wA);
                LDMX4(ah[mt][0], ah[mt][1], ah[mt][2], ah[mt][3], ad);
                LDMX4(al[mt][0], al[mt][1], al[mt][2], al[mt][3], ad + 8192);
            }
            #pragma unroll
            for (int mt=0; mt<4; mt++)
                #pragma unroll
                for (int nt=0; nt<4; nt++) MMA_OP((&acc[(mt*4+nt)*4]), ah[mt], bh[nt]);
            #pragma unroll
            for (int mt=0; mt<4; mt++)
                #pragma unroll
                for (int nt=0; nt<4; nt++) MMA_OP((&acc[(mt*4+nt)*4]), al[mt], bh[nt]);
        }
        if (ks + 2 < nk){
            load_stage(ks+2, (ks+2) % NSTG);
        }
        CP_COMMIT();
    }

    // ---------------- epilogue ----------------
    float scl = bscale ? bscale[bz] : 1.0f;
    #pragma unroll
    for (int mt=0; mt<4; mt++){
        long rA = i0 + wm*64 + mt*16 + g;
        #pragma unroll
        for (int nt=0; nt<4; nt++){
            long cB = j0 + wn*32 + nt*8 + 2*tig;
            float* a = &acc[(mt*4+nt)*4];
            #pragma unroll
            for (int h2=0; h2<2; h2++){
                long rowg = rA + h2*8;
                if (rowg >= (long)Mrows) continue;
                long offr = (long)bz*sCb + rowg*sCi;
                if (sCj == 1 && cB + 1 < (long)Ncols){
                    float v0 = a[h2*2+0] * scl;
                    float v1 = a[h2*2+1] * scl;
                    if (biasJ){ v0 += biasJ[cB]; v1 += biasJ[cB+1]; }
                    if (ACT == 1){ v0 = gelu_f(v0); v1 = gelu_f(v1); }
                    long off = offr + cB;
                    if (addsrc){ v0 += addsrc[off]; v1 += addsrc[off+1]; }
                    if (Dout) *(float2*)(Dout + off) = make_float2(v0, v1);
                    if (Oh){
                        __half h0 = __float2half_rn(v0), h1 = __float2half_rn(v1);
                        *(__half2*)(Oh + off) = __halves2half2(h0, h1);
                        if (Ol) *(__half2*)(Ol + off) = __halves2half2(
                            __float2half_rn(v0 - __half2float(h0)),
                            __float2half_rn(v1 - __half2float(h1)));
                    }
                } else {
                    #pragma unroll
                    for (int q=0; q<2; q++){
                        long col = cB + q;
                        if (col >= (long)Ncols) continue;
                        float v = a[h2*2+q] * scl;
                        if (biasJ) v += biasJ[col];
                        if (ACT == 1) v = gelu_f(v);
                        long off = offr + col*sCj;
                        if (addsrc) v += addsrc[off];
                        if (Dout) Dout[off] = v;
                        if (Oh) split2(v, Oh, Ol, (size_t)off);
                    }
                }
            }
        }
    }
}

// ---------------- norm + finalize ----------------
__global__ void norm1_k(){
    int b = blockIdx.x, c = threadIdx.x;
    const float* base = g_grids + (size_t)b*256*C_;
    float s=0.f, q=0.f;
    for (int r=0;r<256;r++){
        float v = base[(size_t)r*C_ + c];
        s += v; q = fmaf(v,v,q);
    }
    g_part[0][b][c] = s;
    g_part[1][b][c] = q;
}
__global__ void norm2_k(){
    int c = threadIdx.x;
    float s=0.f, q=0.f;
    for (int b=0;b<512;b++){ s += g_part[0][b][c]; q += g_part[1][b][c]; }
    float mu = s * (1.0f/(float)S_);
    float var = q * (1.0f/(float)S_) - mu*mu;
    g_mu[c] = mu;
    g_rstd[c] = rsqrtf(var + 1e-3f);
}
__global__ void fin_k(const float* __restrict__ x,
                      const float* __restrict__ gamma,
                      const float* __restrict__ beta,
                      float* __restrict__ out){
    __shared__ float sm[32][33];
    int j  = blockIdx.y;
    int tc = blockIdx.x & 7;
    int tn = blockIdx.x >> 3;
    int tx = threadIdx.x, ty = threadIdx.y;
    #pragma unroll
    for (int k=0;k<4;k++){
        int n = tn*32 + ty + k*8;
        sm[ty+k*8][tx] = g_grids[((size_t)n*NLAT_ + j)*C_ + tc*32 + tx];
    }
    __syncthreads();
    #pragma unroll
    for (int k=0;k<4;k++){
        int c = tc*32 + ty + k*8;
        int n = tn*32 + tx;
        size_t off = (size_t)c*S_ + (size_t)j*NLON_ + n;
        float v = sm[tx][ty+k*8];
        out[off] = (v - g_mu[c])*g_rstd[c]*gamma[c] + beta[c] + x[off];
    }
}

// ---------------- host side ----------------
#define DEVPTR(T, var, sym) T* var; cudaGetSymbolAddress((void**)&var, sym)

static void launch_gemm(int act, dim3 grid,
    const __half* Ah, const __half* Al, const __half* Bh,
    float* Dout, __half* Oh, __half* Ol,
    const float* biasJ, const float* bscale, const float* addsrc,
    int M, int N, int K,
    long sAi, long sAb, long sBi, long sBb, long sCi, long sCj, long sCb)
{
    if (act)
        mmagemm<1><<<grid,256,SMEM_DYN>>>(Ah,Al,Bh,Dout,Oh,Ol,biasJ,bscale,addsrc,
                                          M,N,K,sAi,sAb,sBi,sBb,sCi,sCj,sCb);
    else
        mmagemm<0><<<grid,256,SMEM_DYN>>>(Ah,Al,Bh,Dout,Oh,Ol,biasJ,bscale,addsrc,
                                          M,N,K,sAi,sAb,sBi,sBb,sCi,sCj,sCb);
}

extern "C" void kernel_launch(void* const* d_in, const int* in_sizes, int n_in,
                              void* d_out, int out_size){
    const float* x      = (const float*)d_in[0];
    const float* leg    = (const float*)d_in[1];
    const float* wquad  = (const float*)d_in[2];
    const float* w_real = (const float*)d_in[3];
    const float* w_imag = (const float*)d_in[4];
    const float* m1w1   = (const float*)d_in[5];
    const float* m1b1   = (const float*)d_in[6];
    const float* m1w2   = (const float*)d_in[7];
    const float* m1b2   = (const float*)d_in[8];
    const float* m2w1   = (const float*)d_in[9];
    const float* m2b1   = (const float*)d_in[10];
    const float* m2w2   = (const float*)d_in[11];
    const float* m2b2   = (const float*)d_in[12];
    const float* gamma  = (const float*)d_in[13];
    const float* beta   = (const float*)d_in[14];
    float* out = (float*)d_out;

    cudaFuncSetAttribute(mmagemm<0>, cudaFuncAttributeMaxDynamicSharedMemorySize, SMEM_DYN);
    cudaFuncSetAttribute(mmagemm<1>, cudaFuncAttributeMaxDynamicSharedMemorySize, SMEM_DYN);

    DEVPTR(__half, xh, g_x_h);  DEVPTR(__half, xl, g_x_l);
    DEVPTR(__half, xth,g_xt_h); DEVPTR(__half, xtl,g_xt_l);
    DEVPTR(__half, lwh,g_lw_h); DEVPTR(__half, lwl,g_lw_l);
    DEVPTR(__half, lgh,g_lg_h); DEVPTR(__half, lgl,g_lg_l);
    DEVPTR(__half, wrh,g_wr_h); DEVPTR(__half, wrl,g_wr_l);
    DEVPTR(__half, wih,g_wi_h); DEVPTR(__half, wil,g_wi_l);
    DEVPTR(__half, Fh, g_F_h);
    DEVPTR(__half, Hh, g_H_h);
    DEVPTR(__half, xrh,g_xr_h);
    DEVPTR(__half, xih,g_xi_h);
    DEVPTR(__half, Gh, g_G_h);
    DEVPTR(__half, mAh,g_mA_h); DEVPTR(__half, mAl,g_mA_l);
    DEVPTR(__half, mBh,g_mB_h); DEVPTR(__half, mBl,g_mB_l);
    DEVPTR(__half, dch,g_dc_h);
    DEVPTR(__half, d2h,g_d2_h); DEVPTR(__half, d2l,g_d2_l);
    DEVPTR(__half, wth,g_wt_h);
    DEVPTR(float, grids, g_grids);
    DEVPTR(float, lsc16, g_lsc16);
    DEVPTR(float, cscale, g_cscale);

    // ---- prep (launch #3 = the big S1 GEMM for ncu) ----
    p_dft    <<<(unsigned)((D2_SZ+255)/256), 256>>>();
    p_split_x<<<(unsigned)((XS_SZ+255)/256), 256>>>(x);
    p_xT     <<<dim3(128, NLAT_), dim3(32,8)>>>(x);

    // ---- S1: rfft DFT-GEMM -> F (ri,m,c,j) hi ----
    launch_gemm(0, dim3(3, 512, 2),
        xh, xl, dch, nullptr, Fh, nullptr, nullptr, nullptr, nullptr,
        C_*NLAT_, M_, NLON_,
        NLON_, 0, NLON_, (long)M_*NLON_,
        1, (long)C_*NLAT_, (long)M_*C_*NLAT_);

    p_lw     <<<(unsigned)((LW_SZ+255)/256), 256>>>(leg, wquad);
    p_legT   <<<dim3(64, M_), dim3(32,8)>>>(leg);
    p_W2     <<<dim3(16, 256), 256>>>(w_real, w_imag);
    p_wT     <<<(C_*C_+255)/256, 256>>>(m1w1, m1w2, m2w1, m2w2);
    p_zeroG2 <<<(unsigned)((NLAT_*C_*(MP_-514)+255)/256), 256>>>();

    // ---- S2: Legendre fwd (batch m). A=16*lw -> H = 16x (l,m,2C) hi ----
    launch_gemm(0, dim3(2, 2, M_),
        lwh, lwl, Fh, nullptr, Hh, nullptr, nullptr, nullptr, nullptr,
        L_, C_, NLAT_,
        (long)M_*NLAT_, NLAT_, NLAT_, (long)C_*NLAT_,
        (long)M_*K2C_, 1, K2C_);
    launch_gemm(0, dim3(2, 2, M_),
        lwh, lwl, Fh + M_*(size_t)C_*NLAT_, nullptr, Hh + C_, nullptr,
        nullptr, nullptr, nullptr,
        L_, C_, NLAT_,
        (long)M_*NLAT_, NLAT_, NLAT_, (long)C_*NLAT_,
        (long)M_*K2C_, 1, K2C_);

    // ---- S3: spectral conv (batch l). bscale=lsc/16 -> xs (m,f,l) hi ----
    launch_gemm(0, dim3(3, 2, L_),
        wrh, wrl, Hh, nullptr, xrh, nullptr, nullptr, lsc16, nullptr,
        C_, M_, K2C_,
        K2C_, (long)C_*K2C_, K2C_, (long)M_*K2C_,
        L_, (long)C_*L_, 1);
    launch_gemm(0, dim3(3, 2, L_),
        wih, wil, Hh, nullptr, xih, nullptr, nullptr, lsc16, nullptr,
        C_, M_, K2C_,
        K2C_, (long)C_*K2C_, K2C_, (long)M_*K2C_,
        L_, (long)C_*L_, 1);

    // ---- S4: Legendre inv (batch m). A=16*lgT -> G = 16x (j,f,544) hi ----
    launch_gemm(0, dim3(2, 2, M_),
        lgh, lgl, xrh, nullptr, Gh, nullptr, nullptr, nullptr, nullptr,
        NLAT_, C_, L_,
        L_, (long)NLAT_*L_, L_, (long)C_*L_,
        (long)C_*MP_, MP_, 1);
    launch_gemm(0, dim3(2, 2, M_),
        lgh, lgl, xih, nullptr, Gh + M_, nullptr, nullptr, nullptr, nullptr,
        NLAT_, C_, L_,
        L_, (long)NLAT_*L_, L_, (long)C_*L_,
        (long)C_*MP_, MP_, 1);

    // ---- S5: irfft + GELU. A=256*d2, B=16*G -> *1/4096 fp32 grids ----
    launch_gemm(1, dim3(512, 4, 1),
        d2h, d2l, Gh, grids, nullptr, nullptr, nullptr, cscale+1, nullptr,
        NLON_, NLAT_*C_, MP_,
        MP_, 0, MP_, 0,
        (long)NLAT_*C_, 1, 0);

    // ---- MLPs: B = 16*wT, bscale = 1/16 ----
    launch_gemm(1, dim3(2, 1024, 1),
        xth, xtl, wth + 0, nullptr, mAh, mAl, m1b1, cscale, nullptr,
        S_, C_, C_, C_, 0, C_, 0, C_, 1, 0);
    launch_gemm(1, dim3(2, 1024, 1),
        mAh, mAl, wth + C_*C_, nullptr, mBh, mBl, m1b2, cscale, grids,
        S_, C_, C_, C_, 0, C_, 0, C_, 1, 0);
    launch_gemm(1, dim3(2, 1024, 1),
        mBh, mBl, wth + 2*C_*C_, nullptr, mAh, mAl, m2b1, cscale, nullptr,
        S_, C_, C_, C_, 0, C_, 0, C_, 1, 0);
    launch_gemm(1, dim3(2, 1024, 1),
        mAh, mAl, wth + 3*C_*C_, grids, nullptr, nullptr, m2b2, cscale, nullptr,
        S_, C_, C_, C_, 0, C_, 0, C_, 1, 0);

    // ---- instance norm + residual + transpose out ----
    norm1_k<<<512, 256>>>();
    norm2_k<<<1, 256>>>();
    fin_k<<<dim3(128, NLAT_), dim3(32,8)>>>(x, gamma, beta, out);
}

// round 10
// speedup vs baseline: 1.7652x; 1.0754x over previous
#include <cuda_runtime.h>
#include <cuda_fp16.h>
#include <math.h>

#define C_    256
#define NLAT_ 256
#define NLON_ 512
#define L_    256
#define M_    257
#define NREF_ 64
#define S_    (NLAT_*NLON_)
#define K2C_  512
#define MP_   544               // 2*M=514 padded to mult of 32

#define XS_SZ   ((size_t)C_*S_)
#define LW_SZ   ((size_t)L_*M_*NLAT_)
#define LGT_SZ  ((size_t)M_*NLAT_*L_)
#define WC_SZ   ((size_t)L_*C_*K2C_)
#define F_SZ    ((size_t)2*M_*C_*NLAT_)
#define H_SZ    ((size_t)L_*M_*K2C_)
#define XSP_SZ  ((size_t)M_*C_*L_)
#define G2_SZ   ((size_t)NLAT_*C_*MP_)
#define DCS_SZ  ((size_t)2*M_*NLON_)
#define D2_SZ   ((size_t)NLON_*MP_)

__device__ __align__(128) __half g_x_h[XS_SZ],  g_x_l[XS_SZ];
__device__ __align__(128) __half g_xt_h[XS_SZ], g_xt_l[XS_SZ];
__device__ __align__(128) __half g_lw_h[LW_SZ], g_lw_l[LW_SZ];
__device__ __align__(128) __half g_lg_h[LGT_SZ],g_lg_l[LGT_SZ];
__device__ __align__(128) __half g_wr_h[WC_SZ], g_wr_l[WC_SZ];
__device__ __align__(128) __half g_wi_h[WC_SZ], g_wi_l[WC_SZ];
__device__ __align__(128) __half g_F_h[F_SZ];
__device__ __align__(128) __half g_H_h[H_SZ];
__device__ __align__(128) __half g_xr_h[XSP_SZ];
__device__ __align__(128) __half g_xi_h[XSP_SZ];
__device__ __align__(128) __half g_G_h[G2_SZ];
__device__ __align__(128) __half g_mA_h[XS_SZ], g_mA_l[XS_SZ];
__device__ __align__(128) __half g_mB_h[XS_SZ], g_mB_l[XS_SZ];
__device__ __align__(128) __half g_dc_h[DCS_SZ];
__device__ __align__(128) __half g_d2_h[D2_SZ];
__device__ __align__(128) __half g_wt_h[4*C_*C_], g_wt_l[4*C_*C_];
__device__ __align__(128) float g_grids[XS_SZ];
__device__ float g_lsc16[L_];
__device__ float g_cscale[2];        // {1/16, 1/4096}
__device__ float g_part[2][512][C_];
__device__ float g_mu[C_], g_rstd[C_];

__device__ __forceinline__ float gelu_f(float v){
    return 0.5f*v*(1.0f + erff(v*0.7071067811865476f));
}
__device__ __forceinline__ void split2(float v, __half* H, __half* Lo, size_t off){
    __half h = __float2half_rn(v);
    H[off]  = h;
    if (Lo) Lo[off] = __float2half_rn(v - __half2float(h));
}
__device__ __forceinline__ unsigned smem_u32(const void* p){
    unsigned a;
    asm("{ .reg .u64 t; cvta.to.shared.u64 t, %1; cvt.u32.u64 %0, t; }" : "=r"(a) : "l"(p));
    return a;
}
__device__ __forceinline__ int swadr(int r, int w){
    return r*64 + ((((w>>2) ^ ((r>>1)&3))) << 4) + ((w & 3) << 2);
}
__device__ __forceinline__ void cpa16(unsigned saddr, const void* g, bool v){
    asm volatile("cp.async.cg.shared.global [%0], [%1], 16, %2;"
                 :: "r"(saddr), "l"(g), "r"(v ? 16 : 0));
}
#define CP_COMMIT() asm volatile("cp.async.commit_group;")
#define LDMX4(r0,r1,r2,r3,addr) \
    asm volatile("ldmatrix.sync.aligned.m8n8.x4.shared.b16 {%0,%1,%2,%3}, [%4];" \
        : "=r"(r0),"=r"(r1),"=r"(r2),"=r"(r3) : "r"(addr))
#define MMA_OP(cc, aa, bb) asm volatile( \
    "mma.sync.aligned.m16n8k16.row.col.f32.f16.f16.f32 " \
    "{%0,%1,%2,%3},{%4,%5,%6,%7},{%8,%9},{%0,%1,%2,%3};" \
    : "+f"(cc[0]),"+f"(cc[1]),"+f"(cc[2]),"+f"(cc[3]) \
    : "r"(aa[0]),"r"(aa[1]),"r"(aa[2]),"r"(aa[3]),"r"(bb[0]),"r"(bb[1]))

// ---------------- prep kernels ----------------
// fused: x -> x_h/x_l (c,j,n) AND xT_h/xT_l (s=n*256+j, c)
__global__ void p_xT2(const float* __restrict__ x){
    __shared__ float sm[32][33];
    int j  = blockIdx.y;
    int tc = blockIdx.x & 7;
    int tn = blockIdx.x >> 3;
    int tx = threadIdx.x, ty = threadIdx.y;
    #pragma unroll
    for (int k=0;k<4;k++){
        int c = tc*32 + ty + k*8;
        size_t offx = (size_t)c*S_ + (size_t)j*NLON_ + tn*32 + tx;
        float v = x[offx];
        sm[ty+k*8][tx] = v;
        split2(v, g_x_h, g_x_l, offx);
    }
    __syncthreads();
    #pragma unroll
    for (int k=0;k<4;k++){
        int n = tn*32 + ty + k*8;
        int c = tc*32 + tx;
        size_t off = ((size_t)n*NLAT_ + j)*C_ + c;
        split2(sm[tx][ty+k*8], g_xt_h, g_xt_l, off);
    }
}
__global__ void p_lw(const float* __restrict__ leg, const float* __restrict__ wq){
    size_t i = (size_t)blockIdx.x*256 + threadIdx.x;
    if (i >= LW_SZ) return;
    split2(16.0f*leg[i]*wq[i & (NLAT_-1)], g_lw_h, g_lw_l, i);
}
__global__ void p_legT(const float* __restrict__ leg){
    __shared__ float sm[32][33];
    int m  = blockIdx.y;
    int tl = blockIdx.x & 7;
    int tj = blockIdx.x >> 3;
    int tx = threadIdx.x, ty = threadIdx.y;
    #pragma unroll
    for (int k=0;k<4;k++){
        int l = tl*32 + ty + k*8;
        sm[ty+k*8][tx] = leg[(size_t)l*M_*NLAT_ + (size_t)m*NLAT_ + tj*32 + tx];
    }
    __syncthreads();
    #pragma unroll
    for (int k=0;k<4;k++){
        int j = tj*32 + ty + k*8;
        int l = tl*32 + tx;
        size_t off = ((size_t)m*NLAT_ + j)*L_ + l;
        split2(16.0f*sm[tx][ty+k*8], g_lg_h, g_lg_l, off);
    }
}
__global__ void p_W2(const float* __restrict__ wr, const float* __restrict__ wi){
    __shared__ float sr[256][8], si[256][8];
    int f  = blockIdx.y;
    int l0 = blockIdx.x * 16;
    int c  = threadIdx.x;
    int i0min = (l0*(NREF_-1)) / (L_-1);
    if (i0min > NREF_-8) i0min = NREF_-8;
    size_t rb = ((size_t)f*C_ + c)*NREF_ + i0min;
    #pragma unroll
    for (int k=0;k<8;k++){ sr[c][k] = wr[rb+k]; si[c][k] = wi[rb+k]; }
    __syncthreads();
    #pragma unroll 4
    for (int li=0; li<16; li++){
        int l = l0 + li;
        float pos = (float)(l*(NREF_-1)) / (float)(L_-1);
        int i0 = (int)floorf(pos);
        if (i0 > NREF_-2) i0 = NREF_-2;
        float fr = pos - (float)i0;
        int k = i0 - i0min;
        float vre = sr[c][k]*(1.0f-fr) + sr[c][k+1]*fr;
        float vim = si[c][k]*(1.0f-fr) + si[c][k+1]*fr;
        size_t ob = ((size_t)l*C_ + f)*K2C_;
        split2( vre, g_wr_h, g_wr_l, ob + c);
        split2(-vim, g_wr_h, g_wr_l, ob + C_ + c);
        split2( vim, g_wi_h, g_wi_l, ob + c);
        split2( vre, g_wi_h, g_wi_l, ob + C_ + c);
    }
}
__global__ void p_dft(){
    int i = blockIdx.x*256 + threadIdx.x;
    if (i < L_) g_lsc16[i] = sqrtf(1.0f + (float)i) * (1.0f/(float)C_) * (1.0f/16.0f);
    if (i < 2)  g_cscale[i] = (i==0) ? 0.0625f : (1.0f/4096.0f);
    if (i < (int)DCS_SZ){
        int n = i & 511;
        int m = (i >> 9) % M_;
        int ri = i / (M_*NLON_);
        int a = (m*n) & 511;
        float ang = (float)a * (1.0f/256.0f);
        float v = ri ? -sinpif(ang) : cospif(ang);
        g_dc_h[i] = __float2half_rn(v);
    }
    if (i < (int)D2_SZ){
        int mp = i % MP_;
        int n  = i / MP_;
        float v = 0.f;
        if (mp < M_){
            float wm = (mp==0 || mp==M_-1) ? 1.0f : 2.0f;
            int a = (mp*n) & 511;
            v = wm * cospif((float)a*(1.0f/256.0f)) * 0.5f;    // 256x of /512
        } else if (mp < 2*M_){
            int m2 = mp - M_;
            float wm = (m2==0 || m2==M_-1) ? 1.0f : 2.0f;
            int a = (m2*n) & 511;
            v = -wm * sinpif((float)a*(1.0f/256.0f)) * 0.5f;
        }
        g_d2_h[i] = __float2half_rn(v);
    }
}
__global__ void p_wT(const float* w1, const float* w2, const float* w3, const float* w4){
    int i = blockIdx.x*256 + threadIdx.x;
    if (i >= C_*C_) return;
    int c = i / C_, cp = i % C_;
    const float* ws[4] = {w1, w2, w3, w4};
    #pragma unroll
    for (int k=0;k<4;k++)
        split2(16.0f*ws[k][i], g_wt_h, g_wt_l, (size_t)k*C_*C_ + (size_t)cp*C_ + c);
}
__global__ void p_zeroG2(){
    int i = blockIdx.x*256 + threadIdx.x;
    int nz = MP_ - 514;
    int tot = NLAT_*C_*nz;
    if (i >= tot) return;
    int k  = i % nz;
    int jf = i / nz;
    g_G_h[(size_t)jf*MP_ + 514 + k] = __float2half_rn(0.f);
}

// ---------------- pipelined mma.sync split-fp16 GEMM ----------------
// D = (Ah[+Al])·Bh^T, 128x128 tile, K-chunk 32, 3-stage cp.async.
// zsplit: for bz >= zsplit, switch to alternate A/B/out pointers (batch merge).
#define STGB 24576
#define NSTG 3
#define SMEM_DYN (NSTG*STGB)

template<int ACT, int TWOPASS>
__global__ __launch_bounds__(256) void mmagemm(
    const __half* __restrict__ Ah, const __half* __restrict__ Al,
    const __half* __restrict__ Bh,
    const __half* __restrict__ Ah2, const __half* __restrict__ Al2,
    const __half* __restrict__ Bh2, __half* __restrict__ Oh2,
    int zsplit,
    float* __restrict__ Dout,
    __half* __restrict__ Oh, __half* __restrict__ Ol,
    const float* __restrict__ biasJ, const float* __restrict__ bscale,
    const float* __restrict__ addsrc,
    int Mrows, int Ncols, int K,
    long sAi, long sAb, long sBi, long sBb,
    long sCi, long sCj, long sCb)
{
    extern __shared__ char dsm[];
    const unsigned sb = smem_u32(dsm);

    const int t    = threadIdx.x;
    const int lane = t & 31;
    const int warp = t >> 5;
    const int g    = lane >> 2;
    const int tig  = lane & 3;
    const int mm   = lane >> 3;
    const int rrl  = lane & 7;
    const int wm   = warp >> 2;
    const int wn   = warp & 3;
    int bz = blockIdx.z;
    if (bz >= zsplit){
        bz -= zsplit;
        if (Ah2){ Ah = Ah2; Al = Al2; }
        if (Bh2){ Bh = Bh2; }
        if (Oh2){ Oh = Oh2; }
    }
    const long i0  = (long)blockIdx.y * 128;
    const long j0  = (long)blockIdx.x * 128;

    const __half* Ahb = Ah + (long)bz*sAb;
    const __half* Alb = TWOPASS ? (Al + (long)bz*sAb) : Ah;
    const __half* Bhb = Bh + (long)bz*sBb;

    const int row   = t >> 1;
    const int half  = t & 1;
    const long arow = i0 + row;
    const long brow = j0 + row;
    const bool bok  = brow < (long)Ncols;
    const long aoff = arow * sAi;
    const long boff = brow * sBi;

    float acc[64];
    #pragma unroll
    for (int i=0;i<64;i++) acc[i] = 0.f;

    auto load_stage = [&](int ks, int s){
        unsigned st = sb + s*STGB;
        long kg = (long)ks*32;
        #pragma unroll
        for (int q=0;q<2;q++){
            int c = half*2 + q;
            long ke = kg + c*8;
            unsigned so = (unsigned)(row*64 + ((c ^ ((row>>1)&3)) << 4));
            cpa16(st + so,          Ahb + aoff + ke, true);
            if (TWOPASS) cpa16(st + 8192 + so, Alb + aoff + ke, true);
            cpa16(st + 16384 + so,  Bhb + boff + ke, bok);
        }
    };

    const int nk = K >> 5;
    load_stage(0, 0);
    CP_COMMIT();
    if (nk > 1){ load_stage(1, 1); }
    CP_COMMIT();

    for (int ks = 0; ks < nk; ks++){
        if (ks + 1 < nk) asm volatile("cp.async.wait_group 1;");
        else             asm volatile("cp.async.wait_group 0;");
        __syncthreads();

        const unsigned sA = sb + (ks % NSTG)*STGB;
        const unsigned sB = sA + 16384;
        #pragma unroll
        for (int kk=0; kk<2; kk++){
            unsigned ah[4][4], al[4][4], bh[4][2];
            #pragma unroll
            for (int p=0;p<2;p++){
                int rowB = wn*32 + (p*2 + (mm>>1))*8 + rrl;
                int wB   = kk*8 + (mm&1)*4;
                unsigned ad = sB + (unsigned)swadr(rowB, wB);
                LDMX4(bh[p*2][0], bh[p*2][1], bh[p*2+1][0], bh[p*2+1][1], ad);
            }
            #pragma unroll
            for (int mt=0; mt<4; mt++){
                int rowA = wm*64 + mt*16 + (mm&1)*8 + rrl;
                int wA   = kk*8 + (mm>>1)*4;
                unsigned ad = sA + (unsigned)swadr(rowA, wA);
                LDMX4(ah[mt][0], ah[mt][1], ah[mt][2], ah[mt][3], ad);
                if (TWOPASS) LDMX4(al[mt][0], al[mt][1], al[mt][2], al[mt][3], ad + 8192);
            }
            #pragma unroll
            for (int mt=0; mt<4; mt++)
                #pragma unroll
                for (int nt=0; nt<4; nt++) MMA_OP((&acc[(mt*4+nt)*4]), ah[mt], bh[nt]);
            if (TWOPASS){
                #pragma unroll
                for (int mt=0; mt<4; mt++)
                    #pragma unroll
                    for (int nt=0; nt<4; nt++) MMA_OP((&acc[(mt*4+nt)*4]), al[mt], bh[nt]);
            }
        }
        if (ks + 2 < nk){
            load_stage(ks+2, (ks+2) % NSTG);
        }
        CP_COMMIT();
    }

    // ---------------- epilogue ----------------
    float scl = bscale ? bscale[bz] : 1.0f;
    #pragma unroll
    for (int mt=0; mt<4; mt++){
        long rA = i0 + wm*64 + mt*16 + g;
        #pragma unroll
        for (int nt=0; nt<4; nt++){
            long cB = j0 + wn*32 + nt*8 + 2*tig;
            float* a = &acc[(mt*4+nt)*4];
            #pragma unroll
            for (int h2=0; h2<2; h2++){
                long rowg = rA + h2*8;
                if (rowg >= (long)Mrows) continue;
                long offr = (long)bz*sCb + rowg*sCi;
                if (sCj == 1 && cB + 1 < (long)Ncols){
                    float v0 = a[h2*2+0] * scl;
                    float v1 = a[h2*2+1] * scl;
                    if (biasJ){ v0 += biasJ[cB]; v1 += biasJ[cB+1]; }
                    if (ACT == 1){ v0 = gelu_f(v0); v1 = gelu_f(v1); }
                    long off = offr + cB;
                    if (addsrc){ v0 += addsrc[off]; v1 += addsrc[off+1]; }
                    if (Dout) *(float2*)(Dout + off) = make_float2(v0, v1);
                    if (Oh){
                        __half h0 = __float2half_rn(v0), h1 = __float2half_rn(v1);
                        *(__half2*)(Oh + off) = __halves2half2(h0, h1);
                        if (Ol) *(__half2*)(Ol + off) = __halves2half2(
                            __float2half_rn(v0 - __half2float(h0)),
                            __float2half_rn(v1 - __half2float(h1)));
                    }
                } else {
                    #pragma unroll
                    for (int q=0; q<2; q++){
                        long col = cB + q;
                        if (col >= (long)Ncols) continue;
                        float v = a[h2*2+q] * scl;
                        if (biasJ) v += biasJ[col];
                        if (ACT == 1) v = gelu_f(v);
                        long off = offr + col*sCj;
                        if (addsrc) v += addsrc[off];
                        if (Dout) Dout[off] = v;
                        if (Oh) split2(v, Oh, Ol, (size_t)off);
                    }
                }
            }
        }
    }
}

// ---------------- norm + finalize ----------------
__global__ void norm1_k(){
    int b = blockIdx.x, c = threadIdx.x;
    const float* base = g_grids + (size_t)b*256*C_;
    float s=0.f, q=0.f;
    for (int r=0;r<256;r++){
        float v = base[(size_t)r*C_ + c];
        s += v; q = fmaf(v,v,q);
    }
    g_part[0][b][c] = s;
    g_part[1][b][c] = q;
}
__global__ void norm2_k(){
    int c = threadIdx.x;
    float s=0.f, q=0.f;
    for (int b=0;b<512;b++){ s += g_part[0][b][c]; q += g_part[1][b][c]; }
    float mu = s * (1.0f/(float)S_);
    float var = q * (1.0f/(float)S_) - mu*mu;
    g_mu[c] = mu;
    g_rstd[c] = rsqrtf(var + 1e-3f);
}
__global__ void fin_k(const float* __restrict__ x,
                      const float* __restrict__ gamma,
                      const float* __restrict__ beta,
                      float* __restrict__ out){
    __shared__ float sm[32][33];
    int j  = blockIdx.y;
    int tc = blockIdx.x & 7;
    int tn = blockIdx.x >> 3;
    int tx = threadIdx.x, ty = threadIdx.y;
    #pragma unroll
    for (int k=0;k<4;k++){
        int n = tn*32 + ty + k*8;
        sm[ty+k*8][tx] = g_grids[((size_t)n*NLAT_ + j)*C_ + tc*32 + tx];
    }
    __syncthreads();
    #pragma unroll
    for (int k=0;k<4;k++){
        int c = tc*32 + ty + k*8;
        int n = tn*32 + tx;
        size_t off = (size_t)c*S_ + (size_t)j*NLON_ + n;
        float v = sm[tx][ty+k*8];
        out[off] = (v - g_mu[c])*g_rstd[c]*gamma[c] + beta[c] + x[off];
    }
}

// ---------------- host side ----------------
#define DEVPTR(T, var, sym) T* var; cudaGetSymbolAddress((void**)&var, sym)

static void launch_gemm(int act, int twopass, dim3 grid,
    const __half* Ah, const __half* Al, const __half* Bh,
    const __half* Ah2, const __half* Al2, const __half* Bh2, __half* Oh2, int zsplit,
    float* Dout, __half* Oh, __half* Ol,
    const float* biasJ, const float* bscale, const float* addsrc,
    int M, int N, int K,
    long sAi, long sAb, long sBi, long sBb, long sCi, long sCj, long sCb)
{
    if (twopass){
        if (act)
            mmagemm<1,1><<<grid,256,SMEM_DYN>>>(Ah,Al,Bh,Ah2,Al2,Bh2,Oh2,zsplit,
                Dout,Oh,Ol,biasJ,bscale,addsrc,M,N,K,sAi,sAb,sBi,sBb,sCi,sCj,sCb);
        else
            mmagemm<0,1><<<grid,256,SMEM_DYN>>>(Ah,Al,Bh,Ah2,Al2,Bh2,Oh2,zsplit,
                Dout,Oh,Ol,biasJ,bscale,addsrc,M,N,K,sAi,sAb,sBi,sBb,sCi,sCj,sCb);
    } else {
        mmagemm<1,0><<<grid,256,SMEM_DYN>>>(Ah,Al,Bh,Ah2,Al2,Bh2,Oh2,zsplit,
            Dout,Oh,Ol,biasJ,bscale,addsrc,M,N,K,sAi,sAb,sBi,sBb,sCi,sCj,sCb);
    }
}

extern "C" void kernel_launch(void* const* d_in, const int* in_sizes, int n_in,
                              void* d_out, int out_size){
    const float* x      = (const float*)d_in[0];
    const float* leg    = (const float*)d_in[1];
    const float* wquad  = (const float*)d_in[2];
    const float* w_real = (const float*)d_in[3];
    const float* w_imag = (const float*)d_in[4];
    const float* m1w1   = (const float*)d_in[5];
    const float* m1b1   = (const float*)d_in[6];
    const float* m1w2   = (const float*)d_in[7];
    const float* m1b2   = (const float*)d_in[8];
    const float* m2w1   = (const float*)d_in[9];
    const float* m2b1   = (const float*)d_in[10];
    const float* m2w2   = (const float*)d_in[11];
    const float* m2b2   = (const float*)d_in[12];
    const float* gamma  = (const float*)d_in[13];
    const float* beta   = (const float*)d_in[14];
    float* out = (float*)d_out;

    cudaFuncSetAttribute(mmagemm<0,1>, cudaFuncAttributeMaxDynamicSharedMemorySize, SMEM_DYN);
    cudaFuncSetAttribute(mmagemm<1,1>, cudaFuncAttributeMaxDynamicSharedMemorySize, SMEM_DYN);
    cudaFuncSetAttribute(mmagemm<1,0>, cudaFuncAttributeMaxDynamicSharedMemorySize, SMEM_DYN);

    DEVPTR(__half, xh, g_x_h);  DEVPTR(__half, xl, g_x_l);
    DEVPTR(__half, xth,g_xt_h); DEVPTR(__half, xtl,g_xt_l);
    DEVPTR(__half, lwh,g_lw_h); DEVPTR(__half, lwl,g_lw_l);
    DEVPTR(__half, lgh,g_lg_h); DEVPTR(__half, lgl,g_lg_l);
    DEVPTR(__half, wrh,g_wr_h); DEVPTR(__half, wrl,g_wr_l);
    DEVPTR(__half, wih,g_wi_h); DEVPTR(__half, wil,g_wi_l);
    DEVPTR(__half, Fh, g_F_h);
    DEVPTR(__half, Hh, g_H_h);
    DEVPTR(__half, xrh,g_xr_h);
    DEVPTR(__half, xih,g_xi_h);
    DEVPTR(__half, Gh, g_G_h);
    DEVPTR(__half, mAh,g_mA_h); DEVPTR(__half, mAl,g_mA_l);
    DEVPTR(__half, mBh,g_mB_h); DEVPTR(__half, mBl,g_mB_l);
    DEVPTR(__half, dch,g_dc_h);
    DEVPTR(__half, d2h,g_d2_h);
    DEVPTR(__half, wth,g_wt_h);
    DEVPTR(float, grids, g_grids);
    DEVPTR(float, lsc16, g_lsc16);
    DEVPTR(float, cscale, g_cscale);

    const int BIGZ = 1 << 30;

    // ---- prep (launch #3 = the big S1 GEMM for ncu) ----
    p_dft <<<(unsigned)((D2_SZ+255)/256), 256>>>();
    p_xT2 <<<dim3(128, NLAT_), dim3(32,8)>>>(x);

    // ---- S1: rfft DFT-GEMM (2-pass) -> F (ri,m,c,j) hi ----
    launch_gemm(0, 1, dim3(3, 512, 2),
        xh, xl, dch, nullptr, nullptr, nullptr, nullptr, BIGZ,
        nullptr, Fh, nullptr, nullptr, nullptr, nullptr,
        C_*NLAT_, M_, NLON_,
        NLON_, 0, NLON_, (long)M_*NLON_,
        1, (long)C_*NLAT_, (long)M_*C_*NLAT_);

    p_lw     <<<(unsigned)((LW_SZ+255)/256), 256>>>(leg, wquad);
    p_legT   <<<dim3(64, M_), dim3(32,8)>>>(leg);
    p_W2     <<<dim3(16, 256), 256>>>(w_real, w_imag);
    p_wT     <<<(C_*C_+255)/256, 256>>>(m1w1, m1w2, m2w1, m2w2);
    p_zeroG2 <<<(unsigned)((NLAT_*C_*(MP_-514)+255)/256), 256>>>();

    // ---- S2 merged (batch 2M): A=16*lw shared; B/out switch at zsplit=M ----
    launch_gemm(0, 1, dim3(2, 2, 2*M_),
        lwh, lwl, Fh,
        nullptr, nullptr, Fh + M_*(size_t)C_*NLAT_, Hh + C_, M_,
        nullptr, Hh, nullptr, nullptr, nullptr, nullptr,
        L_, C_, NLAT_,
        (long)M_*NLAT_, NLAT_, NLAT_, (long)C_*NLAT_,
        (long)M_*K2C_, 1, K2C_);

    // ---- S3 merged (batch 2L): B=Hh shared; A/out switch at zsplit=L ----
    launch_gemm(0, 1, dim3(3, 2, 2*L_),
        wrh, wrl, Hh,
        wih, wil, nullptr, xih, L_,
        nullptr, xrh, nullptr, nullptr, lsc16, nullptr,
        C_, M_, K2C_,
        K2C_, (long)C_*K2C_, K2C_, (long)M_*K2C_,
        L_, (long)C_*L_, 1);

    // ---- S4 merged (batch 2M): A=16*lgT shared; B/out switch at zsplit=M ----
    launch_gemm(0, 1, dim3(2, 2, 2*M_),
        lgh, lgl, xrh,
        nullptr, nullptr, xih, Gh + M_, M_,
        nullptr, Gh, nullptr, nullptr, nullptr, nullptr,
        NLAT_, C_, L_,
        L_, (long)NLAT_*L_, L_, (long)C_*L_,
        (long)C_*MP_, MP_, 1);

    // ---- S5: irfft + GELU (SINGLE-pass A) -> fp32 grids (n,j,f) ----
    launch_gemm(1, 0, dim3(512, 4, 1),
        d2h, nullptr, Gh, nullptr, nullptr, nullptr, nullptr, BIGZ,
        grids, nullptr, nullptr, nullptr, cscale+1, nullptr,
        NLON_, NLAT_*C_, MP_,
        MP_, 0, MP_, 0,
        (long)NLAT_*C_, 1, 0);

    // ---- MLPs (2-pass): B = 16*wT, bscale = 1/16 ----
    launch_gemm(1, 1, dim3(2, 1024, 1),
        xth, xtl, wth + 0, nullptr, nullptr, nullptr, nullptr, BIGZ,
        nullptr, mAh, mAl, m1b1, cscale, nullptr,
        S_, C_, C_, C_, 0, C_, 0, C_, 1, 0);
    launch_gemm(1, 1, dim3(2, 1024, 1),
        mAh, mAl, wth + C_*C_, nullptr, nullptr, nullptr, nullptr, BIGZ,
        nullptr, mBh, mBl, m1b2, cscale, grids,
        S_, C_, C_, C_, 0, C_, 0, C_, 1, 0);
    launch_gemm(1, 1, dim3(2, 1024, 1),
        mBh, mBl, wth + 2*C_*C_, nullptr, nullptr, nullptr, nullptr, BIGZ,
        nullptr, mAh, mAl, m2b1, cscale, nullptr,
        S_, C_, C_, C_, 0, C_, 0, C_, 1, 0);
    launch_gemm(1, 1, dim3(2, 1024, 1),
        mAh, mAl, wth + 3*C_*C_, nullptr, nullptr, nullptr, nullptr, BIGZ,
        grids, nullptr, nullptr, m2b2, cscale, nullptr,
        S_, C_, C_, C_, 0, C_, 0, C_, 1, 0);

    // ---- instance norm + residual + transpose out ----
    norm1_k<<<512, 256>>>();
    norm2_k<<<1, 256>>>();
    fin_k<<<dim3(128, NLAT_), dim3(32,8)>>>(x, gamma, beta, out);
}

// round 11
// speedup vs baseline: 1.9434x; 1.1010x over previous
#include <cuda_runtime.h>
#include <cuda_fp16.h>
#include <math.h>

#define C_    256
#define NLAT_ 256
#define NLON_ 512
#define L_    256
#define M_    257
#define NREF_ 64
#define S_    (NLAT_*NLON_)
#define K2C_  512
#define MP_   544               // 2*M=514 padded to mult of 32

#define XS_SZ   ((size_t)C_*S_)
#define LW_SZ   ((size_t)L_*M_*NLAT_)
#define LGT_SZ  ((size_t)M_*NLAT_*L_)
#define WC_SZ   ((size_t)L_*C_*K2C_)
#define F_SZ    ((size_t)2*M_*C_*NLAT_)
#define H_SZ    ((size_t)L_*M_*K2C_)
#define XSP_SZ  ((size_t)M_*C_*L_)
#define G2_SZ   ((size_t)NLAT_*C_*MP_)
#define DCS_SZ  ((size_t)2*M_*NLON_)
#define D2_SZ   ((size_t)NLON_*MP_)

__device__ __align__(128) __half g_x_h[XS_SZ];
__device__ __align__(128) __half g_xt_h[XS_SZ], g_xt_l[XS_SZ];
__device__ __align__(128) __half g_lw_h[LW_SZ];
__device__ __align__(128) __half g_lg_h[LGT_SZ];
__device__ __align__(128) __half g_wr_h[WC_SZ];
__device__ __align__(128) __half g_wi_h[WC_SZ];
__device__ __align__(128) __half g_F_h[F_SZ];
__device__ __align__(128) __half g_H_h[H_SZ];
__device__ __align__(128) __half g_xr_h[XSP_SZ];
__device__ __align__(128) __half g_xi_h[XSP_SZ];
__device__ __align__(128) __half g_G_h[G2_SZ];
__device__ __align__(128) __half g_mA_h[XS_SZ], g_mA_l[XS_SZ];
__device__ __align__(128) __half g_mB_h[XS_SZ], g_mB_l[XS_SZ];
__device__ __align__(128) __half g_dc_h[DCS_SZ];
__device__ __align__(128) __half g_d2_h[D2_SZ];
__device__ __align__(128) __half g_wt_h[4*C_*C_], g_wt_l[4*C_*C_];
__device__ __align__(128) float g_grids[XS_SZ];
__device__ float g_lsc16[L_];
__device__ float g_cscale[2];        // {1/16, 1/4096}
__device__ float g_part[2][512][C_];
__device__ float g_mu[C_], g_rstd[C_];

__device__ __forceinline__ float gelu_f(float v){
    return 0.5f*v*(1.0f + erff(v*0.7071067811865476f));
}
__device__ __forceinline__ void split2(float v, __half* H, __half* Lo, size_t off){
    __half h = __float2half_rn(v);
    H[off]  = h;
    if (Lo) Lo[off] = __float2half_rn(v - __half2float(h));
}
__device__ __forceinline__ unsigned smem_u32(const void* p){
    unsigned a;
    asm("{ .reg .u64 t; cvta.to.shared.u64 t, %1; cvt.u32.u64 %0, t; }" : "=r"(a) : "l"(p));
    return a;
}
__device__ __forceinline__ int swadr(int r, int w){
    return r*64 + ((((w>>2) ^ ((r>>1)&3))) << 4) + ((w & 3) << 2);
}
__device__ __forceinline__ void cpa16(unsigned saddr, const void* g, bool v){
    asm volatile("cp.async.cg.shared.global [%0], [%1], 16, %2;"
                 :: "r"(saddr), "l"(g), "r"(v ? 16 : 0));
}
#define CP_COMMIT() asm volatile("cp.async.commit_group;")
#define LDMX4(r0,r1,r2,r3,addr) \
    asm volatile("ldmatrix.sync.aligned.m8n8.x4.shared.b16 {%0,%1,%2,%3}, [%4];" \
        : "=r"(r0),"=r"(r1),"=r"(r2),"=r"(r3) : "r"(addr))
#define MMA_OP(cc, aa, bb) asm volatile( \
    "mma.sync.aligned.m16n8k16.row.col.f32.f16.f16.f32 " \
    "{%0,%1,%2,%3},{%4,%5,%6,%7},{%8,%9},{%0,%1,%2,%3};" \
    : "+f"(cc[0]),"+f"(cc[1]),"+f"(cc[2]),"+f"(cc[3]) \
    : "r"(aa[0]),"r"(aa[1]),"r"(aa[2]),"r"(aa[3]),"r"(bb[0]),"r"(bb[1]))

// ---------------- prep kernels ----------------
// fused: x -> x_h (c,j,n) AND xT_h/xT_l (s=n*256+j, c)
__global__ void p_xT2(const float* __restrict__ x){
    __shared__ float sm[32][33];
    int j  = blockIdx.y;
    int tc = blockIdx.x & 7;
    int tn = blockIdx.x >> 3;
    int tx = threadIdx.x, ty = threadIdx.y;
    #pragma unroll
    for (int k=0;k<4;k++){
        int c = tc*32 + ty + k*8;
        size_t offx = (size_t)c*S_ + (size_t)j*NLON_ + tn*32 + tx;
        float v = x[offx];
        sm[ty+k*8][tx] = v;
        g_x_h[offx] = __float2half_rn(v);
    }
    __syncthreads();
    #pragma unroll
    for (int k=0;k<4;k++){
        int n = tn*32 + ty + k*8;
        int c = tc*32 + tx;
        size_t off = ((size_t)n*NLAT_ + j)*C_ + c;
        split2(sm[tx][ty+k*8], g_xt_h, g_xt_l, off);
    }
}
__global__ void p_lw(const float* __restrict__ leg, const float* __restrict__ wq){
    size_t i4 = ((size_t)blockIdx.x*256 + threadIdx.x)*4;
    if (i4 >= LW_SZ) return;
    float4 v = *(const float4*)(leg + i4);
    int w0 = (int)(i4 & (NLAT_-1));
    float a = 16.f*v.x*wq[w0],   b = 16.f*v.y*wq[w0+1];
    float c = 16.f*v.z*wq[w0+2], d = 16.f*v.w*wq[w0+3];
    __half2* o = (__half2*)(g_lw_h + i4);
    o[0] = __floats2half2_rn(a, b);
    o[1] = __floats2half2_rn(c, d);
}
__global__ void p_legT(const float* __restrict__ leg){
    __shared__ float sm[32][33];
    int m  = blockIdx.y;
    int tl = blockIdx.x & 7;
    int tj = blockIdx.x >> 3;
    int tx = threadIdx.x, ty = threadIdx.y;
    #pragma unroll
    for (int k=0;k<4;k++){
        int l = tl*32 + ty + k*8;
        sm[ty+k*8][tx] = leg[(size_t)l*M_*NLAT_ + (size_t)m*NLAT_ + tj*32 + tx];
    }
    __syncthreads();
    #pragma unroll
    for (int k=0;k<4;k++){
        int j = tj*32 + ty + k*8;
        int l = tl*32 + tx;
        size_t off = ((size_t)m*NLAT_ + j)*L_ + l;
        g_lg_h[off] = __float2half_rn(16.0f*sm[tx][ty+k*8]);
    }
}
__global__ void p_W2(const float* __restrict__ wr, const float* __restrict__ wi){
    __shared__ float sr[256][8], si[256][8];
    int f  = blockIdx.y;
    int l0 = blockIdx.x * 16;
    int c  = threadIdx.x;
    int i0min = (l0*(NREF_-1)) / (L_-1);
    if (i0min > NREF_-8) i0min = NREF_-8;
    size_t rb = ((size_t)f*C_ + c)*NREF_ + i0min;
    #pragma unroll
    for (int k=0;k<8;k++){ sr[c][k] = wr[rb+k]; si[c][k] = wi[rb+k]; }
    __syncthreads();
    #pragma unroll 4
    for (int li=0; li<16; li++){
        int l = l0 + li;
        float pos = (float)(l*(NREF_-1)) / (float)(L_-1);
        int i0 = (int)floorf(pos);
        if (i0 > NREF_-2) i0 = NREF_-2;
        float fr = pos - (float)i0;
        int k = i0 - i0min;
        float vre = sr[c][k]*(1.0f-fr) + sr[c][k+1]*fr;
        float vim = si[c][k]*(1.0f-fr) + si[c][k+1]*fr;
        size_t ob = ((size_t)l*C_ + f)*K2C_;
        g_wr_h[ob + c]      = __float2half_rn( vre);
        g_wr_h[ob + C_ + c] = __float2half_rn(-vim);
        g_wi_h[ob + c]      = __float2half_rn( vim);
        g_wi_h[ob + C_ + c] = __float2half_rn( vre);
    }
}
__global__ void p_dft(){
    int i = blockIdx.x*256 + threadIdx.x;
    if (i < L_) g_lsc16[i] = sqrtf(1.0f + (float)i) * (1.0f/(float)C_) * (1.0f/16.0f);
    if (i < 2)  g_cscale[i] = (i==0) ? 0.0625f : (1.0f/4096.0f);
    if (i < (int)DCS_SZ){
        int n = i & 511;
        int m = (i >> 9) % M_;
        int ri = i / (M_*NLON_);
        int a = (m*n) & 511;
        float ang = (float)a * (1.0f/256.0f);
        float v = ri ? -sinpif(ang) : cospif(ang);
        g_dc_h[i] = __float2half_rn(v);
    }
    if (i < (int)D2_SZ){
        int mp = i % MP_;
        int n  = i / MP_;
        float v = 0.f;
        if (mp < M_){
            float wm = (mp==0 || mp==M_-1) ? 1.0f : 2.0f;
            int a = (mp*n) & 511;
            v = wm * cospif((float)a*(1.0f/256.0f)) * 0.5f;    // 256x of /512
        } else if (mp < 2*M_){
            int m2 = mp - M_;
            float wm = (m2==0 || m2==M_-1) ? 1.0f : 2.0f;
            int a = (m2*n) & 511;
            v = -wm * sinpif((float)a*(1.0f/256.0f)) * 0.5f;
        }
        g_d2_h[i] = __float2half_rn(v);
    }
}
__global__ void p_wT(const float* w1, const float* w2, const float* w3, const float* w4){
    int i = blockIdx.x*256 + threadIdx.x;
    if (i >= C_*C_) return;
    int c = i / C_, cp = i % C_;
    const float* ws[4] = {w1, w2, w3, w4};
    #pragma unroll
    for (int k=0;k<4;k++)
        split2(16.0f*ws[k][i], g_wt_h, g_wt_l, (size_t)k*C_*C_ + (size_t)cp*C_ + c);
}
__global__ void p_zeroG2(){
    int i = blockIdx.x*256 + threadIdx.x;
    int nz = MP_ - 514;
    int tot = NLAT_*C_*nz;
    if (i >= tot) return;
    int k  = i % nz;
    int jf = i / nz;
    g_G_h[(size_t)jf*MP_ + 514 + k] = __float2half_rn(0.f);
}

// ---------------- pipelined mma.sync split-fp16 GEMM ----------------
// D = (Ah[+Al])·Bh^T, 128x128 tile, K-chunk 32, 3-stage cp.async.
// zsplit: for bz >= zsplit, switch to alternate A/B/out pointers (batch merge).
#define STGB 24576
#define NSTG 3
#define SMEM_DYN (NSTG*STGB)

template<int ACT, int TWOPASS>
__global__ __launch_bounds__(256) void mmagemm(
    const __half* __restrict__ Ah, const __half* __restrict__ Al,
    const __half* __restrict__ Bh,
    const __half* __restrict__ Ah2, const __half* __restrict__ Al2,
    const __half* __restrict__ Bh2, __half* __restrict__ Oh2,
    int zsplit,
    float* __restrict__ Dout,
    __half* __restrict__ Oh, __half* __restrict__ Ol,
    const float* __restrict__ biasJ, const float* __restrict__ bscale,
    const float* __restrict__ addsrc,
    int Mrows, int Ncols, int K,
    long sAi, long sAb, long sBi, long sBb,
    long sCi, long sCj, long sCb)
{
    extern __shared__ char dsm[];
    const unsigned sb = smem_u32(dsm);

    const int t    = threadIdx.x;
    const int lane = t & 31;
    const int warp = t >> 5;
    const int g    = lane >> 2;
    const int tig  = lane & 3;
    const int mm   = lane >> 3;
    const int rrl  = lane & 7;
    const int wm   = warp >> 2;
    const int wn   = warp & 3;
    int bz = blockIdx.z;
    if (bz >= zsplit){
        bz -= zsplit;
        if (Ah2){ Ah = Ah2; Al = Al2; }
        if (Bh2){ Bh = Bh2; }
        if (Oh2){ Oh = Oh2; }
    }
    const long i0  = (long)blockIdx.y * 128;
    const long j0  = (long)blockIdx.x * 128;

    const __half* Ahb = Ah + (long)bz*sAb;
    const __half* Alb = TWOPASS ? (Al + (long)bz*sAb) : Ah;
    const __half* Bhb = Bh + (long)bz*sBb;

    const int row   = t >> 1;
    const int half  = t & 1;
    const long arow = i0 + row;
    const long brow = j0 + row;
    const bool bok  = brow < (long)Ncols;
    const long aoff = arow * sAi;
    const long boff = brow * sBi;

    float acc[64];
    #pragma unroll
    for (int i=0;i<64;i++) acc[i] = 0.f;

    auto load_stage = [&](int ks, int s){
        unsigned st = sb + s*STGB;
        long kg = (long)ks*32;
        #pragma unroll
        for (int q=0;q<2;q++){
            int c = half*2 + q;
            long ke = kg + c*8;
            unsigned so = (unsigned)(row*64 + ((c ^ ((row>>1)&3)) << 4));
            cpa16(st + so,          Ahb + aoff + ke, true);
            if (TWOPASS) cpa16(st + 8192 + so, Alb + aoff + ke, true);
            cpa16(st + 16384 + so,  Bhb + boff + ke, bok);
        }
    };

    const int nk = K >> 5;
    load_stage(0, 0);
    CP_COMMIT();
    if (nk > 1){ load_stage(1, 1); }
    CP_COMMIT();

    for (int ks = 0; ks < nk; ks++){
        if (ks + 1 < nk) asm volatile("cp.async.wait_group 1;");
        else             asm volatile("cp.async.wait_group 0;");
        __syncthreads();

        const unsigned sA = sb + (ks % NSTG)*STGB;
        const unsigned sB = sA + 16384;
        #pragma unroll
        for (int kk=0; kk<2; kk++){
            unsigned ah[4][4], al[4][4], bh[4][2];
            #pragma unroll
            for (int p=0;p<2;p++){
                int rowB = wn*32 + (p*2 + (mm>>1))*8 + rrl;
                int wB   = kk*8 + (mm&1)*4;
                unsigned ad = sB + (unsigned)swadr(rowB, wB);
                LDMX4(bh[p*2][0], bh[p*2][1], bh[p*2+1][0], bh[p*2+1][1], ad);
            }
            #pragma unroll
            for (int mt=0; mt<4; mt++){
                int rowA = wm*64 + mt*16 + (mm&1)*8 + rrl;
                int wA   = kk*8 + (mm>>1)*4;
                unsigned ad = sA + (unsigned)swadr(rowA, wA);
                LDMX4(ah[mt][0], ah[mt][1], ah[mt][2], ah[mt][3], ad);
                if (TWOPASS) LDMX4(al[mt][0], al[mt][1], al[mt][2], al[mt][3], ad + 8192);
            }
            #pragma unroll
            for (int mt=0; mt<4; mt++)
                #pragma unroll
                for (int nt=0; nt<4; nt++) MMA_OP((&acc[(mt*4+nt)*4]), ah[mt], bh[nt]);
            if (TWOPASS){
                #pragma unroll
                for (int mt=0; mt<4; mt++)
                    #pragma unroll
                    for (int nt=0; nt<4; nt++) MMA_OP((&acc[(mt*4+nt)*4]), al[mt], bh[nt]);
            }
        }
        if (ks + 2 < nk){
            load_stage(ks+2, (ks+2) % NSTG);
        }
        CP_COMMIT();
    }

    // ---------------- epilogue ----------------
    float scl = bscale ? bscale[bz] : 1.0f;
    #pragma unroll
    for (int mt=0; mt<4; mt++){
        long rA = i0 + wm*64 + mt*16 + g;
        #pragma unroll
        for (int nt=0; nt<4; nt++){
            long cB = j0 + wn*32 + nt*8 + 2*tig;
            float* a = &acc[(mt*4+nt)*4];
            #pragma unroll
            for (int h2=0; h2<2; h2++){
                long rowg = rA + h2*8;
                if (rowg >= (long)Mrows) continue;
                long offr = (long)bz*sCb + rowg*sCi;
                if (sCj == 1 && cB + 1 < (long)Ncols){
                    float v0 = a[h2*2+0] * scl;
                    float v1 = a[h2*2+1] * scl;
                    if (biasJ){ v0 += biasJ[cB]; v1 += biasJ[cB+1]; }
                    if (ACT == 1){ v0 = gelu_f(v0); v1 = gelu_f(v1); }
                    long off = offr + cB;
                    if (addsrc){ v0 += addsrc[off]; v1 += addsrc[off+1]; }
                    if (Dout) *(float2*)(Dout + off) = make_float2(v0, v1);
                    if (Oh){
                        __half h0 = __float2half_rn(v0), h1 = __float2half_rn(v1);
                        *(__half2*)(Oh + off) = __halves2half2(h0, h1);
                        if (Ol) *(__half2*)(Ol + off) = __halves2half2(
                            __float2half_rn(v0 - __half2float(h0)),
                            __float2half_rn(v1 - __half2float(h1)));
                    }
                } else {
                    #pragma unroll
                    for (int q=0; q<2; q++){
                        long col = cB + q;
                        if (col >= (long)Ncols) continue;
                        float v = a[h2*2+q] * scl;
                        if (biasJ) v += biasJ[col];
                        if (ACT == 1) v = gelu_f(v);
                        long off = offr + col*sCj;
                        if (addsrc) v += addsrc[off];
                        if (Dout) Dout[off] = v;
                        if (Oh) split2(v, Oh, Ol, (size_t)off);
                    }
                }
            }
        }
    }
}

// ---------------- norm + finalize ----------------
__global__ void norm1_k(){
    int b = blockIdx.x, c = threadIdx.x;
    const float* base = g_grids + (size_t)b*256*C_;
    float s=0.f, q=0.f;
    for (int r=0;r<256;r++){
        float v = base[(size_t)r*C_ + c];
        s += v; q = fmaf(v,v,q);
    }
    g_part[0][b][c] = s;
    g_part[1][b][c] = q;
}
__global__ void norm2_k(){
    int c = threadIdx.x;
    float s=0.f, q=0.f;
    for (int b=0;b<512;b++){ s += g_part[0][b][c]; q += g_part[1][b][c]; }
    float mu = s * (1.0f/(float)S_);
    float var = q * (1.0f/(float)S_) - mu*mu;
    g_mu[c] = mu;
    g_rstd[c] = rsqrtf(var + 1e-3f);
}
__global__ void fin_k(const float* __restrict__ x,
                      const float* __restrict__ gamma,
                      const float* __restrict__ beta,
                      float* __restrict__ out){
    __shared__ float sm[32][33];
    int j  = blockIdx.y;
    int tc = blockIdx.x & 7;
    int tn = blockIdx.x >> 3;
    int tx = threadIdx.x, ty = threadIdx.y;
    #pragma unroll
    for (int k=0;k<4;k++){
        int n = tn*32 + ty + k*8;
        sm[ty+k*8][tx] = g_grids[((size_t)n*NLAT_ + j)*C_ + tc*32 + tx];
    }
    __syncthreads();
    #pragma unroll
    for (int k=0;k<4;k++){
        int c = tc*32 + ty + k*8;
        int n = tn*32 + tx;
        size_t off = (size_t)c*S_ + (size_t)j*NLON_ + n;
        float v = sm[tx][ty+k*8];
        out[off] = (v - g_mu[c])*g_rstd[c]*gamma[c] + beta[c] + x[off];
    }
}

// ---------------- host side ----------------
#define DEVPTR(T, var, sym) T* var; cudaGetSymbolAddress((void**)&var, sym)

static void launch_gemm(int act, int twopass, dim3 grid,
    const __half* Ah, const __half* Al, const __half* Bh,
    const __half* Ah2, const __half* Al2, const __half* Bh2, __half* Oh2, int zsplit,
    float* Dout, __half* Oh, __half* Ol,
    const float* biasJ, const float* bscale, const float* addsrc,
    int M, int N, int K,
    long sAi, long sAb, long sBi, long sBb, long sCi, long sCj, long sCb)
{
    if (act){
        if (twopass)
            mmagemm<1,1><<<grid,256,SMEM_DYN>>>(Ah,Al,Bh,Ah2,Al2,Bh2,Oh2,zsplit,
                Dout,Oh,Ol,biasJ,bscale,addsrc,M,N,K,sAi,sAb,sBi,sBb,sCi,sCj,sCb);
        else
            mmagemm<1,0><<<grid,256,SMEM_DYN>>>(Ah,Al,Bh,Ah2,Al2,Bh2,Oh2,zsplit,
                Dout,Oh,Ol,biasJ,bscale,addsrc,M,N,K,sAi,sAb,sBi,sBb,sCi,sCj,sCb);
    } else {
        if (twopass)
            mmagemm<0,1><<<grid,256,SMEM_DYN>>>(Ah,Al,Bh,Ah2,Al2,Bh2,Oh2,zsplit,
                Dout,Oh,Ol,biasJ,bscale,addsrc,M,N,K,sAi,sAb,sBi,sBb,sCi,sCj,sCb);
        else
            mmagemm<0,0><<<grid,256,SMEM_DYN>>>(Ah,Al,Bh,Ah2,Al2,Bh2,Oh2,zsplit,
                Dout,Oh,Ol,biasJ,bscale,addsrc,M,N,K,sAi,sAb,sBi,sBb,sCi,sCj,sCb);
    }
}

extern "C" void kernel_launch(void* const* d_in, const int* in_sizes, int n_in,
                              void* d_out, int out_size){
    const float* x      = (const float*)d_in[0];
    const float* leg    = (const float*)d_in[1];
    const float* wquad  = (const float*)d_in[2];
    const float* w_real = (const float*)d_in[3];
    const float* w_imag = (const float*)d_in[4];
    const float* m1w1   = (const float*)d_in[5];
    const float* m1b1   = (const float*)d_in[6];
    const float* m1w2   = (const float*)d_in[7];
    const float* m1b2   = (const float*)d_in[8];
    const float* m2w1   = (const float*)d_in[9];
    const float* m2b1   = (const float*)d_in[10];
    const float* m2w2   = (const float*)d_in[11];
    const float* m2b2   = (const float*)d_in[12];
    const float* gamma  = (const float*)d_in[13];
    const float* beta   = (const float*)d_in[14];
    float* out = (float*)d_out;

    cudaFuncSetAttribute(mmagemm<0,0>, cudaFuncAttributeMaxDynamicSharedMemorySize, SMEM_DYN);
    cudaFuncSetAttribute(mmagemm<0,1>, cudaFuncAttributeMaxDynamicSharedMemorySize, SMEM_DYN);
    cudaFuncSetAttribute(mmagemm<1,0>, cudaFuncAttributeMaxDynamicSharedMemorySize, SMEM_DYN);
    cudaFuncSetAttribute(mmagemm<1,1>, cudaFuncAttributeMaxDynamicSharedMemorySize, SMEM_DYN);

    DEVPTR(__half, xh, g_x_h);
    DEVPTR(__half, xth,g_xt_h); DEVPTR(__half, xtl,g_xt_l);
    DEVPTR(__half, lwh,g_lw_h);
    DEVPTR(__half, lgh,g_lg_h);
    DEVPTR(__half, wrh,g_wr_h);
    DEVPTR(__half, wih,g_wi_h);
    DEVPTR(__half, Fh, g_F_h);
    DEVPTR(__half, Hh, g_H_h);
    DEVPTR(__half, xrh,g_xr_h);
    DEVPTR(__half, xih,g_xi_h);
    DEVPTR(__half, Gh, g_G_h);
    DEVPTR(__half, mAh,g_mA_h); DEVPTR(__half, mAl,g_mA_l);
    DEVPTR(__half, mBh,g_mB_h); DEVPTR(__half, mBl,g_mB_l);
    DEVPTR(__half, dch,g_dc_h);
    DEVPTR(__half, d2h,g_d2_h);
    DEVPTR(__half, wth,g_wt_h);
    DEVPTR(float, grids, g_grids);
    DEVPTR(float, lsc16, g_lsc16);
    DEVPTR(float, cscale, g_cscale);

    const int BIGZ = 1 << 30;

    // ---- prep (launch #3 = the big S1 GEMM for ncu) ----
    p_dft <<<(unsigned)((D2_SZ+255)/256), 256>>>();
    p_xT2 <<<dim3(128, NLAT_), dim3(32,8)>>>(x);

    // ---- S1: rfft DFT-GEMM (1-pass) -> F (ri,m,c,j) hi ----
    launch_gemm(0, 0, dim3(3, 512, 2),
        xh, nullptr, dch, nullptr, nullptr, nullptr, nullptr, BIGZ,
        nullptr, Fh, nullptr, nullptr, nullptr, nullptr,
        C_*NLAT_, M_, NLON_,
        NLON_, 0, NLON_, (long)M_*NLON_,
        1, (long)C_*NLAT_, (long)M_*C_*NLAT_);

    p_lw     <<<(unsigned)((LW_SZ/4+255)/256), 256>>>(leg, wquad);
    p_legT   <<<dim3(64, M_), dim3(32,8)>>>(leg);
    p_W2     <<<dim3(16, 256), 256>>>(w_real, w_imag);
    p_wT     <<<(C_*C_+255)/256, 256>>>(m1w1, m1w2, m2w1, m2w2);
    p_zeroG2 <<<(unsigned)((NLAT_*C_*(MP_-514)+255)/256), 256>>>();

    // ---- S2 merged (batch 2M, 1-pass): A=16*lw; B/out switch at zsplit=M ----
    launch_gemm(0, 0, dim3(2, 2, 2*M_),
        lwh, nullptr, Fh,
        nullptr, nullptr, Fh + M_*(size_t)C_*NLAT_, Hh + C_, M_,
        nullptr, Hh, nullptr, nullptr, nullptr, nullptr,
        L_, C_, NLAT_,
        (long)M_*NLAT_, NLAT_, NLAT_, (long)C_*NLAT_,
        (long)M_*K2C_, 1, K2C_);

    // ---- S3 merged (batch 2L, 1-pass): B=Hh shared; A/out switch at zsplit=L ----
    launch_gemm(0, 0, dim3(3, 2, 2*L_),
        wrh, nullptr, Hh,
        wih, nullptr, nullptr, xih, L_,
        nullptr, xrh, nullptr, nullptr, lsc16, nullptr,
        C_, M_, K2C_,
        K2C_, (long)C_*K2C_, K2C_, (long)M_*K2C_,
        L_, (long)C_*L_, 1);

    // ---- S4 merged (batch 2M, 1-pass): A=16*lgT; B/out switch at zsplit=M ----
    launch_gemm(0, 0, dim3(2, 2, 2*M_),
        lgh, nullptr, xrh,
        nullptr, nullptr, xih, Gh + M_, M_,
        nullptr, Gh, nullptr, nullptr, nullptr, nullptr,
        NLAT_, C_, L_,
        L_, (long)NLAT_*L_, L_, (long)C_*L_,
        (long)C_*MP_, MP_, 1);

    // ---- S5: irfft + GELU (1-pass) -> fp32 grids (n,j,f) ----
    launch_gemm(1, 0, dim3(512, 4, 1),
        d2h, nullptr, Gh, nullptr, nullptr, nullptr, nullptr, BIGZ,
        grids, nullptr, nullptr, nullptr, cscale+1, nullptr,
        NLON_, NLAT_*C_, MP_,
        MP_, 0, MP_, 0,
        (long)NLAT_*C_, 1, 0);

    // ---- MLPs (2-pass): B = 16*wT, bscale = 1/16 ----
    launch_gemm(1, 1, dim3(2, 1024, 1),
        xth, xtl, wth + 0, nullptr, nullptr, nullptr, nullptr, BIGZ,
        nullptr, mAh, mAl, m1b1, cscale, nullptr,
        S_, C_, C_, C_, 0, C_, 0, C_, 1, 0);
    launch_gemm(1, 1, dim3(2, 1024, 1),
        mAh, mAl, wth + C_*C_, nullptr, nullptr, nullptr, nullptr, BIGZ,
        nullptr, mBh, mBl, m1b2, cscale, grids,
        S_, C_, C_, C_, 0, C_, 0, C_, 1, 0);
    launch_gemm(1, 1, dim3(2, 1024, 1),
        mBh, mBl, wth + 2*C_*C_, nullptr, nullptr, nullptr, nullptr, BIGZ,
        nullptr, mAh, mAl, m2b1, cscale, nullptr,
        S_, C_, C_, C_, 0, C_, 0, C_, 1, 0);
    launch_gemm(1, 1, dim3(2, 1024, 1),
        mAh, mAl, wth + 3*C_*C_, nullptr, nullptr, nullptr, nullptr, BIGZ,
        grids, nullptr, nullptr, m2b2, cscale, nullptr,
        S_, C_, C_, C_, 0, C_, 0, C_, 1, 0);

    // ---- instance norm + residual + transpose out ----
    norm1_k<<<512, 256>>>();
    norm2_k<<<1, 256>>>();
    fin_k<<<dim3(128, NLAT_), dim3(32,8)>>>(x, gamma, beta, out);
}

// round 12
// speedup vs baseline: 2.1118x; 1.0866x over previous
#include <cuda_runtime.h>
#include <cuda_fp16.h>
#include <math.h>

#define C_    256
#define NLAT_ 256
#define NLON_ 512
#define L_    256
#define M_    257
#define NREF_ 64
#define S_    (NLAT_*NLON_)
#define K2C_  512
#define MP_   544               // 2*M=514 padded to mult of 32

#define XS_SZ   ((size_t)C_*S_)
#define LW_SZ   ((size_t)L_*M_*NLAT_)
#define LGT_SZ  ((size_t)M_*NLAT_*L_)
#define WC_SZ   ((size_t)L_*C_*K2C_)
#define F_SZ    ((size_t)2*M_*C_*NLAT_)
#define H_SZ    ((size_t)L_*M_*K2C_)
#define XSP_SZ  ((size_t)M_*C_*L_)
#define G2_SZ   ((size_t)NLAT_*C_*MP_)
#define DCS_SZ  ((size_t)2*M_*NLON_)
#define D2_SZ   ((size_t)NLON_*MP_)

__device__ __align__(128) __half g_x_h[XS_SZ];
__device__ __align__(128) __half g_xt_h[XS_SZ];
__device__ __align__(128) __half g_lw_h[LW_SZ];
__device__ __align__(128) __half g_lg_h[LGT_SZ];
__device__ __align__(128) __half g_wr_h[WC_SZ];
__device__ __align__(128) __half g_wi_h[WC_SZ];
__device__ __align__(128) __half g_F_h[F_SZ];
__device__ __align__(128) __half g_H_h[H_SZ];
__device__ __align__(128) __half g_xr_h[XSP_SZ];
__device__ __align__(128) __half g_xi_h[XSP_SZ];
__device__ __align__(128) __half g_G_h[G2_SZ];
__device__ __align__(128) __half g_mA_h[XS_SZ];
__device__ __align__(128) __half g_mB_h[XS_SZ];
__device__ __align__(128) __half g_dc_h[DCS_SZ];
__device__ __align__(128) __half g_d2_h[D2_SZ];
__device__ __align__(128) __half g_wt_h[4*C_*C_];
__device__ __align__(128) float g_grids[XS_SZ];
__device__ float g_lsc16[L_];
__device__ float g_cscale[2];        // {1/16, 1/4096}
__device__ float g_part[2][512][C_];
__device__ float g_mu[C_], g_rstd[C_];

__device__ __forceinline__ float gelu_f(float v){
    return 0.5f*v*(1.0f + erff(v*0.7071067811865476f));
}
__device__ __forceinline__ unsigned smem_u32(const void* p){
    unsigned a;
    asm("{ .reg .u64 t; cvta.to.shared.u64 t, %1; cvt.u32.u64 %0, t; }" : "=r"(a) : "l"(p));
    return a;
}
__device__ __forceinline__ int swadr(int r, int w){
    return r*64 + ((((w>>2) ^ ((r>>1)&3))) << 4) + ((w & 3) << 2);
}
__device__ __forceinline__ void cpa16(unsigned saddr, const void* g, bool v){
    asm volatile("cp.async.cg.shared.global [%0], [%1], 16, %2;"
                 :: "r"(saddr), "l"(g), "r"(v ? 16 : 0));
}
#define CP_COMMIT() asm volatile("cp.async.commit_group;")
#define LDMX4(r0,r1,r2,r3,addr) \
    asm volatile("ldmatrix.sync.aligned.m8n8.x4.shared.b16 {%0,%1,%2,%3}, [%4];" \
        : "=r"(r0),"=r"(r1),"=r"(r2),"=r"(r3) : "r"(addr))
#define MMA_OP(cc, aa, bb) asm volatile( \
    "mma.sync.aligned.m16n8k16.row.col.f32.f16.f16.f32 " \
    "{%0,%1,%2,%3},{%4,%5,%6,%7},{%8,%9},{%0,%1,%2,%3};" \
    : "+f"(cc[0]),"+f"(cc[1]),"+f"(cc[2]),"+f"(cc[3]) \
    : "r"(aa[0]),"r"(aa[1]),"r"(aa[2]),"r"(aa[3]),"r"(bb[0]),"r"(bb[1]))

// ---------------- prep kernels ----------------
// fused: x -> x_h (c,j,n) AND xT_h (s=n*256+j, c)
__global__ void p_xT2(const float* __restrict__ x){
    __shared__ float sm[32][33];
    int j  = blockIdx.y;
    int tc = blockIdx.x & 7;
    int tn = blockIdx.x >> 3;
    int tx = threadIdx.x, ty = threadIdx.y;
    #pragma unroll
    for (int k=0;k<4;k++){
        int c = tc*32 + ty + k*8;
        size_t offx = (size_t)c*S_ + (size_t)j*NLON_ + tn*32 + tx;
        float v = x[offx];
        sm[ty+k*8][tx] = v;
        g_x_h[offx] = __float2half_rn(v);
    }
    __syncthreads();
    #pragma unroll
    for (int k=0;k<4;k++){
        int n = tn*32 + ty + k*8;
        int c = tc*32 + tx;
        size_t off = ((size_t)n*NLAT_ + j)*C_ + c;
        g_xt_h[off] = __float2half_rn(sm[tx][ty+k*8]);
    }
}
__global__ void p_lw(const float* __restrict__ leg, const float* __restrict__ wq){
    size_t i4 = ((size_t)blockIdx.x*256 + threadIdx.x)*4;
    if (i4 >= LW_SZ) return;
    float4 v = *(const float4*)(leg + i4);
    int w0 = (int)(i4 & (NLAT_-1));
    float a = 16.f*v.x*wq[w0],   b = 16.f*v.y*wq[w0+1];
    float c = 16.f*v.z*wq[w0+2], d = 16.f*v.w*wq[w0+3];
    __half2* o = (__half2*)(g_lw_h + i4);
    o[0] = __floats2half2_rn(a, b);
    o[1] = __floats2half2_rn(c, d);
}
__global__ void p_legT(const float* __restrict__ leg){
    __shared__ float sm[32][33];
    int m  = blockIdx.y;
    int tl = blockIdx.x & 7;
    int tj = blockIdx.x >> 3;
    int tx = threadIdx.x, ty = threadIdx.y;
    #pragma unroll
    for (int k=0;k<4;k++){
        int l = tl*32 + ty + k*8;
        sm[ty+k*8][tx] = leg[(size_t)l*M_*NLAT_ + (size_t)m*NLAT_ + tj*32 + tx];
    }
    __syncthreads();
    #pragma unroll
    for (int k=0;k<4;k++){
        int j = tj*32 + ty + k*8;
        int l = tl*32 + tx;
        size_t off = ((size_t)m*NLAT_ + j)*L_ + l;
        g_lg_h[off] = __float2half_rn(16.0f*sm[tx][ty+k*8]);
    }
}
__global__ void p_W2(const float* __restrict__ wr, const float* __restrict__ wi){
    __shared__ float sr[256][8], si[256][8];
    int f  = blockIdx.y;
    int l0 = blockIdx.x * 16;
    int c  = threadIdx.x;
    int i0min = (l0*(NREF_-1)) / (L_-1);
    if (i0min > NREF_-8) i0min = NREF_-8;
    size_t rb = ((size_t)f*C_ + c)*NREF_ + i0min;
    #pragma unroll
    for (int k=0;k<8;k++){ sr[c][k] = wr[rb+k]; si[c][k] = wi[rb+k]; }
    __syncthreads();
    #pragma unroll 4
    for (int li=0; li<16; li++){
        int l = l0 + li;
        float pos = (float)(l*(NREF_-1)) / (float)(L_-1);
        int i0 = (int)floorf(pos);
        if (i0 > NREF_-2) i0 = NREF_-2;
        float fr = pos - (float)i0;
        int k = i0 - i0min;
        float vre = sr[c][k]*(1.0f-fr) + sr[c][k+1]*fr;
        float vim = si[c][k]*(1.0f-fr) + si[c][k+1]*fr;
        size_t ob = ((size_t)l*C_ + f)*K2C_;
        g_wr_h[ob + c]      = __float2half_rn( vre);
        g_wr_h[ob + C_ + c] = __float2half_rn(-vim);
        g_wi_h[ob + c]      = __float2half_rn( vim);
        g_wi_h[ob + C_ + c] = __float2half_rn( vre);
    }
}
__global__ void p_dft(){
    int i = blockIdx.x*256 + threadIdx.x;
    if (i < L_) g_lsc16[i] = sqrtf(1.0f + (float)i) * (1.0f/(float)C_) * (1.0f/16.0f);
    if (i < 2)  g_cscale[i] = (i==0) ? 0.0625f : (1.0f/4096.0f);
    if (i < (int)DCS_SZ){
        int n = i & 511;
        int m = (i >> 9) % M_;
        int ri = i / (M_*NLON_);
        int a = (m*n) & 511;
        float ang = (float)a * (1.0f/256.0f);
        float v = ri ? -sinpif(ang) : cospif(ang);
        g_dc_h[i] = __float2half_rn(v);
    }
    if (i < (int)D2_SZ){
        int mp = i % MP_;
        int n  = i / MP_;
        float v = 0.f;
        if (mp < M_){
            float wm = (mp==0 || mp==M_-1) ? 1.0f : 2.0f;
            int a = (mp*n) & 511;
            v = wm * cospif((float)a*(1.0f/256.0f)) * 0.5f;    // 256x of /512
        } else if (mp < 2*M_){
            int m2 = mp - M_;
            float wm = (m2==0 || m2==M_-1) ? 1.0f : 2.0f;
            int a = (m2*n) & 511;
            v = -wm * sinpif((float)a*(1.0f/256.0f)) * 0.5f;
        }
        g_d2_h[i] = __float2half_rn(v);
    }
}
__global__ void p_wT(const float* w1, const float* w2, const float* w3, const float* w4){
    int i = blockIdx.x*256 + threadIdx.x;
    if (i >= C_*C_) return;
    int c = i / C_, cp = i % C_;
    const float* ws[4] = {w1, w2, w3, w4};
    #pragma unroll
    for (int k=0;k<4;k++)
        g_wt_h[(size_t)k*C_*C_ + (size_t)cp*C_ + c] = __float2half_rn(16.0f*ws[k][i]);
}
__global__ void p_zeroG2(){
    int i = blockIdx.x*256 + threadIdx.x;
    int nz = MP_ - 514;
    int tot = NLAT_*C_*nz;
    if (i >= tot) return;
    int k  = i % nz;
    int jf = i / nz;
    g_G_h[(size_t)jf*MP_ + 514 + k] = __float2half_rn(0.f);
}

// ---------------- pipelined mma.sync fp16 GEMM ----------------
// D = Ah·Bh^T (single-pass), 128x128 tile, K-chunk 32, 3-stage cp.async.
// zsplit: for bz >= zsplit, switch to alternate A/B/out pointers (batch merge).
#define STGB 24576
#define NSTG 3
#define SMEM_DYN (NSTG*STGB)

template<int ACT>
__global__ __launch_bounds__(256) void mmagemm(
    const __half* __restrict__ Ah,
    const __half* __restrict__ Bh,
    const __half* __restrict__ Ah2,
    const __half* __restrict__ Bh2, __half* __restrict__ Oh2,
    int zsplit,
    float* __restrict__ Dout,
    __half* __restrict__ Oh,
    const float* __restrict__ biasJ, const float* __restrict__ bscale,
    const float* __restrict__ addsrc,
    int Mrows, int Ncols, int K,
    long sAi, long sAb, long sBi, long sBb,
    long sCi, long sCj, long sCb)
{
    extern __shared__ char dsm[];
    const unsigned sb = smem_u32(dsm);

    const int t    = threadIdx.x;
    const int lane = t & 31;
    const int warp = t >> 5;
    const int g    = lane >> 2;
    const int tig  = lane & 3;
    const int mm   = lane >> 3;
    const int rrl  = lane & 7;
    const int wm   = warp >> 2;
    const int wn   = warp & 3;
    int bz = blockIdx.z;
    if (bz >= zsplit){
        bz -= zsplit;
        if (Ah2){ Ah = Ah2; }
        if (Bh2){ Bh = Bh2; }
        if (Oh2){ Oh = Oh2; }
    }
    const long i0  = (long)blockIdx.y * 128;
    const long j0  = (long)blockIdx.x * 128;

    const __half* Ahb = Ah + (long)bz*sAb;
    const __half* Bhb = Bh + (long)bz*sBb;

    const int row   = t >> 1;
    const int half  = t & 1;
    const long arow = i0 + row;
    const long brow = j0 + row;
    const bool bok  = brow < (long)Ncols;
    const long aoff = arow * sAi;
    const long boff = brow * sBi;

    float acc[64];
    #pragma unroll
    for (int i=0;i<64;i++) acc[i] = 0.f;

    auto load_stage = [&](int ks, int s){
        unsigned st = sb + s*STGB;
        long kg = (long)ks*32;
        #pragma unroll
        for (int q=0;q<2;q++){
            int c = half*2 + q;
            long ke = kg + c*8;
            unsigned so = (unsigned)(row*64 + ((c ^ ((row>>1)&3)) << 4));
            cpa16(st + so,          Ahb + aoff + ke, true);
            cpa16(st + 16384 + so,  Bhb + boff + ke, bok);
        }
    };

    const int nk = K >> 5;
    load_stage(0, 0);
    CP_COMMIT();
    if (nk > 1){ load_stage(1, 1); }
    CP_COMMIT();

    for (int ks = 0; ks < nk; ks++){
        if (ks + 1 < nk) asm volatile("cp.async.wait_group 1;");
        else             asm volatile("cp.async.wait_group 0;");
        __syncthreads();

        const unsigned sA = sb + (ks % NSTG)*STGB;
        const unsigned sB = sA + 16384;
        #pragma unroll
        for (int kk=0; kk<2; kk++){
            unsigned ah[4][4], bh[4][2];
            #pragma unroll
            for (int p=0;p<2;p++){
                int rowB = wn*32 + (p*2 + (mm>>1))*8 + rrl;
                int wB   = kk*8 + (mm&1)*4;
                unsigned ad = sB + (unsigned)swadr(rowB, wB);
                LDMX4(bh[p*2][0], bh[p*2][1], bh[p*2+1][0], bh[p*2+1][1], ad);
            }
            #pragma unroll
            for (int mt=0; mt<4; mt++){
                int rowA = wm*64 + mt*16 + (mm&1)*8 + rrl;
                int wA   = kk*8 + (mm>>1)*4;
                unsigned ad = sA + (unsigned)swadr(rowA, wA);
                LDMX4(ah[mt][0], ah[mt][1], ah[mt][2], ah[mt][3], ad);
            }
            #pragma unroll
            for (int mt=0; mt<4; mt++)
                #pragma unroll
                for (int nt=0; nt<4; nt++) MMA_OP((&acc[(mt*4+nt)*4]), ah[mt], bh[nt]);
        }
        if (ks + 2 < nk){
            load_stage(ks+2, (ks+2) % NSTG);
        }
        CP_COMMIT();
    }

    // ---------------- epilogue ----------------
    float scl = bscale ? bscale[bz] : 1.0f;
    #pragma unroll
    for (int mt=0; mt<4; mt++){
        long rA = i0 + wm*64 + mt*16 + g;
        #pragma unroll
        for (int nt=0; nt<4; nt++){
            long cB = j0 + wn*32 + nt*8 + 2*tig;
            float* a = &acc[(mt*4+nt)*4];
            #pragma unroll
            for (int h2=0; h2<2; h2++){
                long rowg = rA + h2*8;
                if (rowg >= (long)Mrows) continue;
                long offr = (long)bz*sCb + rowg*sCi;
                if (sCj == 1 && cB + 1 < (long)Ncols){
                    float v0 = a[h2*2+0] * scl;
                    float v1 = a[h2*2+1] * scl;
                    if (biasJ){ v0 += biasJ[cB]; v1 += biasJ[cB+1]; }
                    if (ACT == 1){ v0 = gelu_f(v0); v1 = gelu_f(v1); }
                    long off = offr + cB;
                    if (addsrc){ v0 += addsrc[off]; v1 += addsrc[off+1]; }
                    if (Dout) *(float2*)(Dout + off) = make_float2(v0, v1);
                    if (Oh)   *(__half2*)(Oh + off) = __floats2half2_rn(v0, v1);
                } else {
                    #pragma unroll
                    for (int q=0; q<2; q++){
                        long col = cB + q;
                        if (col >= (long)Ncols) continue;
                        float v = a[h2*2+q] * scl;
                        if (biasJ) v += biasJ[col];
                        if (ACT == 1) v = gelu_f(v);
                        long off = offr + col*sCj;
                        if (addsrc) v += addsrc[off];
                        if (Dout) Dout[off] = v;
                        if (Oh)   Oh[off] = __float2half_rn(v);
                    }
                }
            }
        }
    }
}

// ---------------- norm + finalize ----------------
__global__ void norm1_k(){
    int b = blockIdx.x, c = threadIdx.x;
    const float* base = g_grids + (size_t)b*256*C_;
    float s=0.f, q=0.f;
    for (int r=0;r<256;r++){
        float v = base[(size_t)r*C_ + c];
        s += v; q = fmaf(v,v,q);
    }
    g_part[0][b][c] = s;
    g_part[1][b][c] = q;
}
__global__ void norm2_k(){
    int c = threadIdx.x;
    float s=0.f, q=0.f;
    for (int b=0;b<512;b++){ s += g_part[0][b][c]; q += g_part[1][b][c]; }
    float mu = s * (1.0f/(float)S_);
    float var = q * (1.0f/(float)S_) - mu*mu;
    g_mu[c] = mu;
    g_rstd[c] = rsqrtf(var + 1e-3f);
}
__global__ void fin_k(const float* __restrict__ x,
                      const float* __restrict__ gamma,
                      const float* __restrict__ beta,
                      float* __restrict__ out){
    __shared__ float sm[32][33];
    int j  = blockIdx.y;
    int tc = blockIdx.x & 7;
    int tn = blockIdx.x >> 3;
    int tx = threadIdx.x, ty = threadIdx.y;
    #pragma unroll
    for (int k=0;k<4;k++){
        int n = tn*32 + ty + k*8;
        sm[ty+k*8][tx] = g_grids[((size_t)n*NLAT_ + j)*C_ + tc*32 + tx];
    }
    __syncthreads();
    #pragma unroll
    for (int k=0;k<4;k++){
        int c = tc*32 + ty + k*8;
        int n = tn*32 + tx;
        size_t off = (size_t)c*S_ + (size_t)j*NLON_ + n;
        float v = sm[tx][ty+k*8];
        out[off] = (v - g_mu[c])*g_rstd[c]*gamma[c] + beta[c] + x[off];
    }
}

// ---------------- host side ----------------
#define DEVPTR(T, var, sym) T* var; cudaGetSymbolAddress((void**)&var, sym)

static void launch_gemm(int act, dim3 grid,
    const __half* Ah, const __half* Bh,
    const __half* Ah2, const __half* Bh2, __half* Oh2, int zsplit,
    float* Dout, __half* Oh,
    const float* biasJ, const float* bscale, const float* addsrc,
    int M, int N, int K,
    long sAi, long sAb, long sBi, long sBb, long sCi, long sCj, long sCb)
{
    if (act)
        mmagemm<1><<<grid,256,SMEM_DYN>>>(Ah,Bh,Ah2,Bh2,Oh2,zsplit,
            Dout,Oh,biasJ,bscale,addsrc,M,N,K,sAi,sAb,sBi,sBb,sCi,sCj,sCb);
    else
        mmagemm<0><<<grid,256,SMEM_DYN>>>(Ah,Bh,Ah2,Bh2,Oh2,zsplit,
            Dout,Oh,biasJ,bscale,addsrc,M,N,K,sAi,sAb,sBi,sBb,sCi,sCj,sCb);
}

extern "C" void kernel_launch(void* const* d_in, const int* in_sizes, int n_in,
                              void* d_out, int out_size){
    const float* x      = (const float*)d_in[0];
    const float* leg    = (const float*)d_in[1];
    const float* wquad  = (const float*)d_in[2];
    const float* w_real = (const float*)d_in[3];
    const float* w_imag = (const float*)d_in[4];
    const float* m1w1   = (const float*)d_in[5];
    const float* m1b1   = (const float*)d_in[6];
    const float* m1w2   = (const float*)d_in[7];
    const float* m1b2   = (const float*)d_in[8];
    const float* m2w1   = (const float*)d_in[9];
    const float* m2b1   = (const float*)d_in[10];
    const float* m2w2   = (const float*)d_in[11];
    const float* m2b2   = (const float*)d_in[12];
    const float* gamma  = (const float*)d_in[13];
    const float* beta   = (const float*)d_in[14];
    float* out = (float*)d_out;

    cudaFuncSetAttribute(mmagemm<0>, cudaFuncAttributeMaxDynamicSharedMemorySize, SMEM_DYN);
    cudaFuncSetAttribute(mmagemm<1>, cudaFuncAttributeMaxDynamicSharedMemorySize, SMEM_DYN);

    DEVPTR(__half, xh, g_x_h);
    DEVPTR(__half, xth,g_xt_h);
    DEVPTR(__half, lwh,g_lw_h);
    DEVPTR(__half, lgh,g_lg_h);
    DEVPTR(__half, wrh,g_wr_h);
    DEVPTR(__half, wih,g_wi_h);
    DEVPTR(__half, Fh, g_F_h);
    DEVPTR(__half, Hh, g_H_h);
    DEVPTR(__half, xrh,g_xr_h);
    DEVPTR(__half, xih,g_xi_h);
    DEVPTR(__half, Gh, g_G_h);
    DEVPTR(__half, mAh,g_mA_h);
    DEVPTR(__half, mBh,g_mB_h);
    DEVPTR(__half, dch,g_dc_h);
    DEVPTR(__half, d2h,g_d2_h);
    DEVPTR(__half, wth,g_wt_h);
    DEVPTR(float, grids, g_grids);
    DEVPTR(float, lsc16, g_lsc16);
    DEVPTR(float, cscale, g_cscale);

    const int BIGZ = 1 << 30;

    // ---- prep (launch #3 = the big S1 GEMM for ncu) ----
    p_dft <<<(unsigned)((D2_SZ+255)/256), 256>>>();
    p_xT2 <<<dim3(128, NLAT_), dim3(32,8)>>>(x);

    // ---- S1: rfft DFT-GEMM -> F (ri,m,c,j) ----
    launch_gemm(0, dim3(3, 512, 2),
        xh, dch, nullptr, nullptr, nullptr, BIGZ,
        nullptr, Fh, nullptr, nullptr, nullptr,
        C_*NLAT_, M_, NLON_,
        NLON_, 0, NLON_, (long)M_*NLON_,
        1, (long)C_*NLAT_, (long)M_*C_*NLAT_);

    p_lw     <<<(unsigned)((LW_SZ/4+255)/256), 256>>>(leg, wquad);
    p_legT   <<<dim3(64, M_), dim3(32,8)>>>(leg);
    p_W2     <<<dim3(16, 256), 256>>>(w_real, w_imag);
    p_wT     <<<(C_*C_+255)/256, 256>>>(m1w1, m1w2, m2w1, m2w2);
    p_zeroG2 <<<(unsigned)((NLAT_*C_*(MP_-514)+255)/256), 256>>>();

    // ---- S2 merged (batch 2M): A=16*lw; B/out switch at zsplit=M ----
    launch_gemm(0, dim3(2, 2, 2*M_),
        lwh, Fh,
        nullptr, Fh + M_*(size_t)C_*NLAT_, Hh + C_, M_,
        nullptr, Hh, nullptr, nullptr, nullptr,
        L_, C_, NLAT_,
        (long)M_*NLAT_, NLAT_, NLAT_, (long)C_*NLAT_,
        (long)M_*K2C_, 1, K2C_);

    // ---- S3 merged (batch 2L): B=Hh shared; A/out switch at zsplit=L ----
    launch_gemm(0, dim3(3, 2, 2*L_),
        wrh, Hh,
        wih, nullptr, xih, L_,
        nullptr, xrh, nullptr, lsc16, nullptr,
        C_, M_, K2C_,
        K2C_, (long)C_*K2C_, K2C_, (long)M_*K2C_,
        L_, (long)C_*L_, 1);

    // ---- S4 merged (batch 2M): A=16*lgT; B/out switch at zsplit=M ----
    launch_gemm(0, dim3(2, 2, 2*M_),
        lgh, xrh,
        nullptr, xih, Gh + M_, M_,
        nullptr, Gh, nullptr, nullptr, nullptr,
        NLAT_, C_, L_,
        L_, (long)NLAT_*L_, L_, (long)C_*L_,
        (long)C_*MP_, MP_, 1);

    // ---- S5: irfft + GELU -> fp32 grids (n,j,f) ----
    launch_gemm(1, dim3(512, 4, 1),
        d2h, Gh, nullptr, nullptr, nullptr, BIGZ,
        grids, nullptr, nullptr, cscale+1, nullptr,
        NLON_, NLAT_*C_, MP_,
        MP_, 0, MP_, 0,
        (long)NLAT_*C_, 1, 0);

    // ---- MLPs (single-pass): B = 16*wT, bscale = 1/16 ----
    launch_gemm(1, dim3(2, 1024, 1),
        xth, wth + 0, nullptr, nullptr, nullptr, BIGZ,
        nullptr, mAh, m1b1, cscale, nullptr,
        S_, C_, C_, C_, 0, C_, 0, C_, 1, 0);
    launch_gemm(1, dim3(2, 1024, 1),
        mAh, wth + C_*C_, nullptr, nullptr, nullptr, BIGZ,
        nullptr, mBh, m1b2, cscale, grids,
        S_, C_, C_, C_, 0, C_, 0, C_, 1, 0);
    launch_gemm(1, dim3(2, 1024, 1),
        mBh, wth + 2*C_*C_, nullptr, nullptr, nullptr, BIGZ,
        nullptr, mAh, m2b1, cscale, nullptr,
        S_, C_, C_, C_, 0, C_, 0, C_, 1, 0);
    launch_gemm(1, dim3(2, 1024, 1),
        mAh, wth + 3*C_*C_, nullptr, nullptr, nullptr, BIGZ,
        grids, nullptr, m2b2, cscale, nullptr,
        S_, C_, C_, C_, 0, C_, 0, C_, 1, 0);

    // ---- instance norm + residual + transpose out ----
    norm1_k<<<512, 256>>>();
    norm2_k<<<1, 256>>>();
    fin_k<<<dim3(128, NLAT_), dim3(32,8)>>>(x, gamma, beta, out);
}